// round 6
// baseline (speedup 1.0000x reference)
#include <cuda_runtime.h>
#include <cuda_bf16.h>
#include <math.h>
#include <stdint.h>

// Problem dims (fixed for this dataset)
constexpr int S_  = 256;
constexpr int B_  = 8;
constexpr int T_  = 1024;
constexpr int D_  = 512;
constexpr int TS_ = 512;
constexpr int V_  = 32000;
constexpr int SB  = S_ * B_;   // 2048
constexpr int TB  = T_ * B_;   // 8192

// ---------------------------------------------------------------------------
// Scratch arena
// ---------------------------------------------------------------------------
constexpr size_t OQ  = 0;                        // q / later x      : SB*D
constexpr size_t OK_ = OQ  + (size_t)SB * D_;    // k                : TB*D
constexpr size_t OV  = OK_ + (size_t)TB * D_;    // v                : TB*D
constexpr size_t OVT = OV  + (size_t)TB * D_;    // v transposed     : TB*D
constexpr size_t OA  = OVT + (size_t)TB * D_;    // attn (scores)    : SB*T
constexpr size_t OC  = OA  + (size_t)SB * T_;    // ctx              : SB*D
constexpr size_t OL  = OC  + (size_t)SB * D_;    // layernorm out    : SB*D
constexpr size_t OT  = OL  + (size_t)SB * D_;    // outs_token (f32) : SB*D
constexpr size_t OG  = OT  + (size_t)SB * D_;    // gates            : SB*2
constexpr size_t OM  = OG  + (size_t)SB * 2;     // per-row coef     : SB
constexpr size_t ORS = OM  + SB;                 // rowsum exp       : SB
constexpr size_t OWB = ORS + SB;                 // Wgen bf16        : V*TS/2 floats
constexpr size_t OTB = OWB + (size_t)V_ * TS_ / 2;  // tok bf16      : SB*TS/2
constexpr size_t SCRATCH_FLOATS = OTB + (size_t)SB * TS_ / 2;

__device__ float g_scratch[SCRATCH_FLOATS];

// ---------------------------------------------------------------------------
// math helpers
// ---------------------------------------------------------------------------
__device__ __forceinline__ float fexp(float x) {
    float t = fmaxf(fminf(x * 1.4426950408889634f, 126.f), -126.f);
    float mg = t + 12582912.f;
    int   n  = __float_as_int(mg) - 0x4B400000;
    float f  = t - (mg - 12582912.f);
    float p  = 1.54035304e-4f;
    p = fmaf(p, f, 1.33335581e-3f);
    p = fmaf(p, f, 9.61812911e-3f);
    p = fmaf(p, f, 5.55041087e-2f);
    p = fmaf(p, f, 2.40226507e-1f);
    p = fmaf(p, f, 6.93147182e-1f);
    p = fmaf(p, f, 1.0f);
    return __int_as_float(__float_as_int(p) + (n << 23));
}

__device__ __forceinline__ void mma_tf32(float& c0, float& c1, float& c2, float& c3,
                                         unsigned a0, unsigned a1, unsigned a2, unsigned a3,
                                         unsigned b0, unsigned b1)
{
    asm volatile(
        "mma.sync.aligned.m16n8k8.row.col.f32.tf32.tf32.f32 "
        "{%0,%1,%2,%3}, {%4,%5,%6,%7}, {%8,%9}, {%0,%1,%2,%3};"
        : "+f"(c0), "+f"(c1), "+f"(c2), "+f"(c3)
        : "r"(a0), "r"(a1), "r"(a2), "r"(a3), "r"(b0), "r"(b1));
}

__device__ __forceinline__ void mma_bf16(float& c0, float& c1, float& c2, float& c3,
                                         unsigned a0, unsigned a1, unsigned a2, unsigned a3,
                                         unsigned b0, unsigned b1)
{
    asm volatile(
        "mma.sync.aligned.m16n8k16.row.col.f32.bf16.bf16.f32 "
        "{%0,%1,%2,%3}, {%4,%5,%6,%7}, {%8,%9}, {%0,%1,%2,%3};"
        : "+f"(c0), "+f"(c1), "+f"(c2), "+f"(c3)
        : "r"(a0), "r"(a1), "r"(a2), "r"(a3), "r"(b0), "r"(b1));
}

__device__ __forceinline__ void cp16(unsigned dst, const void* src) {
    asm volatile("cp.async.cg.shared.global [%0], [%1], 16;\n" :: "r"(dst), "l"(src));
}

// ---------------------------------------------------------------------------
// Tensor-core NT GEMM (tf32) — 128x128 block, warp 64x32. For small/batched.
// ---------------------------------------------------------------------------
template <int ACT>
__global__ __launch_bounds__(256, 2)
void mma_nt_kernel(const float* __restrict__ A, const float* __restrict__ Bm,
                   const float* __restrict__ bias, float* __restrict__ C,
                   int K, int lda, int ldb, int ldc,
                   long sA, long sB, long sC, float alpha)
{
    extern __shared__ unsigned sh[];

    A  += (long)blockIdx.z * sA;
    Bm += (long)blockIdx.z * sB;
    C  += (long)blockIdx.z * sC;

    const int t    = threadIdx.x;
    const int lane = t & 31;
    const int warp = t >> 5;
    const int wm   = (warp >> 2) * 64;
    const int wn   = (warp & 3) * 32;
    const int grp  = lane >> 2;
    const int qid  = lane & 3;

    const long m0 = (long)blockIdx.y * 128;
    const long n0 = (long)blockIdx.x * 128;

    float acc[4][4][4];
#pragma unroll
    for (int mi = 0; mi < 4; mi++)
#pragma unroll
        for (int ni = 0; ni < 4; ni++)
#pragma unroll
            for (int c = 0; c < 4; c++) acc[mi][ni][c] = 0.f;

    const float* aptr[4];
    const float* bptr[4];
    unsigned soff[4];
#pragma unroll
    for (int i = 0; i < 4; i++) {
        int f   = t + i * 256;
        int row = f >> 3;
        int c4  = f & 7;
        aptr[i] = A  + (m0 + row) * lda + c4 * 4;
        bptr[i] = Bm + (n0 + row) * ldb + c4 * 4;
        soff[i] = (unsigned)(row * 32 + ((c4 ^ (row & 7)) << 2)) * 4u;
    }
    const unsigned sbase = (unsigned)__cvta_generic_to_shared(sh);

    auto issue = [&](int stage, int koff) {
        unsigned ab = sbase + (unsigned)stage * 16384u;
        unsigned bb = sbase + 32768u + (unsigned)stage * 16384u;
#pragma unroll
        for (int i = 0; i < 4; i++) {
            cp16(ab + soff[i], aptr[i] + koff);
            cp16(bb + soff[i], bptr[i] + koff);
        }
        asm volatile("cp.async.commit_group;\n" ::: "memory");
    };

    issue(0, 0);
    const int nIter = K >> 5;
    for (int it = 0; it < nIter; ++it) {
        asm volatile("cp.async.wait_group 0;\n" ::: "memory");
        __syncthreads();
        if (it + 1 < nIter) issue((it + 1) & 1, (it + 1) * 32);

        const unsigned* Asb = sh + (it & 1) * 4096;
        const unsigned* Bsb = sh + 8192 + (it & 1) * 4096;
#pragma unroll
        for (int kk = 0; kk < 4; kk++) {
            unsigned af[4][4], bf[4][2];
#pragma unroll
            for (int mi = 0; mi < 4; mi++) {
                int m  = wm + mi * 16 + grp;
                int m8 = m + 8;
                af[mi][0] = Asb[m  * 32 + ((( kk * 2    ) ^ (m  & 7)) << 2) + qid];
                af[mi][1] = Asb[m8 * 32 + ((( kk * 2    ) ^ (m8 & 7)) << 2) + qid];
                af[mi][2] = Asb[m  * 32 + ((( kk * 2 + 1) ^ (m  & 7)) << 2) + qid];
                af[mi][3] = Asb[m8 * 32 + ((( kk * 2 + 1) ^ (m8 & 7)) << 2) + qid];
            }
#pragma unroll
            for (int ni = 0; ni < 4; ni++) {
                int n = wn + ni * 8 + grp;
                bf[ni][0] = Bsb[n * 32 + ((( kk * 2    ) ^ (n & 7)) << 2) + qid];
                bf[ni][1] = Bsb[n * 32 + ((( kk * 2 + 1) ^ (n & 7)) << 2) + qid];
            }
#pragma unroll
            for (int mi = 0; mi < 4; mi++)
#pragma unroll
                for (int ni = 0; ni < 4; ni++)
                    mma_tf32(acc[mi][ni][0], acc[mi][ni][1], acc[mi][ni][2], acc[mi][ni][3],
                             af[mi][0], af[mi][1], af[mi][2], af[mi][3],
                             bf[ni][0], bf[ni][1]);
        }
        __syncthreads();
    }

#pragma unroll
    for (int mi = 0; mi < 4; mi++) {
        long r0 = m0 + wm + mi * 16 + grp;
        long r1 = r0 + 8;
#pragma unroll
        for (int ni = 0; ni < 4; ni++) {
            long col = n0 + wn + ni * 8 + qid * 2;
            float bv0 = 0.f, bv1 = 0.f;
            if (bias) { bv0 = bias[col]; bv1 = bias[col + 1]; }
            float v00 = (acc[mi][ni][0] + bv0) * alpha;
            float v01 = (acc[mi][ni][1] + bv1) * alpha;
            float v10 = (acc[mi][ni][2] + bv0) * alpha;
            float v11 = (acc[mi][ni][3] + bv1) * alpha;
            if (ACT == 1) { v00 = tanhf(v00); v01 = tanhf(v01); v10 = tanhf(v10); v11 = tanhf(v11); }
            *(float2*)(C + r0 * ldc + col) = make_float2(v00, v01);
            *(float2*)(C + r1 * ldc + col) = make_float2(v10, v11);
        }
    }
}

// ---------------------------------------------------------------------------
// WIDE tf32 NT GEMM: 128x256 block, 8 warps, warp tile 64x64. 96KB SMEM.
// FLOP/B(smem) = 16 -> ~55% tensor (vs 37% at 64x32). For k/v GEMMs.
// ---------------------------------------------------------------------------
__global__ __launch_bounds__(256, 1)
void mma_nt_wide_kernel(const float* __restrict__ A, const float* __restrict__ Bm,
                        const float* __restrict__ bias, float* __restrict__ C,
                        int K, int lda, int ldb, int ldc)
{
    extern __shared__ unsigned sh[];   // A: 2x4096 words @0; B: 2x8192 words @8192

    const int t    = threadIdx.x;
    const int lane = t & 31;
    const int warp = t >> 5;
    const int wm   = (warp >> 2) * 64;       // 0/64
    const int wn   = (warp & 3) * 64;        // 0..192
    const int grp  = lane >> 2;
    const int qid  = lane & 3;

    const long m0 = (long)blockIdx.y * 128;
    const long n0 = (long)blockIdx.x * 256;

    float acc[4][8][4];
#pragma unroll
    for (int mi = 0; mi < 4; mi++)
#pragma unroll
        for (int ni = 0; ni < 8; ni++)
#pragma unroll
            for (int c = 0; c < 4; c++) acc[mi][ni][c] = 0.f;

    const int row0 = t >> 3;                 // 0..31
    const int c4   = t & 7;
    const float* aptr0 = A  + (m0 + row0) * lda + c4 * 4;
    const float* bptr0 = Bm + (n0 + row0) * ldb + c4 * 4;
    const unsigned soff0 = (unsigned)(row0 * 32 + ((c4 ^ (row0 & 7)) << 2)) * 4u;
    const unsigned sbase = (unsigned)__cvta_generic_to_shared(sh);

    auto issue = [&](int stage, int koff) {
        unsigned ab = sbase + (unsigned)stage * 16384u + soff0;
        unsigned bb = sbase + 32768u + (unsigned)stage * 32768u + soff0;
#pragma unroll
        for (int i = 0; i < 4; i++)
            cp16(ab + i * 4096u, aptr0 + (long)i * 32 * lda + koff);
#pragma unroll
        for (int i = 0; i < 8; i++)
            cp16(bb + i * 4096u, bptr0 + (long)i * 32 * ldb + koff);
        asm volatile("cp.async.commit_group;\n" ::: "memory");
    };

    issue(0, 0);
    const int nIter = K >> 5;
    for (int it = 0; it < nIter; ++it) {
        asm volatile("cp.async.wait_group 0;\n" ::: "memory");
        __syncthreads();
        if (it + 1 < nIter) issue((it + 1) & 1, (it + 1) * 32);

        const unsigned* Asb = sh + (it & 1) * 4096;
        const unsigned* Bsb = sh + 8192 + (it & 1) * 8192;
#pragma unroll
        for (int kk = 0; kk < 4; kk++) {
            unsigned af[4][4], bf[8][2];
#pragma unroll
            for (int mi = 0; mi < 4; mi++) {
                int m  = wm + mi * 16 + grp;
                int m8 = m + 8;
                af[mi][0] = Asb[m  * 32 + ((( kk * 2    ) ^ (m  & 7)) << 2) + qid];
                af[mi][1] = Asb[m8 * 32 + ((( kk * 2    ) ^ (m8 & 7)) << 2) + qid];
                af[mi][2] = Asb[m  * 32 + ((( kk * 2 + 1) ^ (m  & 7)) << 2) + qid];
                af[mi][3] = Asb[m8 * 32 + ((( kk * 2 + 1) ^ (m8 & 7)) << 2) + qid];
            }
#pragma unroll
            for (int ni = 0; ni < 8; ni++) {
                int n = wn + ni * 8 + grp;
                bf[ni][0] = Bsb[n * 32 + ((( kk * 2    ) ^ (n & 7)) << 2) + qid];
                bf[ni][1] = Bsb[n * 32 + ((( kk * 2 + 1) ^ (n & 7)) << 2) + qid];
            }
#pragma unroll
            for (int mi = 0; mi < 4; mi++)
#pragma unroll
                for (int ni = 0; ni < 8; ni++)
                    mma_tf32(acc[mi][ni][0], acc[mi][ni][1], acc[mi][ni][2], acc[mi][ni][3],
                             af[mi][0], af[mi][1], af[mi][2], af[mi][3],
                             bf[ni][0], bf[ni][1]);
        }
        __syncthreads();
    }

#pragma unroll
    for (int mi = 0; mi < 4; mi++) {
        long r0 = m0 + wm + mi * 16 + grp;
        long r1 = r0 + 8;
#pragma unroll
        for (int ni = 0; ni < 8; ni++) {
            long col = n0 + wn + ni * 8 + qid * 2;
            float bv0 = bias[col], bv1 = bias[col + 1];
            *(float2*)(C + r0 * ldc + col) = make_float2(acc[mi][ni][0] + bv0, acc[mi][ni][1] + bv1);
            *(float2*)(C + r1 * ldc + col) = make_float2(acc[mi][ni][2] + bv0, acc[mi][ni][3] + bv1);
        }
    }
}

// ---------------------------------------------------------------------------
// WIDE bf16 NT GEMM + fused exp-rowsum: 128x256 block, warp 64x64, BK=64.
// 96KB SMEM (2 stages x (16KB A + 32KB B)). FLOP/B = 32 -> ~55% bf16 tensor.
// ---------------------------------------------------------------------------
__global__ __launch_bounds__(256, 1)
void mma_bf16_wide_kernel(const __nv_bfloat16* __restrict__ A,
                          const __nv_bfloat16* __restrict__ Bm,
                          const float* __restrict__ bias, float* __restrict__ C,
                          float* __restrict__ rowsum,
                          int K, int lda, int ldb, int ldc)
{
    extern __shared__ unsigned sh[];
    char* shc = (char*)sh;

    const int t    = threadIdx.x;
    const int lane = t & 31;
    const int warp = t >> 5;
    const int wm   = (warp >> 2) * 64;
    const int wn   = (warp & 3) * 64;
    const int grp  = lane >> 2;
    const int qid  = lane & 3;

    const long m0 = (long)blockIdx.y * 128;
    const long n0 = (long)blockIdx.x * 256;

    float acc[4][8][4];
#pragma unroll
    for (int mi = 0; mi < 4; mi++)
#pragma unroll
        for (int ni = 0; ni < 8; ni++)
#pragma unroll
            for (int c = 0; c < 4; c++) acc[mi][ni][c] = 0.f;

    const int row0 = t >> 3;                 // 0..31
    const int c8   = t & 7;                  // 16B chunk
    const __nv_bfloat16* aptr0 = A  + (m0 + row0) * lda + c8 * 8;
    const __nv_bfloat16* bptr0 = Bm + (n0 + row0) * ldb + c8 * 8;
    const unsigned soff0 = (unsigned)(row0 * 128 + ((c8 ^ (row0 & 7)) << 4));
    const unsigned sbase = (unsigned)__cvta_generic_to_shared(sh);

    auto issue = [&](int stage, int koff) {
        unsigned ab = sbase + (unsigned)stage * 16384u + soff0;
        unsigned bb = sbase + 32768u + (unsigned)stage * 32768u + soff0;
#pragma unroll
        for (int i = 0; i < 4; i++)
            cp16(ab + i * 4096u, aptr0 + (long)i * 32 * lda + koff);
#pragma unroll
        for (int i = 0; i < 8; i++)
            cp16(bb + i * 4096u, bptr0 + (long)i * 32 * ldb + koff);
        asm volatile("cp.async.commit_group;\n" ::: "memory");
    };

    issue(0, 0);
    const int nIter = K >> 6;                 // BK=64
    for (int it = 0; it < nIter; ++it) {
        asm volatile("cp.async.wait_group 0;\n" ::: "memory");
        __syncthreads();
        if (it + 1 < nIter) issue((it + 1) & 1, (it + 1) * 64);

        const char* Asb = shc + (it & 1) * 16384;
        const char* Bsb = shc + 32768 + (it & 1) * 32768;
#pragma unroll
        for (int kk = 0; kk < 4; kk++) {      // 16 k per step
            unsigned af[4][4], bf[8][2];
#pragma unroll
            for (int mi = 0; mi < 4; mi++) {
                int m  = wm + mi * 16 + grp;
                int m8 = m + 8;
                af[mi][0] = *(const unsigned*)(Asb + m  * 128 + (((kk*2  ) ^ (m  & 7)) << 4) + qid * 4);
                af[mi][1] = *(const unsigned*)(Asb + m8 * 128 + (((kk*2  ) ^ (m8 & 7)) << 4) + qid * 4);
                af[mi][2] = *(const unsigned*)(Asb + m  * 128 + (((kk*2+1) ^ (m  & 7)) << 4) + qid * 4);
                af[mi][3] = *(const unsigned*)(Asb + m8 * 128 + (((kk*2+1) ^ (m8 & 7)) << 4) + qid * 4);
            }
#pragma unroll
            for (int ni = 0; ni < 8; ni++) {
                int n = wn + ni * 8 + grp;
                bf[ni][0] = *(const unsigned*)(Bsb + n * 128 + (((kk*2  ) ^ (n & 7)) << 4) + qid * 4);
                bf[ni][1] = *(const unsigned*)(Bsb + n * 128 + (((kk*2+1) ^ (n & 7)) << 4) + qid * 4);
            }
#pragma unroll
            for (int mi = 0; mi < 4; mi++)
#pragma unroll
                for (int ni = 0; ni < 8; ni++)
                    mma_bf16(acc[mi][ni][0], acc[mi][ni][1], acc[mi][ni][2], acc[mi][ni][3],
                             af[mi][0], af[mi][1], af[mi][2], af[mi][3],
                             bf[ni][0], bf[ni][1]);
        }
        __syncthreads();
    }

    // epilogue: write logits + per-row sum of exp
#pragma unroll
    for (int mi = 0; mi < 4; mi++) {
        long r0 = m0 + wm + mi * 16 + grp;
        long r1 = r0 + 8;
        float e0 = 0.f, e1 = 0.f;
#pragma unroll
        for (int ni = 0; ni < 8; ni++) {
            long col = n0 + wn + ni * 8 + qid * 2;
            float bv0 = bias[col], bv1 = bias[col + 1];
            float v00 = acc[mi][ni][0] + bv0;
            float v01 = acc[mi][ni][1] + bv1;
            float v10 = acc[mi][ni][2] + bv0;
            float v11 = acc[mi][ni][3] + bv1;
            *(float2*)(C + r0 * ldc + col) = make_float2(v00, v01);
            *(float2*)(C + r1 * ldc + col) = make_float2(v10, v11);
            e0 += fexp(v00) + fexp(v01);
            e1 += fexp(v10) + fexp(v11);
        }
        e0 += __shfl_xor_sync(0xFFFFFFFFu, e0, 1);
        e0 += __shfl_xor_sync(0xFFFFFFFFu, e0, 2);
        e1 += __shfl_xor_sync(0xFFFFFFFFu, e1, 1);
        e1 += __shfl_xor_sync(0xFFFFFFFFu, e1, 2);
        if (qid == 0) {
            atomicAdd(rowsum + r0, e0);
            atomicAdd(rowsum + r1, e1);
        }
    }
}

// ---------------------------------------------------------------------------
// fp32 -> bf16 convert
// ---------------------------------------------------------------------------
__global__ __launch_bounds__(256)
void f2b_kernel(const float4* __restrict__ in, __nv_bfloat162* __restrict__ out, int n4)
{
    int i = blockIdx.x * 256 + threadIdx.x;
    if (i >= n4) return;
    float4 v = in[i];
    out[i * 2]     = __floats2bfloat162_rn(v.x, v.y);
    out[i * 2 + 1] = __floats2bfloat162_rn(v.z, v.w);
}

__global__ void zero_kernel(float* __restrict__ p)
{
    p[blockIdx.x * 256 + threadIdx.x] = 0.f;
}

__global__ void coef_kernel(const float* __restrict__ rowsum,
                            const float* __restrict__ gates, float* __restrict__ coef)
{
    int r = blockIdx.x * 256 + threadIdx.x;
    coef[r] = __logf(gates[r * 2 + 0]) - __logf(rowsum[r]);
}

// ---------------------------------------------------------------------------
// v transpose: vt[b][d][t] = v[(t*B+b)*D + d].
// ---------------------------------------------------------------------------
__global__ __launch_bounds__(256)
void vt_kernel(const float* __restrict__ v, float* __restrict__ vt)
{
    __shared__ float tile[32][33];
    int b  = blockIdx.z;
    int t0 = blockIdx.x * 32;
    int d0 = blockIdx.y * 32;
    int x  = threadIdx.x & 31;
    int y  = threadIdx.x >> 5;
#pragma unroll
    for (int j = 0; j < 32; j += 8)
        tile[y + j][x] = v[((long)(t0 + y + j) * B_ + b) * D_ + d0 + x];
    __syncthreads();
#pragma unroll
    for (int j = 0; j < 32; j += 8)
        vt[(long)b * D_ * T_ + (long)(d0 + y + j) * T_ + t0 + x] = tile[x][y + j];
}

// ---------------------------------------------------------------------------
// Softmax over T (in-place). mask: [B,T] bytes.
// ---------------------------------------------------------------------------
__global__ __launch_bounds__(256)
void attn_softmax_kernel(float* __restrict__ attn, const unsigned char* __restrict__ mask)
{
    int row = blockIdx.x;
    int b   = row & (B_ - 1);
    float* p = attn + (long)row * T_;
    const unsigned char* mrow = mask + (long)b * T_;
    int t = threadIdx.x;
    __shared__ float red[256];

    float x[4];
    float mx = -1e30f;
#pragma unroll
    for (int i = 0; i < 4; i++) {
        int tt = t + i * 256;
        float v = p[tt];
        if (mrow[tt]) v = -1e9f;
        x[i] = v;
        mx = fmaxf(mx, v);
    }
    red[t] = mx; __syncthreads();
    for (int s = 128; s > 0; s >>= 1) {
        if (t < s) red[t] = fmaxf(red[t], red[t + s]);
        __syncthreads();
    }
    mx = red[0]; __syncthreads();

    float sum = 0.f;
#pragma unroll
    for (int i = 0; i < 4; i++) { x[i] = fexp(x[i] - mx); sum += x[i]; }
    red[t] = sum; __syncthreads();
    for (int s = 128; s > 0; s >>= 1) {
        if (t < s) red[t] += red[t + s];
        __syncthreads();
    }
    float inv = 1.f / red[0];
#pragma unroll
    for (int i = 0; i < 4; i++) p[t + i * 256] = x[i] * inv;
}

// ---------------------------------------------------------------------------
// LayerNorm(outs + x).
// ---------------------------------------------------------------------------
__global__ __launch_bounds__(256)
void ln_kernel(const float* __restrict__ outs, const float* __restrict__ x,
               const float* __restrict__ g, const float* __restrict__ bb,
               float* __restrict__ out)
{
    int row = blockIdx.x;
    int t = threadIdx.x;
    const float* o  = outs + (long)row * D_;
    const float* xr = x    + (long)row * D_;
    __shared__ float red[256];

    float v0 = o[t] + xr[t];
    float v1 = o[t + 256] + xr[t + 256];

    red[t] = v0 + v1; __syncthreads();
    for (int s = 128; s > 0; s >>= 1) { if (t < s) red[t] += red[t + s]; __syncthreads(); }
    float mu = red[0] * (1.f / D_); __syncthreads();

    float d0 = v0 - mu, d1 = v1 - mu;
    red[t] = d0 * d0 + d1 * d1; __syncthreads();
    for (int s = 128; s > 0; s >>= 1) { if (t < s) red[t] += red[t + s]; __syncthreads(); }
    float inv = rsqrtf(red[0] * (1.f / D_) + 1e-5f);

    out[(long)row * D_ + t]       = d0 * inv * g[t]       + bb[t];
    out[(long)row * D_ + t + 256] = d1 * inv * g[t + 256] + bb[t + 256];
}

// ---------------------------------------------------------------------------
// 2-way gate
// ---------------------------------------------------------------------------
__global__ __launch_bounds__(128)
void gates_kernel(const float* __restrict__ tok, const float* __restrict__ Wdiv,
                  const float* __restrict__ bdiv, float* __restrict__ gates)
{
    int row = blockIdx.x;
    int t = threadIdx.x;
    const float* x = tok + (long)row * D_;
    float z0 = 0.f, z1 = 0.f;
    for (int d = t; d < D_; d += 128) {
        float xv = x[d];
        z0 = fmaf(xv, Wdiv[d],      z0);
        z1 = fmaf(xv, Wdiv[D_ + d], z1);
    }
    __shared__ float r0[128], r1[128];
    r0[t] = z0; r1[t] = z1; __syncthreads();
    for (int s = 64; s > 0; s >>= 1) {
        if (t < s) { r0[t] += r0[t + s]; r1[t] += r1[t + s]; }
        __syncthreads();
    }
    if (t == 0) {
        float a = r0[0] + bdiv[0], b = r1[0] + bdiv[1];
        float m = fmaxf(a, b);
        float e0 = __expf(a - m), e1 = __expf(b - m);
        float inv = 1.f / (e0 + e1);
        gates[row * 2 + 0] = e0 * inv;
        gates[row * 2 + 1] = e1 * inv;
    }
}

// ---------------------------------------------------------------------------
// Log-prob base pass: out = coef[row] + z.
// ---------------------------------------------------------------------------
__global__ __launch_bounds__(256)
void lp_kernel(float* __restrict__ out, const float* __restrict__ coef)
{
    long i4 = (long)blockIdx.x * 256 + threadIdx.x;
    int row = (int)(i4 / (V_ / 4));
    float c = __ldg(coef + row);
    float4* p = (float4*)out + i4;
    float4 v = *p;
    v.x += c; v.y += c; v.z += c; v.w += c;
    *p = v;
}

// ---------------------------------------------------------------------------
// Copy-scatter in log space via CAS.
// ---------------------------------------------------------------------------
__global__ __launch_bounds__(256)
void scatter_kernel(float* __restrict__ out, const float* __restrict__ attn,
                    const float* __restrict__ gates, const int* __restrict__ copy_seq)
{
    int gid = blockIdx.x * 256 + threadIdx.x;
    int row = gid >> 10;
    int t   = gid & 1023;
    int b   = row & (B_ - 1);
    float val = gates[row * 2 + 1] * attn[(long)row * T_ + t];
    int idx = copy_seq[t * B_ + b];
    int* ia = (int*)(out + (long)row * V_ + idx);

    int assumed = *ia;
    int old;
    do {
        old = assumed;
        float cur = __int_as_float(old);
        float nv = __logf(__expf(cur) + val);
        assumed = atomicCAS(ia, old, __float_as_int(nv));
    } while (assumed != old);
}

// ---------------------------------------------------------------------------
// Launch
// ---------------------------------------------------------------------------
extern "C" void kernel_launch(void* const* d_in, const int* in_sizes, int n_in,
                              void* d_out, int out_size)
{
    const float* outs = (const float*)d_in[0];
    const float* gs   = (const float*)d_in[1];
    const unsigned char* mask = (const unsigned char*)d_in[2];
    const int*   cseq = (const int*)d_in[3];
    const float* Wq = (const float*)d_in[4],  *bq = (const float*)d_in[5];
    const float* Wk = (const float*)d_in[6],  *bk = (const float*)d_in[7];
    const float* Wv = (const float*)d_in[8],  *bv = (const float*)d_in[9];
    const float* Wo = (const float*)d_in[10], *bo = (const float*)d_in[11];
    const float* lng = (const float*)d_in[12], *lnb = (const float*)d_in[13];
    const float* Wt = (const float*)d_in[14], *bt = (const float*)d_in[15];
    const float* Wgen = (const float*)d_in[16], *bgen = (const float*)d_in[17];
    const float* Wdiv = (const float*)d_in[18], *bdiv = (const float*)d_in[19];
    float* out = (float*)d_out;

    float* sc = nullptr;
    cudaGetSymbolAddress((void**)&sc, g_scratch);
    float* q     = sc + OQ;
    float* k     = sc + OK_;
    float* v     = sc + OV;
    float* vt    = sc + OVT;
    float* attn  = sc + OA;
    float* ctx   = sc + OC;
    float* ln    = sc + OL;
    float* tok   = sc + OT;
    float* gts   = sc + OG;
    float* coef  = sc + OM;
    float* rowsum = sc + ORS;
    __nv_bfloat16* wgen_b = (__nv_bfloat16*)(sc + OWB);
    __nv_bfloat16* tok_b  = (__nv_bfloat16*)(sc + OTB);

    const float scale = 0.044194173824159216f; // 1/sqrt(512)
    constexpr int SMEM  = 65536;
    constexpr int SMEMW = 98304;
    cudaFuncSetAttribute(mma_nt_kernel<0>, cudaFuncAttributeMaxDynamicSharedMemorySize, SMEM);
    cudaFuncSetAttribute(mma_nt_kernel<1>, cudaFuncAttributeMaxDynamicSharedMemorySize, SMEM);
    cudaFuncSetAttribute(mma_nt_wide_kernel, cudaFuncAttributeMaxDynamicSharedMemorySize, SMEMW);
    cudaFuncSetAttribute(mma_bf16_wide_kernel, cudaFuncAttributeMaxDynamicSharedMemorySize, SMEMW);
    dim3 blk(256);

    // early: Wgen -> bf16, rowsum = 0
    f2b_kernel<<<(V_ * TS_ / 4 + 255) / 256, blk>>>((const float4*)Wgen, (__nv_bfloat162*)wgen_b, V_ * TS_ / 4);
    zero_kernel<<<SB / 256, blk>>>(rowsum);

    // q = (outs @ Wq^T + bq) * scale       [2048 x 512]
    mma_nt_kernel<0><<<dim3(4, 16, 1), blk, SMEM>>>(outs, Wq, bq, q, D_, D_, D_, D_, 0, 0, 0, scale);
    // k = gs @ Wk^T + bk                   [8192 x 512]  (wide)
    mma_nt_wide_kernel<<<dim3(2, 64, 1), blk, SMEMW>>>(gs, Wk, bk, k, D_, D_, D_, D_);
    // v = gs @ Wv^T + bv                   (wide)
    mma_nt_wide_kernel<<<dim3(2, 64, 1), blk, SMEMW>>>(gs, Wv, bv, v, D_, D_, D_, D_);
    // v transpose for ctx GEMM
    vt_kernel<<<dim3(32, 16, 8), blk>>>(v, vt);
    // scores[s,b,t] = q[s,b,:] . k[t,b,:]  (batched over b)
    mma_nt_kernel<0><<<dim3(8, 2, 8), blk, SMEM>>>(q, k, nullptr, attn,
                                                   D_, B_ * D_, B_ * D_, B_ * T_,
                                                   D_, D_, T_, 1.f);
    // softmax over t (with mask)
    attn_softmax_kernel<<<SB, 256>>>(attn, mask);
    // ctx[s,b,:] = attn[s,b,:] @ v[:,b,:]   (NT vs v_T, batched over b)
    mma_nt_kernel<0><<<dim3(4, 2, 8), blk, SMEM>>>(attn, vt, nullptr, ctx,
                                                   T_, B_ * T_, T_, B_ * D_,
                                                   T_, (long)D_ * T_, D_, 1.f);
    // x = ctx @ Wo^T + bo   -> reuse q buffer
    mma_nt_kernel<0><<<dim3(4, 16, 1), blk, SMEM>>>(ctx, Wo, bo, q, D_, D_, D_, D_, 0, 0, 0, 1.f);
    // outs_ln = LN(outs + x)
    ln_kernel<<<SB, 256>>>(outs, q, lng, lnb, ln);
    // tok = tanh(outs_ln @ Wt^T + bt)
    mma_nt_kernel<1><<<dim3(4, 16, 1), blk, SMEM>>>(ln, Wt, bt, tok, D_, D_, D_, TS_, 0, 0, 0, 1.f);
    // gates
    gates_kernel<<<SB, 128>>>(tok, Wdiv, bdiv, gts);
    // tok -> bf16
    f2b_kernel<<<(SB * TS_ / 4 + 255) / 256, blk>>>((const float4*)tok, (__nv_bfloat162*)tok_b, SB * TS_ / 4);
    // logits = tok @ Wgen^T + bgen -> d_out; fused rowsum of exp(logits)  (wide)
    mma_bf16_wide_kernel<<<dim3(125, 16, 1), blk, SMEMW>>>(tok_b, wgen_b, bgen, out, rowsum,
                                                           TS_, TS_, TS_, V_);
    // coef = log(gen) - log(rowsum)
    coef_kernel<<<SB / 256, blk>>>(rowsum, gts, coef);
    // base log-probs in place
    lp_kernel<<<(SB * (V_ / 4)) / 256, 256>>>(out, coef);
    // copy scatter (log-space CAS merge)
    scatter_kernel<<<(SB * T_) / 256, 256>>>(out, attn, gts, cseq);
}

// round 7
// speedup vs baseline: 1.0715x; 1.0715x over previous
#include <cuda_runtime.h>
#include <cuda_bf16.h>
#include <math.h>
#include <stdint.h>

// Problem dims (fixed for this dataset)
constexpr int S_  = 256;
constexpr int B_  = 8;
constexpr int T_  = 1024;
constexpr int D_  = 512;
constexpr int TS_ = 512;
constexpr int V_  = 32000;
constexpr int SB  = S_ * B_;   // 2048
constexpr int TB  = T_ * B_;   // 8192

// ---------------------------------------------------------------------------
// Scratch arena
// ---------------------------------------------------------------------------
constexpr size_t OQ  = 0;                        // q / later x      : SB*D
constexpr size_t OK_ = OQ  + (size_t)SB * D_;    // k                : TB*D
constexpr size_t OV  = OK_ + (size_t)TB * D_;    // v                : TB*D
constexpr size_t OVT = OV  + (size_t)TB * D_;    // v transposed     : TB*D
constexpr size_t OA  = OVT + (size_t)TB * D_;    // attn (scores)    : SB*T
constexpr size_t OC  = OA  + (size_t)SB * T_;    // ctx              : SB*D
constexpr size_t OL  = OC  + (size_t)SB * D_;    // layernorm out    : SB*D
constexpr size_t OT  = OL  + (size_t)SB * D_;    // outs_token (f32) : SB*D
constexpr size_t OG  = OT  + (size_t)SB * D_;    // gates            : SB*2
constexpr size_t OM  = OG  + (size_t)SB * 2;     // per-row coef     : SB
constexpr size_t ORS = OM  + SB;                 // rowsum exp       : SB
constexpr size_t OWB = ORS + SB;                 // Wgen bf16        : V*TS/2 floats
constexpr size_t OTB = OWB + (size_t)V_ * TS_ / 2;  // tok bf16      : SB*TS/2
constexpr size_t SCRATCH_FLOATS = OTB + (size_t)SB * TS_ / 2;

__device__ float g_scratch[SCRATCH_FLOATS];

// ---------------------------------------------------------------------------
// math helpers
// ---------------------------------------------------------------------------
__device__ __forceinline__ float fexp(float x) {
    float t = fmaxf(fminf(x * 1.4426950408889634f, 126.f), -126.f);
    float mg = t + 12582912.f;
    int   n  = __float_as_int(mg) - 0x4B400000;
    float f  = t - (mg - 12582912.f);
    float p  = 1.54035304e-4f;
    p = fmaf(p, f, 1.33335581e-3f);
    p = fmaf(p, f, 9.61812911e-3f);
    p = fmaf(p, f, 5.55041087e-2f);
    p = fmaf(p, f, 2.40226507e-1f);
    p = fmaf(p, f, 6.93147182e-1f);
    p = fmaf(p, f, 1.0f);
    return __int_as_float(__float_as_int(p) + (n << 23));
}

__device__ __forceinline__ void mma_tf32(float& c0, float& c1, float& c2, float& c3,
                                         unsigned a0, unsigned a1, unsigned a2, unsigned a3,
                                         unsigned b0, unsigned b1)
{
    asm volatile(
        "mma.sync.aligned.m16n8k8.row.col.f32.tf32.tf32.f32 "
        "{%0,%1,%2,%3}, {%4,%5,%6,%7}, {%8,%9}, {%0,%1,%2,%3};"
        : "+f"(c0), "+f"(c1), "+f"(c2), "+f"(c3)
        : "r"(a0), "r"(a1), "r"(a2), "r"(a3), "r"(b0), "r"(b1));
}

__device__ __forceinline__ void mma_bf16(float& c0, float& c1, float& c2, float& c3,
                                         unsigned a0, unsigned a1, unsigned a2, unsigned a3,
                                         unsigned b0, unsigned b1)
{
    asm volatile(
        "mma.sync.aligned.m16n8k16.row.col.f32.bf16.bf16.f32 "
        "{%0,%1,%2,%3}, {%4,%5,%6,%7}, {%8,%9}, {%0,%1,%2,%3};"
        : "+f"(c0), "+f"(c1), "+f"(c2), "+f"(c3)
        : "r"(a0), "r"(a1), "r"(a2), "r"(a3), "r"(b0), "r"(b1));
}

__device__ __forceinline__ void cp16(unsigned dst, const void* src) {
    asm volatile("cp.async.cg.shared.global [%0], [%1], 16;\n" :: "r"(dst), "l"(src));
}

// ---------------------------------------------------------------------------
// Tensor-core NT GEMM (tf32): C[m,n] = ACT(alpha*(sum A[m,k]*B[n,k] + bias[n]))
// 128x128 block, 4 warps, warp tile 64x64 (FLOP/B=16), BK=32.
// cp.async double-buffered, XOR-swizzled. 64KB SMEM, 2 CTAs/SM.
// ---------------------------------------------------------------------------
template <int ACT>
__global__ __launch_bounds__(128, 2)
void mma_nt_kernel(const float* __restrict__ A, const float* __restrict__ Bm,
                   const float* __restrict__ bias, float* __restrict__ C,
                   int K, int lda, int ldb, int ldc,
                   long sA, long sB, long sC, float alpha)
{
    extern __shared__ unsigned sh[];   // A: 2 stages x 4096 words @0; B: @8192

    A  += (long)blockIdx.z * sA;
    Bm += (long)blockIdx.z * sB;
    C  += (long)blockIdx.z * sC;

    const int t    = threadIdx.x;
    const int lane = t & 31;
    const int warp = t >> 5;                 // 0..3
    const int wm   = (warp >> 1) * 64;       // 0/64
    const int wn   = (warp & 1) * 64;        // 0/64
    const int grp  = lane >> 2;
    const int qid  = lane & 3;

    const long m0 = (long)blockIdx.y * 128;
    const long n0 = (long)blockIdx.x * 128;

    float acc[4][8][4];
#pragma unroll
    for (int mi = 0; mi < 4; mi++)
#pragma unroll
        for (int ni = 0; ni < 8; ni++)
#pragma unroll
            for (int c = 0; c < 4; c++) acc[mi][ni][c] = 0.f;

    // 1024 float4 chunks per operand tile; 8 per thread, i-stride = 16 rows
    const int row0 = t >> 3;                 // 0..15
    const int c4   = t & 7;
    const float* aptr0 = A  + (m0 + row0) * lda + c4 * 4;
    const float* bptr0 = Bm + (n0 + row0) * ldb + c4 * 4;
    const unsigned soff0 = (unsigned)(row0 * 32 + ((c4 ^ (row0 & 7)) << 2)) * 4u;
    const unsigned sbase = (unsigned)__cvta_generic_to_shared(sh);

    auto issue = [&](int stage, int koff) {
        unsigned ab = sbase + (unsigned)stage * 16384u + soff0;
        unsigned bb = sbase + 32768u + (unsigned)stage * 16384u + soff0;
#pragma unroll
        for (int i = 0; i < 8; i++) {
            cp16(ab + i * 2048u, aptr0 + (long)i * 16 * lda + koff);
            cp16(bb + i * 2048u, bptr0 + (long)i * 16 * ldb + koff);
        }
        asm volatile("cp.async.commit_group;\n" ::: "memory");
    };

    issue(0, 0);
    const int nIter = K >> 5;
    for (int it = 0; it < nIter; ++it) {
        asm volatile("cp.async.wait_group 0;\n" ::: "memory");
        __syncthreads();
        if (it + 1 < nIter) issue((it + 1) & 1, (it + 1) * 32);

        const unsigned* Asb = sh + (it & 1) * 4096;
        const unsigned* Bsb = sh + 8192 + (it & 1) * 4096;
#pragma unroll
        for (int kk = 0; kk < 4; kk++) {
            unsigned af[4][4], bf[8][2];
#pragma unroll
            for (int mi = 0; mi < 4; mi++) {
                int m  = wm + mi * 16 + grp;
                int m8 = m + 8;
                af[mi][0] = Asb[m  * 32 + ((( kk * 2    ) ^ (m  & 7)) << 2) + qid];
                af[mi][1] = Asb[m8 * 32 + ((( kk * 2    ) ^ (m8 & 7)) << 2) + qid];
                af[mi][2] = Asb[m  * 32 + ((( kk * 2 + 1) ^ (m  & 7)) << 2) + qid];
                af[mi][3] = Asb[m8 * 32 + ((( kk * 2 + 1) ^ (m8 & 7)) << 2) + qid];
            }
#pragma unroll
            for (int ni = 0; ni < 8; ni++) {
                int n = wn + ni * 8 + grp;
                bf[ni][0] = Bsb[n * 32 + ((( kk * 2    ) ^ (n & 7)) << 2) + qid];
                bf[ni][1] = Bsb[n * 32 + ((( kk * 2 + 1) ^ (n & 7)) << 2) + qid];
            }
#pragma unroll
            for (int mi = 0; mi < 4; mi++)
#pragma unroll
                for (int ni = 0; ni < 8; ni++)
                    mma_tf32(acc[mi][ni][0], acc[mi][ni][1], acc[mi][ni][2], acc[mi][ni][3],
                             af[mi][0], af[mi][1], af[mi][2], af[mi][3],
                             bf[ni][0], bf[ni][1]);
        }
        __syncthreads();
    }

#pragma unroll
    for (int mi = 0; mi < 4; mi++) {
        long r0 = m0 + wm + mi * 16 + grp;
        long r1 = r0 + 8;
#pragma unroll
        for (int ni = 0; ni < 8; ni++) {
            long col = n0 + wn + ni * 8 + qid * 2;
            float bv0 = 0.f, bv1 = 0.f;
            if (bias) { bv0 = bias[col]; bv1 = bias[col + 1]; }
            float v00 = (acc[mi][ni][0] + bv0) * alpha;
            float v01 = (acc[mi][ni][1] + bv1) * alpha;
            float v10 = (acc[mi][ni][2] + bv0) * alpha;
            float v11 = (acc[mi][ni][3] + bv1) * alpha;
            if (ACT == 1) { v00 = tanhf(v00); v01 = tanhf(v01); v10 = tanhf(v10); v11 = tanhf(v11); }
            *(float2*)(C + r0 * ldc + col) = make_float2(v00, v01);
            *(float2*)(C + r1 * ldc + col) = make_float2(v10, v11);
        }
    }
}

// ---------------------------------------------------------------------------
// bf16 NT GEMM + fused exp-rowsum: 128x128 block, 4 warps, warp 64x64, BK=64.
// 64KB SMEM, 2 CTAs/SM. FLOP/B = 32.
// ---------------------------------------------------------------------------
__global__ __launch_bounds__(128, 2)
void mma_bf16_nt_kernel(const __nv_bfloat16* __restrict__ A,
                        const __nv_bfloat16* __restrict__ Bm,
                        const float* __restrict__ bias, float* __restrict__ C,
                        float* __restrict__ rowsum,
                        int K, int lda, int ldb, int ldc)
{
    extern __shared__ unsigned sh[];
    char* shc = (char*)sh;

    const int t    = threadIdx.x;
    const int lane = t & 31;
    const int warp = t >> 5;
    const int wm   = (warp >> 1) * 64;
    const int wn   = (warp & 1) * 64;
    const int grp  = lane >> 2;
    const int qid  = lane & 3;

    const long m0 = (long)blockIdx.y * 128;
    const long n0 = (long)blockIdx.x * 128;

    float acc[4][8][4];
#pragma unroll
    for (int mi = 0; mi < 4; mi++)
#pragma unroll
        for (int ni = 0; ni < 8; ni++)
#pragma unroll
            for (int c = 0; c < 4; c++) acc[mi][ni][c] = 0.f;

    // tile = 128 rows x 64 bf16 = 16KB; 1024 chunks, 8 per thread, stride 16 rows
    const int row0 = t >> 3;
    const int c8   = t & 7;
    const __nv_bfloat16* aptr0 = A  + (m0 + row0) * lda + c8 * 8;
    const __nv_bfloat16* bptr0 = Bm + (n0 + row0) * ldb + c8 * 8;
    const unsigned soff0 = (unsigned)(row0 * 128 + ((c8 ^ (row0 & 7)) << 4));
    const unsigned sbase = (unsigned)__cvta_generic_to_shared(sh);

    auto issue = [&](int stage, int koff) {
        unsigned ab = sbase + (unsigned)stage * 16384u + soff0;
        unsigned bb = sbase + 32768u + (unsigned)stage * 16384u + soff0;
#pragma unroll
        for (int i = 0; i < 8; i++) {
            cp16(ab + i * 2048u, aptr0 + (long)i * 16 * lda + koff);
            cp16(bb + i * 2048u, bptr0 + (long)i * 16 * ldb + koff);
        }
        asm volatile("cp.async.commit_group;\n" ::: "memory");
    };

    issue(0, 0);
    const int nIter = K >> 6;                 // BK=64
    for (int it = 0; it < nIter; ++it) {
        asm volatile("cp.async.wait_group 0;\n" ::: "memory");
        __syncthreads();
        if (it + 1 < nIter) issue((it + 1) & 1, (it + 1) * 64);

        const char* Asb = shc + (it & 1) * 16384;
        const char* Bsb = shc + 32768 + (it & 1) * 16384;
#pragma unroll
        for (int kk = 0; kk < 4; kk++) {      // 16 k per step
            unsigned af[4][4], bf[8][2];
#pragma unroll
            for (int mi = 0; mi < 4; mi++) {
                int m  = wm + mi * 16 + grp;
                int m8 = m + 8;
                af[mi][0] = *(const unsigned*)(Asb + m  * 128 + (((kk*2  ) ^ (m  & 7)) << 4) + qid * 4);
                af[mi][1] = *(const unsigned*)(Asb + m8 * 128 + (((kk*2  ) ^ (m8 & 7)) << 4) + qid * 4);
                af[mi][2] = *(const unsigned*)(Asb + m  * 128 + (((kk*2+1) ^ (m  & 7)) << 4) + qid * 4);
                af[mi][3] = *(const unsigned*)(Asb + m8 * 128 + (((kk*2+1) ^ (m8 & 7)) << 4) + qid * 4);
            }
#pragma unroll
            for (int ni = 0; ni < 8; ni++) {
                int n = wn + ni * 8 + grp;
                bf[ni][0] = *(const unsigned*)(Bsb + n * 128 + (((kk*2  ) ^ (n & 7)) << 4) + qid * 4);
                bf[ni][1] = *(const unsigned*)(Bsb + n * 128 + (((kk*2+1) ^ (n & 7)) << 4) + qid * 4);
            }
#pragma unroll
            for (int mi = 0; mi < 4; mi++)
#pragma unroll
                for (int ni = 0; ni < 8; ni++)
                    mma_bf16(acc[mi][ni][0], acc[mi][ni][1], acc[mi][ni][2], acc[mi][ni][3],
                             af[mi][0], af[mi][1], af[mi][2], af[mi][3],
                             bf[ni][0], bf[ni][1]);
        }
        __syncthreads();
    }

    // epilogue: write logits + per-row sum of exp
#pragma unroll
    for (int mi = 0; mi < 4; mi++) {
        long r0 = m0 + wm + mi * 16 + grp;
        long r1 = r0 + 8;
        float e0 = 0.f, e1 = 0.f;
#pragma unroll
        for (int ni = 0; ni < 8; ni++) {
            long col = n0 + wn + ni * 8 + qid * 2;
            float bv0 = bias[col], bv1 = bias[col + 1];
            float v00 = acc[mi][ni][0] + bv0;
            float v01 = acc[mi][ni][1] + bv1;
            float v10 = acc[mi][ni][2] + bv0;
            float v11 = acc[mi][ni][3] + bv1;
            *(float2*)(C + r0 * ldc + col) = make_float2(v00, v01);
            *(float2*)(C + r1 * ldc + col) = make_float2(v10, v11);
            e0 += fexp(v00) + fexp(v01);
            e1 += fexp(v10) + fexp(v11);
        }
        e0 += __shfl_xor_sync(0xFFFFFFFFu, e0, 1);
        e0 += __shfl_xor_sync(0xFFFFFFFFu, e0, 2);
        e1 += __shfl_xor_sync(0xFFFFFFFFu, e1, 1);
        e1 += __shfl_xor_sync(0xFFFFFFFFu, e1, 2);
        if (qid == 0) {
            atomicAdd(rowsum + r0, e0);
            atomicAdd(rowsum + r1, e1);
        }
    }
}

// ---------------------------------------------------------------------------
// fp32 -> bf16 convert
// ---------------------------------------------------------------------------
__global__ __launch_bounds__(256)
void f2b_kernel(const float4* __restrict__ in, __nv_bfloat162* __restrict__ out, int n4)
{
    int i = blockIdx.x * 256 + threadIdx.x;
    if (i >= n4) return;
    float4 v = in[i];
    out[i * 2]     = __floats2bfloat162_rn(v.x, v.y);
    out[i * 2 + 1] = __floats2bfloat162_rn(v.z, v.w);
}

__global__ void zero_kernel(float* __restrict__ p)
{
    p[blockIdx.x * 256 + threadIdx.x] = 0.f;
}

__global__ void coef_kernel(const float* __restrict__ rowsum,
                            const float* __restrict__ gates, float* __restrict__ coef)
{
    int r = blockIdx.x * 256 + threadIdx.x;
    coef[r] = __logf(gates[r * 2 + 0]) - __logf(rowsum[r]);
}

// ---------------------------------------------------------------------------
// v transpose: vt[b][d][t] = v[(t*B+b)*D + d].
// ---------------------------------------------------------------------------
__global__ __launch_bounds__(256)
void vt_kernel(const float* __restrict__ v, float* __restrict__ vt)
{
    __shared__ float tile[32][33];
    int b  = blockIdx.z;
    int t0 = blockIdx.x * 32;
    int d0 = blockIdx.y * 32;
    int x  = threadIdx.x & 31;
    int y  = threadIdx.x >> 5;
#pragma unroll
    for (int j = 0; j < 32; j += 8)
        tile[y + j][x] = v[((long)(t0 + y + j) * B_ + b) * D_ + d0 + x];
    __syncthreads();
#pragma unroll
    for (int j = 0; j < 32; j += 8)
        vt[(long)b * D_ * T_ + (long)(d0 + y + j) * T_ + t0 + x] = tile[x][y + j];
}

// ---------------------------------------------------------------------------
// Softmax over T (in-place). mask: [B,T] bytes.
// ---------------------------------------------------------------------------
__global__ __launch_bounds__(256)
void attn_softmax_kernel(float* __restrict__ attn, const unsigned char* __restrict__ mask)
{
    int row = blockIdx.x;
    int b   = row & (B_ - 1);
    float* p = attn + (long)row * T_;
    const unsigned char* mrow = mask + (long)b * T_;
    int t = threadIdx.x;
    __shared__ float red[256];

    float x[4];
    float mx = -1e30f;
#pragma unroll
    for (int i = 0; i < 4; i++) {
        int tt = t + i * 256;
        float v = p[tt];
        if (mrow[tt]) v = -1e9f;
        x[i] = v;
        mx = fmaxf(mx, v);
    }
    red[t] = mx; __syncthreads();
    for (int s = 128; s > 0; s >>= 1) {
        if (t < s) red[t] = fmaxf(red[t], red[t + s]);
        __syncthreads();
    }
    mx = red[0]; __syncthreads();

    float sum = 0.f;
#pragma unroll
    for (int i = 0; i < 4; i++) { x[i] = fexp(x[i] - mx); sum += x[i]; }
    red[t] = sum; __syncthreads();
    for (int s = 128; s > 0; s >>= 1) {
        if (t < s) red[t] += red[t + s];
        __syncthreads();
    }
    float inv = 1.f / red[0];
#pragma unroll
    for (int i = 0; i < 4; i++) p[t + i * 256] = x[i] * inv;
}

// ---------------------------------------------------------------------------
// LayerNorm(outs + x).
// ---------------------------------------------------------------------------
__global__ __launch_bounds__(256)
void ln_kernel(const float* __restrict__ outs, const float* __restrict__ x,
               const float* __restrict__ g, const float* __restrict__ bb,
               float* __restrict__ out)
{
    int row = blockIdx.x;
    int t = threadIdx.x;
    const float* o  = outs + (long)row * D_;
    const float* xr = x    + (long)row * D_;
    __shared__ float red[256];

    float v0 = o[t] + xr[t];
    float v1 = o[t + 256] + xr[t + 256];

    red[t] = v0 + v1; __syncthreads();
    for (int s = 128; s > 0; s >>= 1) { if (t < s) red[t] += red[t + s]; __syncthreads(); }
    float mu = red[0] * (1.f / D_); __syncthreads();

    float d0 = v0 - mu, d1 = v1 - mu;
    red[t] = d0 * d0 + d1 * d1; __syncthreads();
    for (int s = 128; s > 0; s >>= 1) { if (t < s) red[t] += red[t + s]; __syncthreads(); }
    float inv = rsqrtf(red[0] * (1.f / D_) + 1e-5f);

    out[(long)row * D_ + t]       = d0 * inv * g[t]       + bb[t];
    out[(long)row * D_ + t + 256] = d1 * inv * g[t + 256] + bb[t + 256];
}

// ---------------------------------------------------------------------------
// 2-way gate
// ---------------------------------------------------------------------------
__global__ __launch_bounds__(128)
void gates_kernel(const float* __restrict__ tok, const float* __restrict__ Wdiv,
                  const float* __restrict__ bdiv, float* __restrict__ gates)
{
    int row = blockIdx.x;
    int t = threadIdx.x;
    const float* x = tok + (long)row * D_;
    float z0 = 0.f, z1 = 0.f;
    for (int d = t; d < D_; d += 128) {
        float xv = x[d];
        z0 = fmaf(xv, Wdiv[d],      z0);
        z1 = fmaf(xv, Wdiv[D_ + d], z1);
    }
    __shared__ float r0[128], r1[128];
    r0[t] = z0; r1[t] = z1; __syncthreads();
    for (int s = 64; s > 0; s >>= 1) {
        if (t < s) { r0[t] += r0[t + s]; r1[t] += r1[t + s]; }
        __syncthreads();
    }
    if (t == 0) {
        float a = r0[0] + bdiv[0], b = r1[0] + bdiv[1];
        float m = fmaxf(a, b);
        float e0 = __expf(a - m), e1 = __expf(b - m);
        float inv = 1.f / (e0 + e1);
        gates[row * 2 + 0] = e0 * inv;
        gates[row * 2 + 1] = e1 * inv;
    }
}

// ---------------------------------------------------------------------------
// Log-prob base pass: out = coef[row] + z.
// ---------------------------------------------------------------------------
__global__ __launch_bounds__(256)
void lp_kernel(float* __restrict__ out, const float* __restrict__ coef)
{
    long i4 = (long)blockIdx.x * 256 + threadIdx.x;
    int row = (int)(i4 / (V_ / 4));
    float c = __ldg(coef + row);
    float4* p = (float4*)out + i4;
    float4 v = *p;
    v.x += c; v.y += c; v.z += c; v.w += c;
    *p = v;
}

// ---------------------------------------------------------------------------
// Copy-scatter in log space via CAS.
// ---------------------------------------------------------------------------
__global__ __launch_bounds__(256)
void scatter_kernel(float* __restrict__ out, const float* __restrict__ attn,
                    const float* __restrict__ gates, const int* __restrict__ copy_seq)
{
    int gid = blockIdx.x * 256 + threadIdx.x;
    int row = gid >> 10;
    int t   = gid & 1023;
    int b   = row & (B_ - 1);
    float val = gates[row * 2 + 1] * attn[(long)row * T_ + t];
    int idx = copy_seq[t * B_ + b];
    int* ia = (int*)(out + (long)row * V_ + idx);

    int assumed = *ia;
    int old;
    do {
        old = assumed;
        float cur = __int_as_float(old);
        float nv = __logf(__expf(cur) + val);
        assumed = atomicCAS(ia, old, __float_as_int(nv));
    } while (assumed != old);
}

// ---------------------------------------------------------------------------
// Launch
// ---------------------------------------------------------------------------
extern "C" void kernel_launch(void* const* d_in, const int* in_sizes, int n_in,
                              void* d_out, int out_size)
{
    const float* outs = (const float*)d_in[0];
    const float* gs   = (const float*)d_in[1];
    const unsigned char* mask = (const unsigned char*)d_in[2];
    const int*   cseq = (const int*)d_in[3];
    const float* Wq = (const float*)d_in[4],  *bq = (const float*)d_in[5];
    const float* Wk = (const float*)d_in[6],  *bk = (const float*)d_in[7];
    const float* Wv = (const float*)d_in[8],  *bv = (const float*)d_in[9];
    const float* Wo = (const float*)d_in[10], *bo = (const float*)d_in[11];
    const float* lng = (const float*)d_in[12], *lnb = (const float*)d_in[13];
    const float* Wt = (const float*)d_in[14], *bt = (const float*)d_in[15];
    const float* Wgen = (const float*)d_in[16], *bgen = (const float*)d_in[17];
    const float* Wdiv = (const float*)d_in[18], *bdiv = (const float*)d_in[19];
    float* out = (float*)d_out;

    float* sc = nullptr;
    cudaGetSymbolAddress((void**)&sc, g_scratch);
    float* q     = sc + OQ;
    float* k     = sc + OK_;
    float* v     = sc + OV;
    float* vt    = sc + OVT;
    float* attn  = sc + OA;
    float* ctx   = sc + OC;
    float* ln    = sc + OL;
    float* tok   = sc + OT;
    float* gts   = sc + OG;
    float* coef  = sc + OM;
    float* rowsum = sc + ORS;
    __nv_bfloat16* wgen_b = (__nv_bfloat16*)(sc + OWB);
    __nv_bfloat16* tok_b  = (__nv_bfloat16*)(sc + OTB);

    const float scale = 0.044194173824159216f; // 1/sqrt(512)
    constexpr int SMEM = 65536;
    cudaFuncSetAttribute(mma_nt_kernel<0>, cudaFuncAttributeMaxDynamicSharedMemorySize, SMEM);
    cudaFuncSetAttribute(mma_nt_kernel<1>, cudaFuncAttributeMaxDynamicSharedMemorySize, SMEM);
    cudaFuncSetAttribute(mma_bf16_nt_kernel, cudaFuncAttributeMaxDynamicSharedMemorySize, SMEM);
    dim3 blk(256);
    dim3 blkG(128);

    // early: Wgen -> bf16, rowsum = 0
    f2b_kernel<<<(V_ * TS_ / 4 + 255) / 256, blk>>>((const float4*)Wgen, (__nv_bfloat162*)wgen_b, V_ * TS_ / 4);
    zero_kernel<<<SB / 256, blk>>>(rowsum);

    // q = (outs @ Wq^T + bq) * scale       [2048 x 512]
    mma_nt_kernel<0><<<dim3(4, 16, 1), blkG, SMEM>>>(outs, Wq, bq, q, D_, D_, D_, D_, 0, 0, 0, scale);
    // k = gs @ Wk^T + bk                   [8192 x 512]
    mma_nt_kernel<0><<<dim3(4, 64, 1), blkG, SMEM>>>(gs, Wk, bk, k, D_, D_, D_, D_, 0, 0, 0, 1.f);
    // v = gs @ Wv^T + bv
    mma_nt_kernel<0><<<dim3(4, 64, 1), blkG, SMEM>>>(gs, Wv, bv, v, D_, D_, D_, D_, 0, 0, 0, 1.f);
    // v transpose for ctx GEMM
    vt_kernel<<<dim3(32, 16, 8), blk>>>(v, vt);
    // scores[s,b,t] = q[s,b,:] . k[t,b,:]  (batched over b)
    mma_nt_kernel<0><<<dim3(8, 2, 8), blkG, SMEM>>>(q, k, nullptr, attn,
                                                    D_, B_ * D_, B_ * D_, B_ * T_,
                                                    D_, D_, T_, 1.f);
    // softmax over t (with mask)
    attn_softmax_kernel<<<SB, 256>>>(attn, mask);
    // ctx[s,b,:] = attn[s,b,:] @ v[:,b,:]   (NT vs v_T, batched over b)
    mma_nt_kernel<0><<<dim3(4, 2, 8), blkG, SMEM>>>(attn, vt, nullptr, ctx,
                                                    T_, B_ * T_, T_, B_ * D_,
                                                    T_, (long)D_ * T_, D_, 1.f);
    // x = ctx @ Wo^T + bo   -> reuse q buffer
    mma_nt_kernel<0><<<dim3(4, 16, 1), blkG, SMEM>>>(ctx, Wo, bo, q, D_, D_, D_, D_, 0, 0, 0, 1.f);
    // outs_ln = LN(outs + x)
    ln_kernel<<<SB, 256>>>(outs, q, lng, lnb, ln);
    // tok = tanh(outs_ln @ Wt^T + bt)
    mma_nt_kernel<1><<<dim3(4, 16, 1), blkG, SMEM>>>(ln, Wt, bt, tok, D_, D_, D_, TS_, 0, 0, 0, 1.f);
    // gates
    gates_kernel<<<SB, 128>>>(tok, Wdiv, bdiv, gts);
    // tok -> bf16
    f2b_kernel<<<(SB * TS_ / 4 + 255) / 256, blk>>>((const float4*)tok, (__nv_bfloat162*)tok_b, SB * TS_ / 4);
    // logits = tok @ Wgen^T + bgen -> d_out; fused rowsum of exp(logits)
    mma_bf16_nt_kernel<<<dim3(250, 16, 1), blkG, SMEM>>>(tok_b, wgen_b, bgen, out, rowsum,
                                                         TS_, TS_, TS_, V_);
    // coef = log(gen) - log(rowsum)
    coef_kernel<<<SB / 256, blk>>>(rowsum, gts, coef);
    // base log-probs in place
    lp_kernel<<<(SB * (V_ / 4)) / 256, 256>>>(out, coef);
    // copy scatter (log-space CAS merge)
    scatter_kernel<<<(SB * T_) / 256, 256>>>(out, attn, gts, cseq);
}

// round 9
// speedup vs baseline: 1.0747x; 1.0030x over previous
#include <cuda_runtime.h>
#include <cuda_bf16.h>
#include <math.h>
#include <stdint.h>

// Problem dims (fixed for this dataset)
constexpr int S_  = 256;
constexpr int B_  = 8;
constexpr int T_  = 1024;
constexpr int D_  = 512;
constexpr int TS_ = 512;
constexpr int V_  = 32000;
constexpr int SB  = S_ * B_;   // 2048
constexpr int TB  = T_ * B_;   // 8192

// ---------------------------------------------------------------------------
// Scratch arena
// ---------------------------------------------------------------------------
constexpr size_t OQ  = 0;                        // q / later x      : SB*D
constexpr size_t OK_ = OQ  + (size_t)SB * D_;    // k                : TB*D
constexpr size_t OV  = OK_ + (size_t)TB * D_;    // v                : TB*D
constexpr size_t OVT = OV  + (size_t)TB * D_;    // v transposed     : TB*D
constexpr size_t OA  = OVT + (size_t)TB * D_;    // attn (scores)    : SB*T
constexpr size_t OC  = OA  + (size_t)SB * T_;    // ctx              : SB*D
constexpr size_t OL  = OC  + (size_t)SB * D_;    // layernorm out    : SB*D
constexpr size_t OT  = OL  + (size_t)SB * D_;    // outs_token (f32) : SB*D
constexpr size_t OG  = OT  + (size_t)SB * D_;    // gates            : SB*2
constexpr size_t OM  = OG  + (size_t)SB * 2;     // per-row coef     : SB
constexpr size_t ORS = OM  + SB;                 // rowsum exp       : SB
constexpr size_t OWB = ORS + SB;                 // Wgen bf16        : V*TS/2 floats
constexpr size_t OTB = OWB + (size_t)V_ * TS_ / 2;  // tok bf16      : SB*TS/2
constexpr size_t SCRATCH_FLOATS = OTB + (size_t)SB * TS_ / 2;

__device__ float g_scratch[SCRATCH_FLOATS];

// ---------------------------------------------------------------------------
// math helpers
// ---------------------------------------------------------------------------
__device__ __forceinline__ float fexp(float x) {
    float t = fmaxf(fminf(x * 1.4426950408889634f, 126.f), -126.f);
    float mg = t + 12582912.f;
    int   n  = __float_as_int(mg) - 0x4B400000;
    float f  = t - (mg - 12582912.f);
    float p  = 1.54035304e-4f;
    p = fmaf(p, f, 1.33335581e-3f);
    p = fmaf(p, f, 9.61812911e-3f);
    p = fmaf(p, f, 5.55041087e-2f);
    p = fmaf(p, f, 2.40226507e-1f);
    p = fmaf(p, f, 6.93147182e-1f);
    p = fmaf(p, f, 1.0f);
    return __int_as_float(__float_as_int(p) + (n << 23));
}

__device__ __forceinline__ void mma_tf32(float& c0, float& c1, float& c2, float& c3,
                                         unsigned a0, unsigned a1, unsigned a2, unsigned a3,
                                         unsigned b0, unsigned b1)
{
    asm volatile(
        "mma.sync.aligned.m16n8k8.row.col.f32.tf32.tf32.f32 "
        "{%0,%1,%2,%3}, {%4,%5,%6,%7}, {%8,%9}, {%0,%1,%2,%3};"
        : "+f"(c0), "+f"(c1), "+f"(c2), "+f"(c3)
        : "r"(a0), "r"(a1), "r"(a2), "r"(a3), "r"(b0), "r"(b1));
}

__device__ __forceinline__ void mma_bf16(float& c0, float& c1, float& c2, float& c3,
                                         unsigned a0, unsigned a1, unsigned a2, unsigned a3,
                                         unsigned b0, unsigned b1)
{
    asm volatile(
        "mma.sync.aligned.m16n8k16.row.col.f32.bf16.bf16.f32 "
        "{%0,%1,%2,%3}, {%4,%5,%6,%7}, {%8,%9}, {%0,%1,%2,%3};"
        : "+f"(c0), "+f"(c1), "+f"(c2), "+f"(c3)
        : "r"(a0), "r"(a1), "r"(a2), "r"(a3), "r"(b0), "r"(b1));
}

__device__ __forceinline__ void cp16(unsigned dst, const void* src) {
    asm volatile("cp.async.cg.shared.global [%0], [%1], 16;\n" :: "r"(dst), "l"(src));
}

// ---------------------------------------------------------------------------
// Tensor-core NT GEMM (tf32): C[m,n] = ACT(alpha*(sum A[m,k]*B[n,k] + bias[n]))
// 128x128 block, 4 warps, warp tile 64x64, BK=32, 64KB SMEM, 2 CTAs/SM.
// If ACT==1 and Cb != nullptr, also writes bf16 copy of C into Cb.
// ---------------------------------------------------------------------------
template <int ACT>
__global__ __launch_bounds__(128, 2)
void mma_nt_kernel(const float* __restrict__ A, const float* __restrict__ Bm,
                   const float* __restrict__ bias, float* __restrict__ C,
                   __nv_bfloat16* __restrict__ Cb,
                   int K, int lda, int ldb, int ldc,
                   long sA, long sB, long sC, float alpha)
{
    extern __shared__ unsigned sh[];

    A  += (long)blockIdx.z * sA;
    Bm += (long)blockIdx.z * sB;
    C  += (long)blockIdx.z * sC;

    const int t    = threadIdx.x;
    const int lane = t & 31;
    const int warp = t >> 5;
    const int wm   = (warp >> 1) * 64;
    const int wn   = (warp & 1) * 64;
    const int grp  = lane >> 2;
    const int qid  = lane & 3;

    const long m0 = (long)blockIdx.y * 128;
    const long n0 = (long)blockIdx.x * 128;

    float acc[4][8][4];
#pragma unroll
    for (int mi = 0; mi < 4; mi++)
#pragma unroll
        for (int ni = 0; ni < 8; ni++)
#pragma unroll
            for (int c = 0; c < 4; c++) acc[mi][ni][c] = 0.f;

    const int row0 = t >> 3;
    const int c4   = t & 7;
    const float* aptr0 = A  + (m0 + row0) * lda + c4 * 4;
    const float* bptr0 = Bm + (n0 + row0) * ldb + c4 * 4;
    const unsigned soff0 = (unsigned)(row0 * 32 + ((c4 ^ (row0 & 7)) << 2)) * 4u;
    const unsigned sbase = (unsigned)__cvta_generic_to_shared(sh);

    auto issue = [&](int stage, int koff) {
        unsigned ab = sbase + (unsigned)stage * 16384u + soff0;
        unsigned bb = sbase + 32768u + (unsigned)stage * 16384u + soff0;
#pragma unroll
        for (int i = 0; i < 8; i++) {
            cp16(ab + i * 2048u, aptr0 + (long)i * 16 * lda + koff);
            cp16(bb + i * 2048u, bptr0 + (long)i * 16 * ldb + koff);
        }
        asm volatile("cp.async.commit_group;\n" ::: "memory");
    };

    issue(0, 0);
    const int nIter = K >> 5;
    for (int it = 0; it < nIter; ++it) {
        asm volatile("cp.async.wait_group 0;\n" ::: "memory");
        __syncthreads();
        if (it + 1 < nIter) issue((it + 1) & 1, (it + 1) * 32);

        const unsigned* Asb = sh + (it & 1) * 4096;
        const unsigned* Bsb = sh + 8192 + (it & 1) * 4096;
#pragma unroll
        for (int kk = 0; kk < 4; kk++) {
            unsigned af[4][4], bf[8][2];
#pragma unroll
            for (int mi = 0; mi < 4; mi++) {
                int m  = wm + mi * 16 + grp;
                int m8 = m + 8;
                af[mi][0] = Asb[m  * 32 + ((( kk * 2    ) ^ (m  & 7)) << 2) + qid];
                af[mi][1] = Asb[m8 * 32 + ((( kk * 2    ) ^ (m8 & 7)) << 2) + qid];
                af[mi][2] = Asb[m  * 32 + ((( kk * 2 + 1) ^ (m  & 7)) << 2) + qid];
                af[mi][3] = Asb[m8 * 32 + ((( kk * 2 + 1) ^ (m8 & 7)) << 2) + qid];
            }
#pragma unroll
            for (int ni = 0; ni < 8; ni++) {
                int n = wn + ni * 8 + grp;
                bf[ni][0] = Bsb[n * 32 + ((( kk * 2    ) ^ (n & 7)) << 2) + qid];
                bf[ni][1] = Bsb[n * 32 + ((( kk * 2 + 1) ^ (n & 7)) << 2) + qid];
            }
#pragma unroll
            for (int mi = 0; mi < 4; mi++)
#pragma unroll
                for (int ni = 0; ni < 8; ni++)
                    mma_tf32(acc[mi][ni][0], acc[mi][ni][1], acc[mi][ni][2], acc[mi][ni][3],
                             af[mi][0], af[mi][1], af[mi][2], af[mi][3],
                             bf[ni][0], bf[ni][1]);
        }
        __syncthreads();
    }

#pragma unroll
    for (int mi = 0; mi < 4; mi++) {
        long r0 = m0 + wm + mi * 16 + grp;
        long r1 = r0 + 8;
#pragma unroll
        for (int ni = 0; ni < 8; ni++) {
            long col = n0 + wn + ni * 8 + qid * 2;
            float bv0 = 0.f, bv1 = 0.f;
            if (bias) { bv0 = bias[col]; bv1 = bias[col + 1]; }
            float v00 = (acc[mi][ni][0] + bv0) * alpha;
            float v01 = (acc[mi][ni][1] + bv1) * alpha;
            float v10 = (acc[mi][ni][2] + bv0) * alpha;
            float v11 = (acc[mi][ni][3] + bv1) * alpha;
            if (ACT == 1) { v00 = tanhf(v00); v01 = tanhf(v01); v10 = tanhf(v10); v11 = tanhf(v11); }
            *(float2*)(C + r0 * ldc + col) = make_float2(v00, v01);
            *(float2*)(C + r1 * ldc + col) = make_float2(v10, v11);
            if (ACT == 1 && Cb) {
                *(__nv_bfloat162*)(Cb + r0 * ldc + col) = __floats2bfloat162_rn(v00, v01);
                *(__nv_bfloat162*)(Cb + r1 * ldc + col) = __floats2bfloat162_rn(v10, v11);
            }
        }
    }
}

// ---------------------------------------------------------------------------
// bf16 NT GEMM + fused exp-rowsum: 128x128 block, 4 warps, warp 64x64, BK=64.
// 3-stage cp.async pipeline: 3 x (16KB A + 16KB B) = 96KB SMEM, 2 CTAs/SM.
// Loads run two chunks ahead of compute (wait_group tapers 2->1->0).
// ---------------------------------------------------------------------------
__global__ __launch_bounds__(128, 2)
void mma_bf16_nt_kernel(const __nv_bfloat16* __restrict__ A,
                        const __nv_bfloat16* __restrict__ Bm,
                        const float* __restrict__ bias, float* __restrict__ C,
                        float* __restrict__ rowsum,
                        int K, int lda, int ldb, int ldc)
{
    extern __shared__ unsigned sh[];
    char* shc = (char*)sh;

    const int t    = threadIdx.x;
    const int lane = t & 31;
    const int warp = t >> 5;
    const int wm   = (warp >> 1) * 64;
    const int wn   = (warp & 1) * 64;
    const int grp  = lane >> 2;
    const int qid  = lane & 3;

    const long m0 = (long)blockIdx.y * 128;
    const long n0 = (long)blockIdx.x * 128;

    float acc[4][8][4];
#pragma unroll
    for (int mi = 0; mi < 4; mi++)
#pragma unroll
        for (int ni = 0; ni < 8; ni++)
#pragma unroll
            for (int c = 0; c < 4; c++) acc[mi][ni][c] = 0.f;

    // tile = 128 rows x 64 bf16 = 16KB per operand; 1024 chunks, 8/thread
    const int row0 = t >> 3;
    const int c8   = t & 7;
    const __nv_bfloat16* aptr0 = A  + (m0 + row0) * lda + c8 * 8;
    const __nv_bfloat16* bptr0 = Bm + (n0 + row0) * ldb + c8 * 8;
    const unsigned soff0 = (unsigned)(row0 * 128 + ((c8 ^ (row0 & 7)) << 4));
    const unsigned sbase = (unsigned)__cvta_generic_to_shared(sh);

    // stage s: A at s*32768, B at s*32768 + 16384
    auto issue = [&](int stage, int koff) {
        unsigned ab = sbase + (unsigned)stage * 32768u + soff0;
        unsigned bb = ab + 16384u;
#pragma unroll
        for (int i = 0; i < 8; i++) {
            cp16(ab + i * 2048u, aptr0 + (long)i * 16 * lda + koff);
            cp16(bb + i * 2048u, bptr0 + (long)i * 16 * ldb + koff);
        }
        asm volatile("cp.async.commit_group;\n" ::: "memory");
    };

    const int nIter = K >> 6;                 // BK=64 (8 for K=512)
    issue(0, 0);
    if (nIter > 1) issue(1, 64);
    if (nIter > 2) issue(2, 128);

    for (int it = 0; it < nIter; ++it) {
        // ensure chunk `it` is resident: pending after it = min(2, nIter-1-it)
        int rem = nIter - 1 - it;
        if (rem >= 2)      asm volatile("cp.async.wait_group 2;\n" ::: "memory");
        else if (rem == 1) asm volatile("cp.async.wait_group 1;\n" ::: "memory");
        else               asm volatile("cp.async.wait_group 0;\n" ::: "memory");
        __syncthreads();

        int s = it % 3;
        const char* Asb = shc + s * 32768;
        const char* Bsb = Asb + 16384;
#pragma unroll
        for (int kk = 0; kk < 4; kk++) {      // 16 k per step
            unsigned af[4][4], bf[8][2];
#pragma unroll
            for (int mi = 0; mi < 4; mi++) {
                int m  = wm + mi * 16 + grp;
                int m8 = m + 8;
                af[mi][0] = *(const unsigned*)(Asb + m  * 128 + (((kk*2  ) ^ (m  & 7)) << 4) + qid * 4);
                af[mi][1] = *(const unsigned*)(Asb + m8 * 128 + (((kk*2  ) ^ (m8 & 7)) << 4) + qid * 4);
                af[mi][2] = *(const unsigned*)(Asb + m  * 128 + (((kk*2+1) ^ (m  & 7)) << 4) + qid * 4);
                af[mi][3] = *(const unsigned*)(Asb + m8 * 128 + (((kk*2+1) ^ (m8 & 7)) << 4) + qid * 4);
            }
#pragma unroll
            for (int ni = 0; ni < 8; ni++) {
                int n = wn + ni * 8 + grp;
                bf[ni][0] = *(const unsigned*)(Bsb + n * 128 + (((kk*2  ) ^ (n & 7)) << 4) + qid * 4);
                bf[ni][1] = *(const unsigned*)(Bsb + n * 128 + (((kk*2+1) ^ (n & 7)) << 4) + qid * 4);
            }
#pragma unroll
            for (int mi = 0; mi < 4; mi++)
#pragma unroll
                for (int ni = 0; ni < 8; ni++)
                    mma_bf16(acc[mi][ni][0], acc[mi][ni][1], acc[mi][ni][2], acc[mi][ni][3],
                             af[mi][0], af[mi][1], af[mi][2], af[mi][3],
                             bf[ni][0], bf[ni][1]);
        }
        __syncthreads();                      // all warps done reading stage s
        if (it + 3 < nIter) issue(s, (it + 3) * 64);
    }

    // epilogue: write logits + per-row sum of exp
#pragma unroll
    for (int mi = 0; mi < 4; mi++) {
        long r0 = m0 + wm + mi * 16 + grp;
        long r1 = r0 + 8;
        float e0 = 0.f, e1 = 0.f;
#pragma unroll
        for (int ni = 0; ni < 8; ni++) {
            long col = n0 + wn + ni * 8 + qid * 2;
            float bv0 = bias[col], bv1 = bias[col + 1];
            float v00 = acc[mi][ni][0] + bv0;
            float v01 = acc[mi][ni][1] + bv1;
            float v10 = acc[mi][ni][2] + bv0;
            float v11 = acc[mi][ni][3] + bv1;
            *(float2*)(C + r0 * ldc + col) = make_float2(v00, v01);
            *(float2*)(C + r1 * ldc + col) = make_float2(v10, v11);
            e0 += fexp(v00) + fexp(v01);
            e1 += fexp(v10) + fexp(v11);
        }
        e0 += __shfl_xor_sync(0xFFFFFFFFu, e0, 1);
        e0 += __shfl_xor_sync(0xFFFFFFFFu, e0, 2);
        e1 += __shfl_xor_sync(0xFFFFFFFFu, e1, 1);
        e1 += __shfl_xor_sync(0xFFFFFFFFu, e1, 2);
        if (qid == 0) {
            atomicAdd(rowsum + r0, e0);
            atomicAdd(rowsum + r1, e1);
        }
    }
}

// ---------------------------------------------------------------------------
// fp32 -> bf16 convert
// ---------------------------------------------------------------------------
__global__ __launch_bounds__(256)
void f2b_kernel(const float4* __restrict__ in, __nv_bfloat162* __restrict__ out, int n4)
{
    int i = blockIdx.x * 256 + threadIdx.x;
    if (i >= n4) return;
    float4 v = in[i];
    out[i * 2]     = __floats2bfloat162_rn(v.x, v.y);
    out[i * 2 + 1] = __floats2bfloat162_rn(v.z, v.w);
}

__global__ void zero_kernel(float* __restrict__ p)
{
    p[blockIdx.x * 256 + threadIdx.x] = 0.f;
}

__global__ void coef_kernel(const float* __restrict__ rowsum,
                            const float* __restrict__ gates, float* __restrict__ coef)
{
    int r = blockIdx.x * 256 + threadIdx.x;
    coef[r] = __logf(gates[r * 2 + 0]) - __logf(rowsum[r]);
}

// ---------------------------------------------------------------------------
// v transpose: vt[b][d][t] = v[(t*B+b)*D + d].
// ---------------------------------------------------------------------------
__global__ __launch_bounds__(256)
void vt_kernel(const float* __restrict__ v, float* __restrict__ vt)
{
    __shared__ float tile[32][33];
    int b  = blockIdx.z;
    int t0 = blockIdx.x * 32;
    int d0 = blockIdx.y * 32;
    int x  = threadIdx.x & 31;
    int y  = threadIdx.x >> 5;
#pragma unroll
    for (int j = 0; j < 32; j += 8)
        tile[y + j][x] = v[((long)(t0 + y + j) * B_ + b) * D_ + d0 + x];
    __syncthreads();
#pragma unroll
    for (int j = 0; j < 32; j += 8)
        vt[(long)b * D_ * T_ + (long)(d0 + y + j) * T_ + t0 + x] = tile[x][y + j];
}

// ---------------------------------------------------------------------------
// Softmax over T (in-place). mask: [B,T] bytes.
// ---------------------------------------------------------------------------
__global__ __launch_bounds__(256)
void attn_softmax_kernel(float* __restrict__ attn, const unsigned char* __restrict__ mask)
{
    int row = blockIdx.x;
    int b   = row & (B_ - 1);
    float* p = attn + (long)row * T_;
    const unsigned char* mrow = mask + (long)b * T_;
    int t = threadIdx.x;
    __shared__ float red[256];

    float x[4];
    float mx = -1e30f;
#pragma unroll
    for (int i = 0; i < 4; i++) {
        int tt = t + i * 256;
        float v = p[tt];
        if (mrow[tt]) v = -1e9f;
        x[i] = v;
        mx = fmaxf(mx, v);
    }
    red[t] = mx; __syncthreads();
    for (int s = 128; s > 0; s >>= 1) {
        if (t < s) red[t] = fmaxf(red[t], red[t + s]);
        __syncthreads();
    }
    mx = red[0]; __syncthreads();

    float sum = 0.f;
#pragma unroll
    for (int i = 0; i < 4; i++) { x[i] = fexp(x[i] - mx); sum += x[i]; }
    red[t] = sum; __syncthreads();
    for (int s = 128; s > 0; s >>= 1) {
        if (t < s) red[t] += red[t + s];
        __syncthreads();
    }
    float inv = 1.f / red[0];
#pragma unroll
    for (int i = 0; i < 4; i++) p[t + i * 256] = x[i] * inv;
}

// ---------------------------------------------------------------------------
// LayerNorm(outs + x).
// ---------------------------------------------------------------------------
__global__ __launch_bounds__(256)
void ln_kernel(const float* __restrict__ outs, const float* __restrict__ x,
               const float* __restrict__ g, const float* __restrict__ bb,
               float* __restrict__ out)
{
    int row = blockIdx.x;
    int t = threadIdx.x;
    const float* o  = outs + (long)row * D_;
    const float* xr = x    + (long)row * D_;
    __shared__ float red[256];

    float v0 = o[t] + xr[t];
    float v1 = o[t + 256] + xr[t + 256];

    red[t] = v0 + v1; __syncthreads();
    for (int s = 128; s > 0; s >>= 1) { if (t < s) red[t] += red[t + s]; __syncthreads(); }
    float mu = red[0] * (1.f / D_); __syncthreads();

    float d0 = v0 - mu, d1 = v1 - mu;
    red[t] = d0 * d0 + d1 * d1; __syncthreads();
    for (int s = 128; s > 0; s >>= 1) { if (t < s) red[t] += red[t + s]; __syncthreads(); }
    float inv = rsqrtf(red[0] * (1.f / D_) + 1e-5f);

    out[(long)row * D_ + t]       = d0 * inv * g[t]       + bb[t];
    out[(long)row * D_ + t + 256] = d1 * inv * g[t + 256] + bb[t + 256];
}

// ---------------------------------------------------------------------------
// 2-way gate
// ---------------------------------------------------------------------------
__global__ __launch_bounds__(128)
void gates_kernel(const float* __restrict__ tok, const float* __restrict__ Wdiv,
                  const float* __restrict__ bdiv, float* __restrict__ gates)
{
    int row = blockIdx.x;
    int t = threadIdx.x;
    const float* x = tok + (long)row * D_;
    float z0 = 0.f, z1 = 0.f;
    for (int d = t; d < D_; d += 128) {
        float xv = x[d];
        z0 = fmaf(xv, Wdiv[d],      z0);
        z1 = fmaf(xv, Wdiv[D_ + d], z1);
    }
    __shared__ float r0[128], r1[128];
    r0[t] = z0; r1[t] = z1; __syncthreads();
    for (int s = 64; s > 0; s >>= 1) {
        if (t < s) { r0[t] += r0[t + s]; r1[t] += r1[t + s]; }
        __syncthreads();
    }
    if (t == 0) {
        float a = r0[0] + bdiv[0], b = r1[0] + bdiv[1];
        float m = fmaxf(a, b);
        float e0 = __expf(a - m), e1 = __expf(b - m);
        float inv = 1.f / (e0 + e1);
        gates[row * 2 + 0] = e0 * inv;
        gates[row * 2 + 1] = e1 * inv;
    }
}

// ---------------------------------------------------------------------------
// Log-prob base pass: out = coef[row] + z.
// ---------------------------------------------------------------------------
__global__ __launch_bounds__(256)
void lp_kernel(float* __restrict__ out, const float* __restrict__ coef)
{
    long i4 = (long)blockIdx.x * 256 + threadIdx.x;
    int row = (int)(i4 / (V_ / 4));
    float c = __ldg(coef + row);
    float4* p = (float4*)out + i4;
    float4 v = *p;
    v.x += c; v.y += c; v.z += c; v.w += c;
    *p = v;
}

// ---------------------------------------------------------------------------
// Copy-scatter in log space via CAS.
// ---------------------------------------------------------------------------
__global__ __launch_bounds__(256)
void scatter_kernel(float* __restrict__ out, const float* __restrict__ attn,
                    const float* __restrict__ gates, const int* __restrict__ copy_seq)
{
    int gid = blockIdx.x * 256 + threadIdx.x;
    int row = gid >> 10;
    int t   = gid & 1023;
    int b   = row & (B_ - 1);
    float val = gates[row * 2 + 1] * attn[(long)row * T_ + t];
    int idx = copy_seq[t * B_ + b];
    int* ia = (int*)(out + (long)row * V_ + idx);

    int assumed = *ia;
    int old;
    do {
        old = assumed;
        float cur = __int_as_float(old);
        float nv = __logf(__expf(cur) + val);
        assumed = atomicCAS(ia, old, __float_as_int(nv));
    } while (assumed != old);
}

// ---------------------------------------------------------------------------
// Launch
// ---------------------------------------------------------------------------
extern "C" void kernel_launch(void* const* d_in, const int* in_sizes, int n_in,
                              void* d_out, int out_size)
{
    const float* outs = (const float*)d_in[0];
    const float* gs   = (const float*)d_in[1];
    const unsigned char* mask = (const unsigned char*)d_in[2];
    const int*   cseq = (const int*)d_in[3];
    const float* Wq = (const float*)d_in[4],  *bq = (const float*)d_in[5];
    const float* Wk = (const float*)d_in[6],  *bk = (const float*)d_in[7];
    const float* Wv = (const float*)d_in[8],  *bv = (const float*)d_in[9];
    const float* Wo = (const float*)d_in[10], *bo = (const float*)d_in[11];
    const float* lng = (const float*)d_in[12], *lnb = (const float*)d_in[13];
    const float* Wt = (const float*)d_in[14], *bt = (const float*)d_in[15];
    const float* Wgen = (const float*)d_in[16], *bgen = (const float*)d_in[17];
    const float* Wdiv = (const float*)d_in[18], *bdiv = (const float*)d_in[19];
    float* out = (float*)d_out;

    float* sc = nullptr;
    cudaGetSymbolAddress((void**)&sc, g_scratch);
    float* q     = sc + OQ;
    float* k     = sc + OK_;
    float* v     = sc + OV;
    float* vt    = sc + OVT;
    float* attn  = sc + OA;
    float* ctx   = sc + OC;
    float* ln    = sc + OL;
    float* tok   = sc + OT;
    float* gts   = sc + OG;
    float* coef  = sc + OM;
    float* rowsum = sc + ORS;
    __nv_bfloat16* wgen_b = (__nv_bfloat16*)(sc + OWB);
    __nv_bfloat16* tok_b  = (__nv_bfloat16*)(sc + OTB);

    const float scale = 0.044194173824159216f; // 1/sqrt(512)
    constexpr int SMEM  = 65536;
    constexpr int SMEM3 = 98304;
    cudaFuncSetAttribute(mma_nt_kernel<0>, cudaFuncAttributeMaxDynamicSharedMemorySize, SMEM);
    cudaFuncSetAttribute(mma_nt_kernel<1>, cudaFuncAttributeMaxDynamicSharedMemorySize, SMEM);
    cudaFuncSetAttribute(mma_bf16_nt_kernel, cudaFuncAttributeMaxDynamicSharedMemorySize, SMEM3);
    dim3 blk(256);
    dim3 blkG(128);

    // early: Wgen -> bf16, rowsum = 0
    f2b_kernel<<<(V_ * TS_ / 4 + 255) / 256, blk>>>((const float4*)Wgen, (__nv_bfloat162*)wgen_b, V_ * TS_ / 4);
    zero_kernel<<<SB / 256, blk>>>(rowsum);

    // q = (outs @ Wq^T + bq) * scale       [2048 x 512]
    mma_nt_kernel<0><<<dim3(4, 16, 1), blkG, SMEM>>>(outs, Wq, bq, q, nullptr, D_, D_, D_, D_, 0, 0, 0, scale);
    // k = gs @ Wk^T + bk                   [8192 x 512]
    mma_nt_kernel<0><<<dim3(4, 64, 1), blkG, SMEM>>>(gs, Wk, bk, k, nullptr, D_, D_, D_, D_, 0, 0, 0, 1.f);
    // v = gs @ Wv^T + bv
    mma_nt_kernel<0><<<dim3(4, 64, 1), blkG, SMEM>>>(gs, Wv, bv, v, nullptr, D_, D_, D_, D_, 0, 0, 0, 1.f);
    // v transpose for ctx GEMM
    vt_kernel<<<dim3(32, 16, 8), blk>>>(v, vt);
    // scores[s,b,t] = q[s,b,:] . k[t,b,:]  (batched over b)
    mma_nt_kernel<0><<<dim3(8, 2, 8), blkG, SMEM>>>(q, k, nullptr, attn, nullptr,
                                                    D_, B_ * D_, B_ * D_, B_ * T_,
                                                    D_, D_, T_, 1.f);
    // softmax over t (with mask)
    attn_softmax_kernel<<<SB, 256>>>(attn, mask);
    // ctx[s,b,:] = attn[s,b,:] @ v[:,b,:]   (NT vs v_T, batched over b)
    mma_nt_kernel<0><<<dim3(4, 2, 8), blkG, SMEM>>>(attn, vt, nullptr, ctx, nullptr,
                                                    T_, B_ * T_, T_, B_ * D_,
                                                    T_, (long)D_ * T_, D_, 1.f);
    // x = ctx @ Wo^T + bo   -> reuse q buffer
    mma_nt_kernel<0><<<dim3(4, 16, 1), blkG, SMEM>>>(ctx, Wo, bo, q, nullptr, D_, D_, D_, D_, 0, 0, 0, 1.f);
    // outs_ln = LN(outs + x)
    ln_kernel<<<SB, 256>>>(outs, q, lng, lnb, ln);
    // tok = tanh(outs_ln @ Wt^T + bt); also emits tok_b (bf16) fused
    mma_nt_kernel<1><<<dim3(4, 16, 1), blkG, SMEM>>>(ln, Wt, bt, tok, tok_b, D_, D_, D_, TS_, 0, 0, 0, 1.f);
    // gates
    gates_kernel<<<SB, 128>>>(tok, Wdiv, bdiv, gts);
    // logits = tok @ Wgen^T + bgen -> d_out; fused rowsum of exp(logits)
    mma_bf16_nt_kernel<<<dim3(250, 16, 1), blkG, SMEM3>>>(tok_b, wgen_b, bgen, out, rowsum,
                                                          TS_, TS_, TS_, V_);
    // coef = log(gen) - log(rowsum)
    coef_kernel<<<SB / 256, blk>>>(rowsum, gts, coef);
    // base log-probs in place
    lp_kernel<<<(SB * (V_ / 4)) / 256, 256>>>(out, coef);
    // copy scatter (log-space CAS merge)
    scatter_kernel<<<(SB * T_) / 256, 256>>>(out, attn, gts, cseq);
}

// round 10
// speedup vs baseline: 1.0810x; 1.0058x over previous
#include <cuda_runtime.h>
#include <cuda_bf16.h>
#include <math.h>
#include <stdint.h>

// Problem dims (fixed for this dataset)
constexpr int S_  = 256;
constexpr int B_  = 8;
constexpr int T_  = 1024;
constexpr int D_  = 512;
constexpr int TS_ = 512;
constexpr int V_  = 32000;
constexpr int SB  = S_ * B_;   // 2048
constexpr int TB  = T_ * B_;   // 8192

// ---------------------------------------------------------------------------
// Scratch arena
// ---------------------------------------------------------------------------
constexpr size_t OQ  = 0;                        // q / later x      : SB*D
constexpr size_t OK_ = OQ  + (size_t)SB * D_;    // k                : TB*D
constexpr size_t OV  = OK_ + (size_t)TB * D_;    // v                : TB*D
constexpr size_t OVT = OV  + (size_t)TB * D_;    // v transposed     : TB*D
constexpr size_t OA  = OVT + (size_t)TB * D_;    // attn (scores)    : SB*T
constexpr size_t OC  = OA  + (size_t)SB * T_;    // ctx              : SB*D
constexpr size_t OL  = OC  + (size_t)SB * D_;    // layernorm out    : SB*D
constexpr size_t OT  = OL  + (size_t)SB * D_;    // outs_token (f32) : SB*D
constexpr size_t OG  = OT  + (size_t)SB * D_;    // gates            : SB*2
constexpr size_t OM  = OG  + (size_t)SB * 2;     // per-row coef     : SB
constexpr size_t ORS = OM  + SB;                 // rowsum exp       : SB
constexpr size_t OWB = ORS + SB;                 // Wgen bf16        : V*TS/2 floats
constexpr size_t OTB = OWB + (size_t)V_ * TS_ / 2;  // tok bf16      : SB*TS/2
constexpr size_t SCRATCH_FLOATS = OTB + (size_t)SB * TS_ / 2;

__device__ float g_scratch[SCRATCH_FLOATS];

// ---------------------------------------------------------------------------
// math helpers
// ---------------------------------------------------------------------------
__device__ __forceinline__ float fexp(float x) {
    float t = fmaxf(fminf(x * 1.4426950408889634f, 126.f), -126.f);
    float mg = t + 12582912.f;
    int   n  = __float_as_int(mg) - 0x4B400000;
    float f  = t - (mg - 12582912.f);
    float p  = 1.54035304e-4f;
    p = fmaf(p, f, 1.33335581e-3f);
    p = fmaf(p, f, 9.61812911e-3f);
    p = fmaf(p, f, 5.55041087e-2f);
    p = fmaf(p, f, 2.40226507e-1f);
    p = fmaf(p, f, 6.93147182e-1f);
    p = fmaf(p, f, 1.0f);
    return __int_as_float(__float_as_int(p) + (n << 23));
}

__device__ __forceinline__ void mma_tf32(float& c0, float& c1, float& c2, float& c3,
                                         unsigned a0, unsigned a1, unsigned a2, unsigned a3,
                                         unsigned b0, unsigned b1)
{
    asm volatile(
        "mma.sync.aligned.m16n8k8.row.col.f32.tf32.tf32.f32 "
        "{%0,%1,%2,%3}, {%4,%5,%6,%7}, {%8,%9}, {%0,%1,%2,%3};"
        : "+f"(c0), "+f"(c1), "+f"(c2), "+f"(c3)
        : "r"(a0), "r"(a1), "r"(a2), "r"(a3), "r"(b0), "r"(b1));
}

__device__ __forceinline__ void mma_bf16(float& c0, float& c1, float& c2, float& c3,
                                         unsigned a0, unsigned a1, unsigned a2, unsigned a3,
                                         unsigned b0, unsigned b1)
{
    asm volatile(
        "mma.sync.aligned.m16n8k16.row.col.f32.bf16.bf16.f32 "
        "{%0,%1,%2,%3}, {%4,%5,%6,%7}, {%8,%9}, {%0,%1,%2,%3};"
        : "+f"(c0), "+f"(c1), "+f"(c2), "+f"(c3)
        : "r"(a0), "r"(a1), "r"(a2), "r"(a3), "r"(b0), "r"(b1));
}

__device__ __forceinline__ void ldsm_x4(unsigned& r0, unsigned& r1, unsigned& r2, unsigned& r3,
                                        unsigned addr)
{
    asm volatile("ldmatrix.sync.aligned.m8n8.x4.shared.b16 {%0,%1,%2,%3}, [%4];"
                 : "=r"(r0), "=r"(r1), "=r"(r2), "=r"(r3) : "r"(addr));
}

__device__ __forceinline__ void cp16(unsigned dst, const void* src) {
    asm volatile("cp.async.cg.shared.global [%0], [%1], 16;\n" :: "r"(dst), "l"(src));
}

// ---------------------------------------------------------------------------
// Tensor-core NT GEMM (tf32): C[m,n] = ACT(alpha*(sum A[m,k]*B[n,k] + bias[n]))
// 128x128 block, 4 warps, warp tile 64x64, BK=32, 64KB SMEM, 2 CTAs/SM.
// If ACT==1 and Cb != nullptr, also writes bf16 copy of C into Cb.
// ---------------------------------------------------------------------------
template <int ACT>
__global__ __launch_bounds__(128, 2)
void mma_nt_kernel(const float* __restrict__ A, const float* __restrict__ Bm,
                   const float* __restrict__ bias, float* __restrict__ C,
                   __nv_bfloat16* __restrict__ Cb,
                   int K, int lda, int ldb, int ldc,
                   long sA, long sB, long sC, float alpha)
{
    extern __shared__ unsigned sh[];

    A  += (long)blockIdx.z * sA;
    Bm += (long)blockIdx.z * sB;
    C  += (long)blockIdx.z * sC;

    const int t    = threadIdx.x;
    const int lane = t & 31;
    const int warp = t >> 5;
    const int wm   = (warp >> 1) * 64;
    const int wn   = (warp & 1) * 64;
    const int grp  = lane >> 2;
    const int qid  = lane & 3;

    const long m0 = (long)blockIdx.y * 128;
    const long n0 = (long)blockIdx.x * 128;

    float acc[4][8][4];
#pragma unroll
    for (int mi = 0; mi < 4; mi++)
#pragma unroll
        for (int ni = 0; ni < 8; ni++)
#pragma unroll
            for (int c = 0; c < 4; c++) acc[mi][ni][c] = 0.f;

    const int row0 = t >> 3;
    const int c4   = t & 7;
    const float* aptr0 = A  + (m0 + row0) * lda + c4 * 4;
    const float* bptr0 = Bm + (n0 + row0) * ldb + c4 * 4;
    const unsigned soff0 = (unsigned)(row0 * 32 + ((c4 ^ (row0 & 7)) << 2)) * 4u;
    const unsigned sbase = (unsigned)__cvta_generic_to_shared(sh);

    auto issue = [&](int stage, int koff) {
        unsigned ab = sbase + (unsigned)stage * 16384u + soff0;
        unsigned bb = sbase + 32768u + (unsigned)stage * 16384u + soff0;
#pragma unroll
        for (int i = 0; i < 8; i++) {
            cp16(ab + i * 2048u, aptr0 + (long)i * 16 * lda + koff);
            cp16(bb + i * 2048u, bptr0 + (long)i * 16 * ldb + koff);
        }
        asm volatile("cp.async.commit_group;\n" ::: "memory");
    };

    issue(0, 0);
    const int nIter = K >> 5;
    for (int it = 0; it < nIter; ++it) {
        asm volatile("cp.async.wait_group 0;\n" ::: "memory");
        __syncthreads();
        if (it + 1 < nIter) issue((it + 1) & 1, (it + 1) * 32);

        const unsigned* Asb = sh + (it & 1) * 4096;
        const unsigned* Bsb = sh + 8192 + (it & 1) * 4096;
#pragma unroll
        for (int kk = 0; kk < 4; kk++) {
            unsigned af[4][4], bf[8][2];
#pragma unroll
            for (int mi = 0; mi < 4; mi++) {
                int m  = wm + mi * 16 + grp;
                int m8 = m + 8;
                af[mi][0] = Asb[m  * 32 + ((( kk * 2    ) ^ (m  & 7)) << 2) + qid];
                af[mi][1] = Asb[m8 * 32 + ((( kk * 2    ) ^ (m8 & 7)) << 2) + qid];
                af[mi][2] = Asb[m  * 32 + ((( kk * 2 + 1) ^ (m  & 7)) << 2) + qid];
                af[mi][3] = Asb[m8 * 32 + ((( kk * 2 + 1) ^ (m8 & 7)) << 2) + qid];
            }
#pragma unroll
            for (int ni = 0; ni < 8; ni++) {
                int n = wn + ni * 8 + grp;
                bf[ni][0] = Bsb[n * 32 + ((( kk * 2    ) ^ (n & 7)) << 2) + qid];
                bf[ni][1] = Bsb[n * 32 + ((( kk * 2 + 1) ^ (n & 7)) << 2) + qid];
            }
#pragma unroll
            for (int mi = 0; mi < 4; mi++)
#pragma unroll
                for (int ni = 0; ni < 8; ni++)
                    mma_tf32(acc[mi][ni][0], acc[mi][ni][1], acc[mi][ni][2], acc[mi][ni][3],
                             af[mi][0], af[mi][1], af[mi][2], af[mi][3],
                             bf[ni][0], bf[ni][1]);
        }
        __syncthreads();
    }

#pragma unroll
    for (int mi = 0; mi < 4; mi++) {
        long r0 = m0 + wm + mi * 16 + grp;
        long r1 = r0 + 8;
#pragma unroll
        for (int ni = 0; ni < 8; ni++) {
            long col = n0 + wn + ni * 8 + qid * 2;
            float bv0 = 0.f, bv1 = 0.f;
            if (bias) { bv0 = bias[col]; bv1 = bias[col + 1]; }
            float v00 = (acc[mi][ni][0] + bv0) * alpha;
            float v01 = (acc[mi][ni][1] + bv1) * alpha;
            float v10 = (acc[mi][ni][2] + bv0) * alpha;
            float v11 = (acc[mi][ni][3] + bv1) * alpha;
            if (ACT == 1) { v00 = tanhf(v00); v01 = tanhf(v01); v10 = tanhf(v10); v11 = tanhf(v11); }
            *(float2*)(C + r0 * ldc + col) = make_float2(v00, v01);
            *(float2*)(C + r1 * ldc + col) = make_float2(v10, v11);
            if (ACT == 1 && Cb) {
                *(__nv_bfloat162*)(Cb + r0 * ldc + col) = __floats2bfloat162_rn(v00, v01);
                *(__nv_bfloat162*)(Cb + r1 * ldc + col) = __floats2bfloat162_rn(v10, v11);
            }
        }
    }
}

// ---------------------------------------------------------------------------
// bf16 NT GEMM + fused exp-rowsum: 128x128 block, 4 warps, warp 64x64, BK=64.
// 3-stage cp.async pipeline (96KB SMEM, 2 CTAs/SM). Fragments via ldmatrix.x4:
// per k16-step, 8 LDSM replace 32 LDS.32 (same bytes, 1/4 the issue slots).
// ---------------------------------------------------------------------------
__global__ __launch_bounds__(128, 2)
void mma_bf16_nt_kernel(const __nv_bfloat16* __restrict__ A,
                        const __nv_bfloat16* __restrict__ Bm,
                        const float* __restrict__ bias, float* __restrict__ C,
                        float* __restrict__ rowsum,
                        int K, int lda, int ldb, int ldc)
{
    extern __shared__ unsigned sh[];

    const int t    = threadIdx.x;
    const int lane = t & 31;
    const int warp = t >> 5;
    const int wm   = (warp >> 1) * 64;
    const int wn   = (warp & 1) * 64;
    const int grp  = lane >> 2;
    const int qid  = lane & 3;

    const long m0 = (long)blockIdx.y * 128;
    const long n0 = (long)blockIdx.x * 128;

    float acc[4][8][4];
#pragma unroll
    for (int mi = 0; mi < 4; mi++)
#pragma unroll
        for (int ni = 0; ni < 8; ni++)
#pragma unroll
            for (int c = 0; c < 4; c++) acc[mi][ni][c] = 0.f;

    // cp.async mapping: tile = 128 rows x 64 bf16 = 16KB; 1024 chunks, 8/thread
    const int row0 = t >> 3;
    const int c8   = t & 7;
    const __nv_bfloat16* aptr0 = A  + (m0 + row0) * lda + c8 * 8;
    const __nv_bfloat16* bptr0 = Bm + (n0 + row0) * ldb + c8 * 8;
    const unsigned soff0 = (unsigned)(row0 * 128 + ((c8 ^ (row0 & 7)) << 4));
    const unsigned sbase = (unsigned)__cvta_generic_to_shared(sh);

    // ldmatrix per-lane precomputed offsets
    // A: lanes 0-15 -> rows (lane&15), k-chunk sel = lane>>4
    const int a_lr = lane & 15;
    const int a_cs = lane >> 4;               // 0/1
    unsigned a_off[4]; int a_m7[4];
#pragma unroll
    for (int mi = 0; mi < 4; mi++) {
        int m = wm + mi * 16 + a_lr;
        a_off[mi] = (unsigned)(m * 128);
        a_m7[mi]  = m & 7;
    }
    // B: group g = lane>>3: tile order {b0(ni), b1(ni), b0(ni+1), b1(ni+1)}
    const int b_g  = lane >> 3;
    const int b_cs = b_g & 1;                 // k-chunk sel
    unsigned b_off[4]; int b_n7[4];
#pragma unroll
    for (int p = 0; p < 4; p++) {
        int n = wn + p * 16 + ((b_g & 2) << 2) + (lane & 7);
        b_off[p] = (unsigned)(n * 128);
        b_n7[p]  = n & 7;
    }

    // stage s: A at s*32768, B at s*32768 + 16384
    auto issue = [&](int stage, int koff) {
        unsigned ab = sbase + (unsigned)stage * 32768u + soff0;
        unsigned bb = ab + 16384u;
#pragma unroll
        for (int i = 0; i < 8; i++) {
            cp16(ab + i * 2048u, aptr0 + (long)i * 16 * lda + koff);
            cp16(bb + i * 2048u, bptr0 + (long)i * 16 * ldb + koff);
        }
        asm volatile("cp.async.commit_group;\n" ::: "memory");
    };

    const int nIter = K >> 6;                 // BK=64 (8 for K=512)
    issue(0, 0);
    if (nIter > 1) issue(1, 64);
    if (nIter > 2) issue(2, 128);

    for (int it = 0; it < nIter; ++it) {
        int rem = nIter - 1 - it;
        if (rem >= 2)      asm volatile("cp.async.wait_group 2;\n" ::: "memory");
        else if (rem == 1) asm volatile("cp.async.wait_group 1;\n" ::: "memory");
        else               asm volatile("cp.async.wait_group 0;\n" ::: "memory");
        __syncthreads();

        int s = it % 3;
        unsigned abase = sbase + (unsigned)s * 32768u;
        unsigned bbase = abase + 16384u;
#pragma unroll
        for (int kk = 0; kk < 4; kk++) {      // 16 k per step
            unsigned af[4][4], bf[8][2];
            int ca = kk * 2 + a_cs;
            int cb = kk * 2 + b_cs;
#pragma unroll
            for (int mi = 0; mi < 4; mi++) {
                unsigned addr = abase + a_off[mi] + (unsigned)((ca ^ a_m7[mi]) << 4);
                ldsm_x4(af[mi][0], af[mi][1], af[mi][2], af[mi][3], addr);
            }
#pragma unroll
            for (int p = 0; p < 4; p++) {
                unsigned addr = bbase + b_off[p] + (unsigned)((cb ^ b_n7[p]) << 4);
                ldsm_x4(bf[2*p][0], bf[2*p][1], bf[2*p+1][0], bf[2*p+1][1], addr);
            }
#pragma unroll
            for (int mi = 0; mi < 4; mi++)
#pragma unroll
                for (int ni = 0; ni < 8; ni++)
                    mma_bf16(acc[mi][ni][0], acc[mi][ni][1], acc[mi][ni][2], acc[mi][ni][3],
                             af[mi][0], af[mi][1], af[mi][2], af[mi][3],
                             bf[ni][0], bf[ni][1]);
        }
        __syncthreads();                      // all warps done reading stage s
        if (it + 3 < nIter) issue(s, (it + 3) * 64);
    }

    // epilogue: write logits + per-row sum of exp
#pragma unroll
    for (int mi = 0; mi < 4; mi++) {
        long r0 = m0 + wm + mi * 16 + grp;
        long r1 = r0 + 8;
        float e0 = 0.f, e1 = 0.f;
#pragma unroll
        for (int ni = 0; ni < 8; ni++) {
            long col = n0 + wn + ni * 8 + qid * 2;
            float bv0 = bias[col], bv1 = bias[col + 1];
            float v00 = acc[mi][ni][0] + bv0;
            float v01 = acc[mi][ni][1] + bv1;
            float v10 = acc[mi][ni][2] + bv0;
            float v11 = acc[mi][ni][3] + bv1;
            *(float2*)(C + r0 * ldc + col) = make_float2(v00, v01);
            *(float2*)(C + r1 * ldc + col) = make_float2(v10, v11);
            e0 += fexp(v00) + fexp(v01);
            e1 += fexp(v10) + fexp(v11);
        }
        e0 += __shfl_xor_sync(0xFFFFFFFFu, e0, 1);
        e0 += __shfl_xor_sync(0xFFFFFFFFu, e0, 2);
        e1 += __shfl_xor_sync(0xFFFFFFFFu, e1, 1);
        e1 += __shfl_xor_sync(0xFFFFFFFFu, e1, 2);
        if (qid == 0) {
            atomicAdd(rowsum + r0, e0);
            atomicAdd(rowsum + r1, e1);
        }
    }
}

// ---------------------------------------------------------------------------
// fp32 -> bf16 convert
// ---------------------------------------------------------------------------
__global__ __launch_bounds__(256)
void f2b_kernel(const float4* __restrict__ in, __nv_bfloat162* __restrict__ out, int n4)
{
    int i = blockIdx.x * 256 + threadIdx.x;
    if (i >= n4) return;
    float4 v = in[i];
    out[i * 2]     = __floats2bfloat162_rn(v.x, v.y);
    out[i * 2 + 1] = __floats2bfloat162_rn(v.z, v.w);
}

__global__ void zero_kernel(float* __restrict__ p)
{
    p[blockIdx.x * 256 + threadIdx.x] = 0.f;
}

__global__ void coef_kernel(const float* __restrict__ rowsum,
                            const float* __restrict__ gates, float* __restrict__ coef)
{
    int r = blockIdx.x * 256 + threadIdx.x;
    coef[r] = __logf(gates[r * 2 + 0]) - __logf(rowsum[r]);
}

// ---------------------------------------------------------------------------
// v transpose: vt[b][d][t] = v[(t*B+b)*D + d].
// ---------------------------------------------------------------------------
__global__ __launch_bounds__(256)
void vt_kernel(const float* __restrict__ v, float* __restrict__ vt)
{
    __shared__ float tile[32][33];
    int b  = blockIdx.z;
    int t0 = blockIdx.x * 32;
    int d0 = blockIdx.y * 32;
    int x  = threadIdx.x & 31;
    int y  = threadIdx.x >> 5;
#pragma unroll
    for (int j = 0; j < 32; j += 8)
        tile[y + j][x] = v[((long)(t0 + y + j) * B_ + b) * D_ + d0 + x];
    __syncthreads();
#pragma unroll
    for (int j = 0; j < 32; j += 8)
        vt[(long)b * D_ * T_ + (long)(d0 + y + j) * T_ + t0 + x] = tile[x][y + j];
}

// ---------------------------------------------------------------------------
// Softmax over T (in-place). mask: [B,T] bytes.
// ---------------------------------------------------------------------------
__global__ __launch_bounds__(256)
void attn_softmax_kernel(float* __restrict__ attn, const unsigned char* __restrict__ mask)
{
    int row = blockIdx.x;
    int b   = row & (B_ - 1);
    float* p = attn + (long)row * T_;
    const unsigned char* mrow = mask + (long)b * T_;
    int t = threadIdx.x;
    __shared__ float red[256];

    float x[4];
    float mx = -1e30f;
#pragma unroll
    for (int i = 0; i < 4; i++) {
        int tt = t + i * 256;
        float v = p[tt];
        if (mrow[tt]) v = -1e9f;
        x[i] = v;
        mx = fmaxf(mx, v);
    }
    red[t] = mx; __syncthreads();
    for (int s = 128; s > 0; s >>= 1) {
        if (t < s) red[t] = fmaxf(red[t], red[t + s]);
        __syncthreads();
    }
    mx = red[0]; __syncthreads();

    float sum = 0.f;
#pragma unroll
    for (int i = 0; i < 4; i++) { x[i] = fexp(x[i] - mx); sum += x[i]; }
    red[t] = sum; __syncthreads();
    for (int s = 128; s > 0; s >>= 1) {
        if (t < s) red[t] += red[t + s];
        __syncthreads();
    }
    float inv = 1.f / red[0];
#pragma unroll
    for (int i = 0; i < 4; i++) p[t + i * 256] = x[i] * inv;
}

// ---------------------------------------------------------------------------
// LayerNorm(outs + x).
// ---------------------------------------------------------------------------
__global__ __launch_bounds__(256)
void ln_kernel(const float* __restrict__ outs, const float* __restrict__ x,
               const float* __restrict__ g, const float* __restrict__ bb,
               float* __restrict__ out)
{
    int row = blockIdx.x;
    int t = threadIdx.x;
    const float* o  = outs + (long)row * D_;
    const float* xr = x    + (long)row * D_;
    __shared__ float red[256];

    float v0 = o[t] + xr[t];
    float v1 = o[t + 256] + xr[t + 256];

    red[t] = v0 + v1; __syncthreads();
    for (int s = 128; s > 0; s >>= 1) { if (t < s) red[t] += red[t + s]; __syncthreads(); }
    float mu = red[0] * (1.f / D_); __syncthreads();

    float d0 = v0 - mu, d1 = v1 - mu;
    red[t] = d0 * d0 + d1 * d1; __syncthreads();
    for (int s = 128; s > 0; s >>= 1) { if (t < s) red[t] += red[t + s]; __syncthreads(); }
    float inv = rsqrtf(red[0] * (1.f / D_) + 1e-5f);

    out[(long)row * D_ + t]       = d0 * inv * g[t]       + bb[t];
    out[(long)row * D_ + t + 256] = d1 * inv * g[t + 256] + bb[t + 256];
}

// ---------------------------------------------------------------------------
// 2-way gate
// ---------------------------------------------------------------------------
__global__ __launch_bounds__(128)
void gates_kernel(const float* __restrict__ tok, const float* __restrict__ Wdiv,
                  const float* __restrict__ bdiv, float* __restrict__ gates)
{
    int row = blockIdx.x;
    int t = threadIdx.x;
    const float* x = tok + (long)row * D_;
    float z0 = 0.f, z1 = 0.f;
    for (int d = t; d < D_; d += 128) {
        float xv = x[d];
        z0 = fmaf(xv, Wdiv[d],      z0);
        z1 = fmaf(xv, Wdiv[D_ + d], z1);
    }
    __shared__ float r0[128], r1[128];
    r0[t] = z0; r1[t] = z1; __syncthreads();
    for (int s = 64; s > 0; s >>= 1) {
        if (t < s) { r0[t] += r0[t + s]; r1[t] += r1[t + s]; }
        __syncthreads();
    }
    if (t == 0) {
        float a = r0[0] + bdiv[0], b = r1[0] + bdiv[1];
        float m = fmaxf(a, b);
        float e0 = __expf(a - m), e1 = __expf(b - m);
        float inv = 1.f / (e0 + e1);
        gates[row * 2 + 0] = e0 * inv;
        gates[row * 2 + 1] = e1 * inv;
    }
}

// ---------------------------------------------------------------------------
// Log-prob base pass: out = coef[row] + z.
// ---------------------------------------------------------------------------
__global__ __launch_bounds__(256)
void lp_kernel(float* __restrict__ out, const float* __restrict__ coef)
{
    long i4 = (long)blockIdx.x * 256 + threadIdx.x;
    int row = (int)(i4 / (V_ / 4));
    float c = __ldg(coef + row);
    float4* p = (float4*)out + i4;
    float4 v = *p;
    v.x += c; v.y += c; v.z += c; v.w += c;
    *p = v;
}

// ---------------------------------------------------------------------------
// Copy-scatter in log space via CAS.
// ---------------------------------------------------------------------------
__global__ __launch_bounds__(256)
void scatter_kernel(float* __restrict__ out, const float* __restrict__ attn,
                    const float* __restrict__ gates, const int* __restrict__ copy_seq)
{
    int gid = blockIdx.x * 256 + threadIdx.x;
    int row = gid >> 10;
    int t   = gid & 1023;
    int b   = row & (B_ - 1);
    float val = gates[row * 2 + 1] * attn[(long)row * T_ + t];
    int idx = copy_seq[t * B_ + b];
    int* ia = (int*)(out + (long)row * V_ + idx);

    int assumed = *ia;
    int old;
    do {
        old = assumed;
        float cur = __int_as_float(old);
        float nv = __logf(__expf(cur) + val);
        assumed = atomicCAS(ia, old, __float_as_int(nv));
    } while (assumed != old);
}

// ---------------------------------------------------------------------------
// Launch
// ---------------------------------------------------------------------------
extern "C" void kernel_launch(void* const* d_in, const int* in_sizes, int n_in,
                              void* d_out, int out_size)
{
    const float* outs = (const float*)d_in[0];
    const float* gs   = (const float*)d_in[1];
    const unsigned char* mask = (const unsigned char*)d_in[2];
    const int*   cseq = (const int*)d_in[3];
    const float* Wq = (const float*)d_in[4],  *bq = (const float*)d_in[5];
    const float* Wk = (const float*)d_in[6],  *bk = (const float*)d_in[7];
    const float* Wv = (const float*)d_in[8],  *bv = (const float*)d_in[9];
    const float* Wo = (const float*)d_in[10], *bo = (const float*)d_in[11];
    const float* lng = (const float*)d_in[12], *lnb = (const float*)d_in[13];
    const float* Wt = (const float*)d_in[14], *bt = (const float*)d_in[15];
    const float* Wgen = (const float*)d_in[16], *bgen = (const float*)d_in[17];
    const float* Wdiv = (const float*)d_in[18], *bdiv = (const float*)d_in[19];
    float* out = (float*)d_out;

    float* sc = nullptr;
    cudaGetSymbolAddress((void**)&sc, g_scratch);
    float* q     = sc + OQ;
    float* k     = sc + OK_;
    float* v     = sc + OV;
    float* vt    = sc + OVT;
    float* attn  = sc + OA;
    float* ctx   = sc + OC;
    float* ln    = sc + OL;
    float* tok   = sc + OT;
    float* gts   = sc + OG;
    float* coef  = sc + OM;
    float* rowsum = sc + ORS;
    __nv_bfloat16* wgen_b = (__nv_bfloat16*)(sc + OWB);
    __nv_bfloat16* tok_b  = (__nv_bfloat16*)(sc + OTB);

    const float scale = 0.044194173824159216f; // 1/sqrt(512)
    constexpr int SMEM  = 65536;
    constexpr int SMEM3 = 98304;
    cudaFuncSetAttribute(mma_nt_kernel<0>, cudaFuncAttributeMaxDynamicSharedMemorySize, SMEM);
    cudaFuncSetAttribute(mma_nt_kernel<1>, cudaFuncAttributeMaxDynamicSharedMemorySize, SMEM);
    cudaFuncSetAttribute(mma_bf16_nt_kernel, cudaFuncAttributeMaxDynamicSharedMemorySize, SMEM3);
    dim3 blk(256);
    dim3 blkG(128);

    // early: Wgen -> bf16, rowsum = 0
    f2b_kernel<<<(V_ * TS_ / 4 + 255) / 256, blk>>>((const float4*)Wgen, (__nv_bfloat162*)wgen_b, V_ * TS_ / 4);
    zero_kernel<<<SB / 256, blk>>>(rowsum);

    // q = (outs @ Wq^T + bq) * scale       [2048 x 512]
    mma_nt_kernel<0><<<dim3(4, 16, 1), blkG, SMEM>>>(outs, Wq, bq, q, nullptr, D_, D_, D_, D_, 0, 0, 0, scale);
    // k = gs @ Wk^T + bk                   [8192 x 512]
    mma_nt_kernel<0><<<dim3(4, 64, 1), blkG, SMEM>>>(gs, Wk, bk, k, nullptr, D_, D_, D_, D_, 0, 0, 0, 1.f);
    // v = gs @ Wv^T + bv
    mma_nt_kernel<0><<<dim3(4, 64, 1), blkG, SMEM>>>(gs, Wv, bv, v, nullptr, D_, D_, D_, D_, 0, 0, 0, 1.f);
    // v transpose for ctx GEMM
    vt_kernel<<<dim3(32, 16, 8), blk>>>(v, vt);
    // scores[s,b,t] = q[s,b,:] . k[t,b,:]  (batched over b)
    mma_nt_kernel<0><<<dim3(8, 2, 8), blkG, SMEM>>>(q, k, nullptr, attn, nullptr,
                                                    D_, B_ * D_, B_ * D_, B_ * T_,
                                                    D_, D_, T_, 1.f);
    // softmax over t (with mask)
    attn_softmax_kernel<<<SB, 256>>>(attn, mask);
    // ctx[s,b,:] = attn[s,b,:] @ v[:,b,:]   (NT vs v_T, batched over b)
    mma_nt_kernel<0><<<dim3(4, 2, 8), blkG, SMEM>>>(attn, vt, nullptr, ctx, nullptr,
                                                    T_, B_ * T_, T_, B_ * D_,
                                                    T_, (long)D_ * T_, D_, 1.f);
    // x = ctx @ Wo^T + bo   -> reuse q buffer
    mma_nt_kernel<0><<<dim3(4, 16, 1), blkG, SMEM>>>(ctx, Wo, bo, q, nullptr, D_, D_, D_, D_, 0, 0, 0, 1.f);
    // outs_ln = LN(outs + x)
    ln_kernel<<<SB, 256>>>(outs, q, lng, lnb, ln);
    // tok = tanh(outs_ln @ Wt^T + bt); also emits tok_b (bf16) fused
    mma_nt_kernel<1><<<dim3(4, 16, 1), blkG, SMEM>>>(ln, Wt, bt, tok, tok_b, D_, D_, D_, TS_, 0, 0, 0, 1.f);
    // gates
    gates_kernel<<<SB, 128>>>(tok, Wdiv, bdiv, gts);
    // logits = tok @ Wgen^T + bgen -> d_out; fused rowsum of exp(logits)
    mma_bf16_nt_kernel<<<dim3(250, 16, 1), blkG, SMEM3>>>(tok_b, wgen_b, bgen, out, rowsum,
                                                          TS_, TS_, TS_, V_);
    // coef = log(gen) - log(rowsum)
    coef_kernel<<<SB / 256, blk>>>(rowsum, gts, coef);
    // base log-probs in place
    lp_kernel<<<(SB * (V_ / 4)) / 256, 256>>>(out, coef);
    // copy scatter (log-space CAS merge)
    scatter_kernel<<<(SB * T_) / 256, 256>>>(out, attn, gts, cseq);
}

// round 11
// speedup vs baseline: 1.0881x; 1.0066x over previous
#include <cuda_runtime.h>
#include <cuda_bf16.h>
#include <math.h>
#include <stdint.h>

// Problem dims (fixed for this dataset)
constexpr int S_  = 256;
constexpr int B_  = 8;
constexpr int T_  = 1024;
constexpr int D_  = 512;
constexpr int TS_ = 512;
constexpr int V_  = 32000;
constexpr int SB  = S_ * B_;   // 2048
constexpr int TB  = T_ * B_;   // 8192

// ---------------------------------------------------------------------------
// Scratch arena
// ---------------------------------------------------------------------------
constexpr size_t OQ  = 0;                        // q / later x      : SB*D
constexpr size_t OK_ = OQ  + (size_t)SB * D_;    // k                : TB*D
constexpr size_t OV  = OK_ + (size_t)TB * D_;    // v                : TB*D
constexpr size_t OVT = OV  + (size_t)TB * D_;    // v transposed     : TB*D
constexpr size_t OA  = OVT + (size_t)TB * D_;    // attn (scores)    : SB*T
constexpr size_t OC  = OA  + (size_t)SB * T_;    // ctx              : SB*D
constexpr size_t OL  = OC  + (size_t)SB * D_;    // layernorm out    : SB*D
constexpr size_t OT  = OL  + (size_t)SB * D_;    // outs_token (f32) : SB*D
constexpr size_t OG  = OT  + (size_t)SB * D_;    // gates            : SB*2
constexpr size_t ORS = OG  + (size_t)SB * 2;     // rowsum exp       : SB
constexpr size_t OWB = ORS + SB;                 // Wgen bf16        : V*TS/2 floats
constexpr size_t OTB = OWB + (size_t)V_ * TS_ / 2;  // tok bf16      : SB*TS/2
constexpr size_t SCRATCH_FLOATS = OTB + (size_t)SB * TS_ / 2;

__device__ float g_scratch[SCRATCH_FLOATS];

// ---------------------------------------------------------------------------
// math helpers
// ---------------------------------------------------------------------------
__device__ __forceinline__ float fexp(float x) {
    float t = fmaxf(fminf(x * 1.4426950408889634f, 126.f), -126.f);
    float mg = t + 12582912.f;
    int   n  = __float_as_int(mg) - 0x4B400000;
    float f  = t - (mg - 12582912.f);
    float p  = 1.54035304e-4f;
    p = fmaf(p, f, 1.33335581e-3f);
    p = fmaf(p, f, 9.61812911e-3f);
    p = fmaf(p, f, 5.55041087e-2f);
    p = fmaf(p, f, 2.40226507e-1f);
    p = fmaf(p, f, 6.93147182e-1f);
    p = fmaf(p, f, 1.0f);
    return __int_as_float(__float_as_int(p) + (n << 23));
}

__device__ __forceinline__ void mma_tf32(float& c0, float& c1, float& c2, float& c3,
                                         unsigned a0, unsigned a1, unsigned a2, unsigned a3,
                                         unsigned b0, unsigned b1)
{
    asm volatile(
        "mma.sync.aligned.m16n8k8.row.col.f32.tf32.tf32.f32 "
        "{%0,%1,%2,%3}, {%4,%5,%6,%7}, {%8,%9}, {%0,%1,%2,%3};"
        : "+f"(c0), "+f"(c1), "+f"(c2), "+f"(c3)
        : "r"(a0), "r"(a1), "r"(a2), "r"(a3), "r"(b0), "r"(b1));
}

__device__ __forceinline__ void mma_bf16(float& c0, float& c1, float& c2, float& c3,
                                         unsigned a0, unsigned a1, unsigned a2, unsigned a3,
                                         unsigned b0, unsigned b1)
{
    asm volatile(
        "mma.sync.aligned.m16n8k16.row.col.f32.bf16.bf16.f32 "
        "{%0,%1,%2,%3}, {%4,%5,%6,%7}, {%8,%9}, {%0,%1,%2,%3};"
        : "+f"(c0), "+f"(c1), "+f"(c2), "+f"(c3)
        : "r"(a0), "r"(a1), "r"(a2), "r"(a3), "r"(b0), "r"(b1));
}

__device__ __forceinline__ void ldsm_x4(unsigned& r0, unsigned& r1, unsigned& r2, unsigned& r3,
                                        unsigned addr)
{
    asm volatile("ldmatrix.sync.aligned.m8n8.x4.shared.b16 {%0,%1,%2,%3}, [%4];"
                 : "=r"(r0), "=r"(r1), "=r"(r2), "=r"(r3) : "r"(addr));
}

__device__ __forceinline__ void cp16(unsigned dst, const void* src) {
    asm volatile("cp.async.cg.shared.global [%0], [%1], 16;\n" :: "r"(dst), "l"(src));
}

// ---------------------------------------------------------------------------
// Tensor-core NT GEMM (tf32): C[m,n] = ACT(alpha*(sum A[m,k]*B[n,k] + bias[n]))
// 128x128 block, 4 warps, warp tile 64x64, BK=32, 64KB SMEM, 2 CTAs/SM.
// If ACT==1 and Cb != nullptr, also writes bf16 copy of C into Cb.
// ---------------------------------------------------------------------------
template <int ACT>
__global__ __launch_bounds__(128, 2)
void mma_nt_kernel(const float* __restrict__ A, const float* __restrict__ Bm,
                   const float* __restrict__ bias, float* __restrict__ C,
                   __nv_bfloat16* __restrict__ Cb,
                   int K, int lda, int ldb, int ldc,
                   long sA, long sB, long sC, float alpha)
{
    extern __shared__ unsigned sh[];

    A  += (long)blockIdx.z * sA;
    Bm += (long)blockIdx.z * sB;
    C  += (long)blockIdx.z * sC;

    const int t    = threadIdx.x;
    const int lane = t & 31;
    const int warp = t >> 5;
    const int wm   = (warp >> 1) * 64;
    const int wn   = (warp & 1) * 64;
    const int grp  = lane >> 2;
    const int qid  = lane & 3;

    const long m0 = (long)blockIdx.y * 128;
    const long n0 = (long)blockIdx.x * 128;

    float acc[4][8][4];
#pragma unroll
    for (int mi = 0; mi < 4; mi++)
#pragma unroll
        for (int ni = 0; ni < 8; ni++)
#pragma unroll
            for (int c = 0; c < 4; c++) acc[mi][ni][c] = 0.f;

    const int row0 = t >> 3;
    const int c4   = t & 7;
    const float* aptr0 = A  + (m0 + row0) * lda + c4 * 4;
    const float* bptr0 = Bm + (n0 + row0) * ldb + c4 * 4;
    const unsigned soff0 = (unsigned)(row0 * 32 + ((c4 ^ (row0 & 7)) << 2)) * 4u;
    const unsigned sbase = (unsigned)__cvta_generic_to_shared(sh);

    auto issue = [&](int stage, int koff) {
        unsigned ab = sbase + (unsigned)stage * 16384u + soff0;
        unsigned bb = sbase + 32768u + (unsigned)stage * 16384u + soff0;
#pragma unroll
        for (int i = 0; i < 8; i++) {
            cp16(ab + i * 2048u, aptr0 + (long)i * 16 * lda + koff);
            cp16(bb + i * 2048u, bptr0 + (long)i * 16 * ldb + koff);
        }
        asm volatile("cp.async.commit_group;\n" ::: "memory");
    };

    issue(0, 0);
    const int nIter = K >> 5;
    for (int it = 0; it < nIter; ++it) {
        asm volatile("cp.async.wait_group 0;\n" ::: "memory");
        __syncthreads();
        if (it + 1 < nIter) issue((it + 1) & 1, (it + 1) * 32);

        const unsigned* Asb = sh + (it & 1) * 4096;
        const unsigned* Bsb = sh + 8192 + (it & 1) * 4096;
#pragma unroll
        for (int kk = 0; kk < 4; kk++) {
            unsigned af[4][4], bf[8][2];
#pragma unroll
            for (int mi = 0; mi < 4; mi++) {
                int m  = wm + mi * 16 + grp;
                int m8 = m + 8;
                af[mi][0] = Asb[m  * 32 + ((( kk * 2    ) ^ (m  & 7)) << 2) + qid];
                af[mi][1] = Asb[m8 * 32 + ((( kk * 2    ) ^ (m8 & 7)) << 2) + qid];
                af[mi][2] = Asb[m  * 32 + ((( kk * 2 + 1) ^ (m  & 7)) << 2) + qid];
                af[mi][3] = Asb[m8 * 32 + ((( kk * 2 + 1) ^ (m8 & 7)) << 2) + qid];
            }
#pragma unroll
            for (int ni = 0; ni < 8; ni++) {
                int n = wn + ni * 8 + grp;
                bf[ni][0] = Bsb[n * 32 + ((( kk * 2    ) ^ (n & 7)) << 2) + qid];
                bf[ni][1] = Bsb[n * 32 + ((( kk * 2 + 1) ^ (n & 7)) << 2) + qid];
            }
#pragma unroll
            for (int mi = 0; mi < 4; mi++)
#pragma unroll
                for (int ni = 0; ni < 8; ni++)
                    mma_tf32(acc[mi][ni][0], acc[mi][ni][1], acc[mi][ni][2], acc[mi][ni][3],
                             af[mi][0], af[mi][1], af[mi][2], af[mi][3],
                             bf[ni][0], bf[ni][1]);
        }
        __syncthreads();
    }

#pragma unroll
    for (int mi = 0; mi < 4; mi++) {
        long r0 = m0 + wm + mi * 16 + grp;
        long r1 = r0 + 8;
#pragma unroll
        for (int ni = 0; ni < 8; ni++) {
            long col = n0 + wn + ni * 8 + qid * 2;
            float bv0 = 0.f, bv1 = 0.f;
            if (bias) { bv0 = bias[col]; bv1 = bias[col + 1]; }
            float v00 = (acc[mi][ni][0] + bv0) * alpha;
            float v01 = (acc[mi][ni][1] + bv1) * alpha;
            float v10 = (acc[mi][ni][2] + bv0) * alpha;
            float v11 = (acc[mi][ni][3] + bv1) * alpha;
            if (ACT == 1) { v00 = tanhf(v00); v01 = tanhf(v01); v10 = tanhf(v10); v11 = tanhf(v11); }
            *(float2*)(C + r0 * ldc + col) = make_float2(v00, v01);
            *(float2*)(C + r1 * ldc + col) = make_float2(v10, v11);
            if (ACT == 1 && Cb) {
                *(__nv_bfloat162*)(Cb + r0 * ldc + col) = __floats2bfloat162_rn(v00, v01);
                *(__nv_bfloat162*)(Cb + r1 * ldc + col) = __floats2bfloat162_rn(v10, v11);
            }
        }
    }
}

// ---------------------------------------------------------------------------
// bf16 NT GEMM + fused exp-rowsum: 128x128 block, 4 warps, warp 64x64, BK=64.
// 3-stage cp.async pipeline (96KB SMEM, 2 CTAs/SM). ldmatrix.x4 fragments.
// ---------------------------------------------------------------------------
__global__ __launch_bounds__(128, 2)
void mma_bf16_nt_kernel(const __nv_bfloat16* __restrict__ A,
                        const __nv_bfloat16* __restrict__ Bm,
                        const float* __restrict__ bias, float* __restrict__ C,
                        float* __restrict__ rowsum,
                        int K, int lda, int ldb, int ldc)
{
    extern __shared__ unsigned sh[];

    const int t    = threadIdx.x;
    const int lane = t & 31;
    const int warp = t >> 5;
    const int wm   = (warp >> 1) * 64;
    const int wn   = (warp & 1) * 64;
    const int grp  = lane >> 2;
    const int qid  = lane & 3;

    const long m0 = (long)blockIdx.y * 128;
    const long n0 = (long)blockIdx.x * 128;

    float acc[4][8][4];
#pragma unroll
    for (int mi = 0; mi < 4; mi++)
#pragma unroll
        for (int ni = 0; ni < 8; ni++)
#pragma unroll
            for (int c = 0; c < 4; c++) acc[mi][ni][c] = 0.f;

    const int row0 = t >> 3;
    const int c8   = t & 7;
    const __nv_bfloat16* aptr0 = A  + (m0 + row0) * lda + c8 * 8;
    const __nv_bfloat16* bptr0 = Bm + (n0 + row0) * ldb + c8 * 8;
    const unsigned soff0 = (unsigned)(row0 * 128 + ((c8 ^ (row0 & 7)) << 4));
    const unsigned sbase = (unsigned)__cvta_generic_to_shared(sh);

    const int a_lr = lane & 15;
    const int a_cs = lane >> 4;
    unsigned a_off[4]; int a_m7[4];
#pragma unroll
    for (int mi = 0; mi < 4; mi++) {
        int m = wm + mi * 16 + a_lr;
        a_off[mi] = (unsigned)(m * 128);
        a_m7[mi]  = m & 7;
    }
    const int b_g  = lane >> 3;
    const int b_cs = b_g & 1;
    unsigned b_off[4]; int b_n7[4];
#pragma unroll
    for (int p = 0; p < 4; p++) {
        int n = wn + p * 16 + ((b_g & 2) << 2) + (lane & 7);
        b_off[p] = (unsigned)(n * 128);
        b_n7[p]  = n & 7;
    }

    auto issue = [&](int stage, int koff) {
        unsigned ab = sbase + (unsigned)stage * 32768u + soff0;
        unsigned bb = ab + 16384u;
#pragma unroll
        for (int i = 0; i < 8; i++) {
            cp16(ab + i * 2048u, aptr0 + (long)i * 16 * lda + koff);
            cp16(bb + i * 2048u, bptr0 + (long)i * 16 * ldb + koff);
        }
        asm volatile("cp.async.commit_group;\n" ::: "memory");
    };

    const int nIter = K >> 6;
    issue(0, 0);
    if (nIter > 1) issue(1, 64);
    if (nIter > 2) issue(2, 128);

    for (int it = 0; it < nIter; ++it) {
        int rem = nIter - 1 - it;
        if (rem >= 2)      asm volatile("cp.async.wait_group 2;\n" ::: "memory");
        else if (rem == 1) asm volatile("cp.async.wait_group 1;\n" ::: "memory");
        else               asm volatile("cp.async.wait_group 0;\n" ::: "memory");
        __syncthreads();

        int s = it % 3;
        unsigned abase = sbase + (unsigned)s * 32768u;
        unsigned bbase = abase + 16384u;
#pragma unroll
        for (int kk = 0; kk < 4; kk++) {
            unsigned af[4][4], bf[8][2];
            int ca = kk * 2 + a_cs;
            int cb = kk * 2 + b_cs;
#pragma unroll
            for (int mi = 0; mi < 4; mi++) {
                unsigned addr = abase + a_off[mi] + (unsigned)((ca ^ a_m7[mi]) << 4);
                ldsm_x4(af[mi][0], af[mi][1], af[mi][2], af[mi][3], addr);
            }
#pragma unroll
            for (int p = 0; p < 4; p++) {
                unsigned addr = bbase + b_off[p] + (unsigned)((cb ^ b_n7[p]) << 4);
                ldsm_x4(bf[2*p][0], bf[2*p][1], bf[2*p+1][0], bf[2*p+1][1], addr);
            }
#pragma unroll
            for (int mi = 0; mi < 4; mi++)
#pragma unroll
                for (int ni = 0; ni < 8; ni++)
                    mma_bf16(acc[mi][ni][0], acc[mi][ni][1], acc[mi][ni][2], acc[mi][ni][3],
                             af[mi][0], af[mi][1], af[mi][2], af[mi][3],
                             bf[ni][0], bf[ni][1]);
        }
        __syncthreads();
        if (it + 3 < nIter) issue(s, (it + 3) * 64);
    }

    // epilogue: write logits + per-row sum of exp
#pragma unroll
    for (int mi = 0; mi < 4; mi++) {
        long r0 = m0 + wm + mi * 16 + grp;
        long r1 = r0 + 8;
        float e0 = 0.f, e1 = 0.f;
#pragma unroll
        for (int ni = 0; ni < 8; ni++) {
            long col = n0 + wn + ni * 8 + qid * 2;
            float bv0 = bias[col], bv1 = bias[col + 1];
            float v00 = acc[mi][ni][0] + bv0;
            float v01 = acc[mi][ni][1] + bv1;
            float v10 = acc[mi][ni][2] + bv0;
            float v11 = acc[mi][ni][3] + bv1;
            *(float2*)(C + r0 * ldc + col) = make_float2(v00, v01);
            *(float2*)(C + r1 * ldc + col) = make_float2(v10, v11);
            e0 += fexp(v00) + fexp(v01);
            e1 += fexp(v10) + fexp(v11);
        }
        e0 += __shfl_xor_sync(0xFFFFFFFFu, e0, 1);
        e0 += __shfl_xor_sync(0xFFFFFFFFu, e0, 2);
        e1 += __shfl_xor_sync(0xFFFFFFFFu, e1, 1);
        e1 += __shfl_xor_sync(0xFFFFFFFFu, e1, 2);
        if (qid == 0) {
            atomicAdd(rowsum + r0, e0);
            atomicAdd(rowsum + r1, e1);
        }
    }
}

// ---------------------------------------------------------------------------
// fp32 -> bf16 convert
// ---------------------------------------------------------------------------
__global__ __launch_bounds__(256)
void f2b_kernel(const float4* __restrict__ in, __nv_bfloat162* __restrict__ out, int n4)
{
    int i = blockIdx.x * 256 + threadIdx.x;
    if (i >= n4) return;
    float4 v = in[i];
    out[i * 2]     = __floats2bfloat162_rn(v.x, v.y);
    out[i * 2 + 1] = __floats2bfloat162_rn(v.z, v.w);
}

__global__ void zero_kernel(float* __restrict__ p)
{
    p[blockIdx.x * 256 + threadIdx.x] = 0.f;
}

// ---------------------------------------------------------------------------
// v transpose: vt[b][d][t] = v[(t*B+b)*D + d].
// ---------------------------------------------------------------------------
__global__ __launch_bounds__(256)
void vt_kernel(const float* __restrict__ v, float* __restrict__ vt)
{
    __shared__ float tile[32][33];
    int b  = blockIdx.z;
    int t0 = blockIdx.x * 32;
    int d0 = blockIdx.y * 32;
    int x  = threadIdx.x & 31;
    int y  = threadIdx.x >> 5;
#pragma unroll
    for (int j = 0; j < 32; j += 8)
        tile[y + j][x] = v[((long)(t0 + y + j) * B_ + b) * D_ + d0 + x];
    __syncthreads();
#pragma unroll
    for (int j = 0; j < 32; j += 8)
        vt[(long)b * D_ * T_ + (long)(d0 + y + j) * T_ + t0 + x] = tile[x][y + j];
}

// ---------------------------------------------------------------------------
// Softmax over T (in-place). mask: [B,T] bytes.
// ---------------------------------------------------------------------------
__global__ __launch_bounds__(256)
void attn_softmax_kernel(float* __restrict__ attn, const unsigned char* __restrict__ mask)
{
    int row = blockIdx.x;
    int b   = row & (B_ - 1);
    float* p = attn + (long)row * T_;
    const unsigned char* mrow = mask + (long)b * T_;
    int t = threadIdx.x;
    __shared__ float red[256];

    float x[4];
    float mx = -1e30f;
#pragma unroll
    for (int i = 0; i < 4; i++) {
        int tt = t + i * 256;
        float v = p[tt];
        if (mrow[tt]) v = -1e9f;
        x[i] = v;
        mx = fmaxf(mx, v);
    }
    red[t] = mx; __syncthreads();
    for (int s = 128; s > 0; s >>= 1) {
        if (t < s) red[t] = fmaxf(red[t], red[t + s]);
        __syncthreads();
    }
    mx = red[0]; __syncthreads();

    float sum = 0.f;
#pragma unroll
    for (int i = 0; i < 4; i++) { x[i] = fexp(x[i] - mx); sum += x[i]; }
    red[t] = sum; __syncthreads();
    for (int s = 128; s > 0; s >>= 1) {
        if (t < s) red[t] += red[t + s];
        __syncthreads();
    }
    float inv = 1.f / red[0];
#pragma unroll
    for (int i = 0; i < 4; i++) p[t + i * 256] = x[i] * inv;
}

// ---------------------------------------------------------------------------
// LayerNorm(outs + x).
// ---------------------------------------------------------------------------
__global__ __launch_bounds__(256)
void ln_kernel(const float* __restrict__ outs, const float* __restrict__ x,
               const float* __restrict__ g, const float* __restrict__ bb,
               float* __restrict__ out)
{
    int row = blockIdx.x;
    int t = threadIdx.x;
    const float* o  = outs + (long)row * D_;
    const float* xr = x    + (long)row * D_;
    __shared__ float red[256];

    float v0 = o[t] + xr[t];
    float v1 = o[t + 256] + xr[t + 256];

    red[t] = v0 + v1; __syncthreads();
    for (int s = 128; s > 0; s >>= 1) { if (t < s) red[t] += red[t + s]; __syncthreads(); }
    float mu = red[0] * (1.f / D_); __syncthreads();

    float d0 = v0 - mu, d1 = v1 - mu;
    red[t] = d0 * d0 + d1 * d1; __syncthreads();
    for (int s = 128; s > 0; s >>= 1) { if (t < s) red[t] += red[t + s]; __syncthreads(); }
    float inv = rsqrtf(red[0] * (1.f / D_) + 1e-5f);

    out[(long)row * D_ + t]       = d0 * inv * g[t]       + bb[t];
    out[(long)row * D_ + t + 256] = d1 * inv * g[t + 256] + bb[t + 256];
}

// ---------------------------------------------------------------------------
// 2-way gate
// ---------------------------------------------------------------------------
__global__ __launch_bounds__(128)
void gates_kernel(const float* __restrict__ tok, const float* __restrict__ Wdiv,
                  const float* __restrict__ bdiv, float* __restrict__ gates)
{
    int row = blockIdx.x;
    int t = threadIdx.x;
    const float* x = tok + (long)row * D_;
    float z0 = 0.f, z1 = 0.f;
    for (int d = t; d < D_; d += 128) {
        float xv = x[d];
        z0 = fmaf(xv, Wdiv[d],      z0);
        z1 = fmaf(xv, Wdiv[D_ + d], z1);
    }
    __shared__ float r0[128], r1[128];
    r0[t] = z0; r1[t] = z1; __syncthreads();
    for (int s = 64; s > 0; s >>= 1) {
        if (t < s) { r0[t] += r0[t + s]; r1[t] += r1[t + s]; }
        __syncthreads();
    }
    if (t == 0) {
        float a = r0[0] + bdiv[0], b = r1[0] + bdiv[1];
        float m = fmaxf(a, b);
        float e0 = __expf(a - m), e1 = __expf(b - m);
        float inv = 1.f / (e0 + e1);
        gates[row * 2 + 0] = e0 * inv;
        gates[row * 2 + 1] = e1 * inv;
    }
}

// ---------------------------------------------------------------------------
// Fused coef + log-prob base + copy-scatter. One block (256 thr) per row.
//   coef  = log(gen_gate) - log(rowsum)
//   out[row, :] += coef                       (float4 pass)
//   out[row, idx(t)] = log(exp(.) + copy_val) (CAS, row-local, after sync)
// ---------------------------------------------------------------------------
__global__ __launch_bounds__(256)
void lp_scatter_kernel(float* __restrict__ out, const float* __restrict__ rowsum,
                       const float* __restrict__ gates, const float* __restrict__ attn,
                       const int* __restrict__ copy_seq)
{
    int row = blockIdx.x;
    int t   = threadIdx.x;
    int b   = row & (B_ - 1);

    float coef = __logf(gates[row * 2 + 0]) - __logf(rowsum[row]);
    float gate1 = gates[row * 2 + 1];

    float4* o4 = (float4*)(out + (long)row * V_);
    for (int j = t; j < V_ / 4; j += 256) {
        float4 v = o4[j];
        v.x += coef; v.y += coef; v.z += coef; v.w += coef;
        o4[j] = v;
    }
    __syncthreads();

    const float* arow = attn + (long)row * T_;
    float* orow = out + (long)row * V_;
#pragma unroll
    for (int e = 0; e < 4; e++) {
        int tt = t + e * 256;
        float val = gate1 * arow[tt];
        int idx = copy_seq[tt * B_ + b];
        int* ia = (int*)(orow + idx);
        int assumed = *ia;
        int old;
        do {
            old = assumed;
            float cur = __int_as_float(old);
            float nv = __logf(__expf(cur) + val);
            assumed = atomicCAS(ia, old, __float_as_int(nv));
        } while (assumed != old);
    }
}

// ---------------------------------------------------------------------------
// Launch
// ---------------------------------------------------------------------------
extern "C" void kernel_launch(void* const* d_in, const int* in_sizes, int n_in,
                              void* d_out, int out_size)
{
    const float* outs = (const float*)d_in[0];
    const float* gs   = (const float*)d_in[1];
    const unsigned char* mask = (const unsigned char*)d_in[2];
    const int*   cseq = (const int*)d_in[3];
    const float* Wq = (const float*)d_in[4],  *bq = (const float*)d_in[5];
    const float* Wk = (const float*)d_in[6],  *bk = (const float*)d_in[7];
    const float* Wv = (const float*)d_in[8],  *bv = (const float*)d_in[9];
    const float* Wo = (const float*)d_in[10], *bo = (const float*)d_in[11];
    const float* lng = (const float*)d_in[12], *lnb = (const float*)d_in[13];
    const float* Wt = (const float*)d_in[14], *bt = (const float*)d_in[15];
    const float* Wgen = (const float*)d_in[16], *bgen = (const float*)d_in[17];
    const float* Wdiv = (const float*)d_in[18], *bdiv = (const float*)d_in[19];
    float* out = (float*)d_out;

    float* sc = nullptr;
    cudaGetSymbolAddress((void**)&sc, g_scratch);
    float* q     = sc + OQ;
    float* k     = sc + OK_;
    float* v     = sc + OV;
    float* vt    = sc + OVT;
    float* attn  = sc + OA;
    float* ctx   = sc + OC;
    float* ln    = sc + OL;
    float* tok   = sc + OT;
    float* gts   = sc + OG;
    float* rowsum = sc + ORS;
    __nv_bfloat16* wgen_b = (__nv_bfloat16*)(sc + OWB);
    __nv_bfloat16* tok_b  = (__nv_bfloat16*)(sc + OTB);

    const float scale = 0.044194173824159216f; // 1/sqrt(512)
    constexpr int SMEM  = 65536;
    constexpr int SMEM3 = 98304;
    cudaFuncSetAttribute(mma_nt_kernel<0>, cudaFuncAttributeMaxDynamicSharedMemorySize, SMEM);
    cudaFuncSetAttribute(mma_nt_kernel<1>, cudaFuncAttributeMaxDynamicSharedMemorySize, SMEM);
    cudaFuncSetAttribute(mma_bf16_nt_kernel, cudaFuncAttributeMaxDynamicSharedMemorySize, SMEM3);
    dim3 blk(256);
    dim3 blkG(128);

    // Side stream + events (created once on the uncaptured correctness call;
    // record/wait pairs are graph-capturable fork/join).
    static cudaStream_t s2 = [] { cudaStream_t s; cudaStreamCreate(&s); return s; }();
    static cudaEvent_t evFork = [] { cudaEvent_t e; cudaEventCreateWithFlags(&e, cudaEventDisableTiming); return e; }();
    static cudaEvent_t evWgen = [] { cudaEvent_t e; cudaEventCreateWithFlags(&e, cudaEventDisableTiming); return e; }();
    static cudaEvent_t evV    = [] { cudaEvent_t e; cudaEventCreateWithFlags(&e, cudaEventDisableTiming); return e; }();
    static cudaEvent_t evVT   = [] { cudaEvent_t e; cudaEventCreateWithFlags(&e, cudaEventDisableTiming); return e; }();

    // fork: Wgen->bf16 + rowsum=0 on side stream (overlaps q/k/v GEMMs)
    cudaEventRecord(evFork, 0);
    cudaStreamWaitEvent(s2, evFork, 0);
    f2b_kernel<<<(V_ * TS_ / 4 + 255) / 256, blk, 0, s2>>>((const float4*)Wgen, (__nv_bfloat162*)wgen_b, V_ * TS_ / 4);
    zero_kernel<<<SB / 256, blk, 0, s2>>>(rowsum);
    cudaEventRecord(evWgen, s2);

    // main: q = (outs @ Wq^T + bq) * scale   [2048 x 512]
    mma_nt_kernel<0><<<dim3(4, 16, 1), blkG, SMEM>>>(outs, Wq, bq, q, nullptr, D_, D_, D_, D_, 0, 0, 0, scale);
    // k = gs @ Wk^T + bk                     [8192 x 512]
    mma_nt_kernel<0><<<dim3(4, 64, 1), blkG, SMEM>>>(gs, Wk, bk, k, nullptr, D_, D_, D_, D_, 0, 0, 0, 1.f);
    // v = gs @ Wv^T + bv
    mma_nt_kernel<0><<<dim3(4, 64, 1), blkG, SMEM>>>(gs, Wv, bv, v, nullptr, D_, D_, D_, D_, 0, 0, 0, 1.f);
    cudaEventRecord(evV, 0);

    // side: v transpose (overlaps scores + softmax on main)
    cudaStreamWaitEvent(s2, evV, 0);
    vt_kernel<<<dim3(32, 16, 8), blk, 0, s2>>>(v, vt);
    cudaEventRecord(evVT, s2);

    // main: scores[s,b,t] = q . k (batched over b), then softmax
    mma_nt_kernel<0><<<dim3(8, 2, 8), blkG, SMEM>>>(q, k, nullptr, attn, nullptr,
                                                    D_, B_ * D_, B_ * D_, B_ * T_,
                                                    D_, D_, T_, 1.f);
    attn_softmax_kernel<<<SB, 256>>>(attn, mask);

    // join vt, then ctx = attn @ v  (NT vs v_T, batched over b)
    cudaStreamWaitEvent(0, evVT, 0);
    mma_nt_kernel<0><<<dim3(4, 2, 8), blkG, SMEM>>>(attn, vt, nullptr, ctx, nullptr,
                                                    T_, B_ * T_, T_, B_ * D_,
                                                    T_, (long)D_ * T_, D_, 1.f);
    // x = ctx @ Wo^T + bo   -> reuse q buffer
    mma_nt_kernel<0><<<dim3(4, 16, 1), blkG, SMEM>>>(ctx, Wo, bo, q, nullptr, D_, D_, D_, D_, 0, 0, 0, 1.f);
    // outs_ln = LN(outs + x)
    ln_kernel<<<SB, 256>>>(outs, q, lng, lnb, ln);
    // tok = tanh(outs_ln @ Wt^T + bt); fused bf16 emit
    mma_nt_kernel<1><<<dim3(4, 16, 1), blkG, SMEM>>>(ln, Wt, bt, tok, tok_b, D_, D_, D_, TS_, 0, 0, 0, 1.f);
    // gates
    gates_kernel<<<SB, 128>>>(tok, Wdiv, bdiv, gts);

    // join Wgen conversion + rowsum init, then vocab GEMM (fused exp-rowsum)
    cudaStreamWaitEvent(0, evWgen, 0);
    mma_bf16_nt_kernel<<<dim3(250, 16, 1), blkG, SMEM3>>>(tok_b, wgen_b, bgen, out, rowsum,
                                                          TS_, TS_, TS_, V_);
    // fused coef + base log-probs + copy scatter (one block per row)
    lp_scatter_kernel<<<SB, 256>>>(out, rowsum, gts, attn, cseq);
}

// round 12
// speedup vs baseline: 1.0964x; 1.0077x over previous
#include <cuda_runtime.h>
#include <cuda_bf16.h>
#include <math.h>
#include <stdint.h>

// Problem dims (fixed for this dataset)
constexpr int S_  = 256;
constexpr int B_  = 8;
constexpr int T_  = 1024;
constexpr int D_  = 512;
constexpr int TS_ = 512;
constexpr int V_  = 32000;
constexpr int SB  = S_ * B_;   // 2048
constexpr int TB  = T_ * B_;   // 8192

// ---------------------------------------------------------------------------
// Scratch arena
// ---------------------------------------------------------------------------
constexpr size_t OQ  = 0;                        // q / later x      : SB*D
constexpr size_t OK_ = OQ  + (size_t)SB * D_;    // k                : TB*D
constexpr size_t OV  = OK_ + (size_t)TB * D_;    // v                : TB*D
constexpr size_t OVT = OV  + (size_t)TB * D_;    // v transposed     : TB*D
constexpr size_t OA  = OVT + (size_t)TB * D_;    // attn (scores)    : SB*T
constexpr size_t OC  = OA  + (size_t)SB * T_;    // ctx              : SB*D
constexpr size_t OL  = OC  + (size_t)SB * D_;    // layernorm out    : SB*D
constexpr size_t OT  = OL  + (size_t)SB * D_;    // outs_token (f32) : SB*D
constexpr size_t OG  = OT  + (size_t)SB * D_;    // gates            : SB*2
constexpr size_t ORS = OG  + (size_t)SB * 2;     // rowsum exp       : SB
constexpr size_t OWB = ORS + SB;                 // Wgen bf16        : V*TS/2 floats
constexpr size_t OTB = OWB + (size_t)V_ * TS_ / 2;  // tok bf16      : SB*TS/2
constexpr size_t SCRATCH_FLOATS = OTB + (size_t)SB * TS_ / 2;

__device__ float g_scratch[SCRATCH_FLOATS];

// ---------------------------------------------------------------------------
// math helpers
// ---------------------------------------------------------------------------
__device__ __forceinline__ float fexp(float x) {
    float t = fmaxf(fminf(x * 1.4426950408889634f, 126.f), -126.f);
    float mg = t + 12582912.f;
    int   n  = __float_as_int(mg) - 0x4B400000;
    float f  = t - (mg - 12582912.f);
    float p  = 1.54035304e-4f;
    p = fmaf(p, f, 1.33335581e-3f);
    p = fmaf(p, f, 9.61812911e-3f);
    p = fmaf(p, f, 5.55041087e-2f);
    p = fmaf(p, f, 2.40226507e-1f);
    p = fmaf(p, f, 6.93147182e-1f);
    p = fmaf(p, f, 1.0f);
    return __int_as_float(__float_as_int(p) + (n << 23));
}

__device__ __forceinline__ void mma_tf32(float& c0, float& c1, float& c2, float& c3,
                                         unsigned a0, unsigned a1, unsigned a2, unsigned a3,
                                         unsigned b0, unsigned b1)
{
    asm volatile(
        "mma.sync.aligned.m16n8k8.row.col.f32.tf32.tf32.f32 "
        "{%0,%1,%2,%3}, {%4,%5,%6,%7}, {%8,%9}, {%0,%1,%2,%3};"
        : "+f"(c0), "+f"(c1), "+f"(c2), "+f"(c3)
        : "r"(a0), "r"(a1), "r"(a2), "r"(a3), "r"(b0), "r"(b1));
}

__device__ __forceinline__ void mma_bf16(float& c0, float& c1, float& c2, float& c3,
                                         unsigned a0, unsigned a1, unsigned a2, unsigned a3,
                                         unsigned b0, unsigned b1)
{
    asm volatile(
        "mma.sync.aligned.m16n8k16.row.col.f32.bf16.bf16.f32 "
        "{%0,%1,%2,%3}, {%4,%5,%6,%7}, {%8,%9}, {%0,%1,%2,%3};"
        : "+f"(c0), "+f"(c1), "+f"(c2), "+f"(c3)
        : "r"(a0), "r"(a1), "r"(a2), "r"(a3), "r"(b0), "r"(b1));
}

__device__ __forceinline__ void ldsm_x4(unsigned& r0, unsigned& r1, unsigned& r2, unsigned& r3,
                                        unsigned addr)
{
    asm volatile("ldmatrix.sync.aligned.m8n8.x4.shared.b16 {%0,%1,%2,%3}, [%4];"
                 : "=r"(r0), "=r"(r1), "=r"(r2), "=r"(r3) : "r"(addr));
}

__device__ __forceinline__ void cp16(unsigned dst, const void* src) {
    asm volatile("cp.async.cg.shared.global [%0], [%1], 16;\n" :: "r"(dst), "l"(src));
}

// ---------------------------------------------------------------------------
// Tensor-core NT GEMM (tf32): C[m,n] = ACT(alpha*(sum A[m,k]*B[n,k] + bias[n]))
// 128x128 block, 4 warps, warp tile 64x64, BK=32, 64KB SMEM, 2 CTAs/SM.
// Single __syncthreads per k-iter (issue-at-top double buffering).
// If ACT==1 and Cb != nullptr, also writes bf16 copy of C into Cb.
// ---------------------------------------------------------------------------
template <int ACT>
__global__ __launch_bounds__(128, 2)
void mma_nt_kernel(const float* __restrict__ A, const float* __restrict__ Bm,
                   const float* __restrict__ bias, float* __restrict__ C,
                   __nv_bfloat16* __restrict__ Cb,
                   int K, int lda, int ldb, int ldc,
                   long sA, long sB, long sC, float alpha)
{
    extern __shared__ unsigned sh[];

    A  += (long)blockIdx.z * sA;
    Bm += (long)blockIdx.z * sB;
    C  += (long)blockIdx.z * sC;

    const int t    = threadIdx.x;
    const int lane = t & 31;
    const int warp = t >> 5;
    const int wm   = (warp >> 1) * 64;
    const int wn   = (warp & 1) * 64;
    const int grp  = lane >> 2;
    const int qid  = lane & 3;

    const long m0 = (long)blockIdx.y * 128;
    const long n0 = (long)blockIdx.x * 128;

    float acc[4][8][4];
#pragma unroll
    for (int mi = 0; mi < 4; mi++)
#pragma unroll
        for (int ni = 0; ni < 8; ni++)
#pragma unroll
            for (int c = 0; c < 4; c++) acc[mi][ni][c] = 0.f;

    const int row0 = t >> 3;
    const int c4   = t & 7;
    const float* aptr0 = A  + (m0 + row0) * lda + c4 * 4;
    const float* bptr0 = Bm + (n0 + row0) * ldb + c4 * 4;
    const unsigned soff0 = (unsigned)(row0 * 32 + ((c4 ^ (row0 & 7)) << 2)) * 4u;
    const unsigned sbase = (unsigned)__cvta_generic_to_shared(sh);

    auto issue = [&](int stage, int koff) {
        unsigned ab = sbase + (unsigned)stage * 16384u + soff0;
        unsigned bb = sbase + 32768u + (unsigned)stage * 16384u + soff0;
#pragma unroll
        for (int i = 0; i < 8; i++) {
            cp16(ab + i * 2048u, aptr0 + (long)i * 16 * lda + koff);
            cp16(bb + i * 2048u, bptr0 + (long)i * 16 * ldb + koff);
        }
        asm volatile("cp.async.commit_group;\n" ::: "memory");
    };

    issue(0, 0);
    const int nIter = K >> 5;
    for (int it = 0; it < nIter; ++it) {
        asm volatile("cp.async.wait_group 0;\n" ::: "memory");
        __syncthreads();
        if (it + 1 < nIter) issue((it + 1) & 1, (it + 1) * 32);

        const unsigned* Asb = sh + (it & 1) * 4096;
        const unsigned* Bsb = sh + 8192 + (it & 1) * 4096;
#pragma unroll
        for (int kk = 0; kk < 4; kk++) {
            unsigned af[4][4], bf[8][2];
#pragma unroll
            for (int mi = 0; mi < 4; mi++) {
                int m  = wm + mi * 16 + grp;
                int m8 = m + 8;
                af[mi][0] = Asb[m  * 32 + ((( kk * 2    ) ^ (m  & 7)) << 2) + qid];
                af[mi][1] = Asb[m8 * 32 + ((( kk * 2    ) ^ (m8 & 7)) << 2) + qid];
                af[mi][2] = Asb[m  * 32 + ((( kk * 2 + 1) ^ (m  & 7)) << 2) + qid];
                af[mi][3] = Asb[m8 * 32 + ((( kk * 2 + 1) ^ (m8 & 7)) << 2) + qid];
            }
#pragma unroll
            for (int ni = 0; ni < 8; ni++) {
                int n = wn + ni * 8 + grp;
                bf[ni][0] = Bsb[n * 32 + ((( kk * 2    ) ^ (n & 7)) << 2) + qid];
                bf[ni][1] = Bsb[n * 32 + ((( kk * 2 + 1) ^ (n & 7)) << 2) + qid];
            }
#pragma unroll
            for (int mi = 0; mi < 4; mi++)
#pragma unroll
                for (int ni = 0; ni < 8; ni++)
                    mma_tf32(acc[mi][ni][0], acc[mi][ni][1], acc[mi][ni][2], acc[mi][ni][3],
                             af[mi][0], af[mi][1], af[mi][2], af[mi][3],
                             bf[ni][0], bf[ni][1]);
        }
        // no trailing sync: next iter's (wait_group + barrier) covers both
        // cp-completion visibility and read-before-overwrite ordering.
    }

#pragma unroll
    for (int mi = 0; mi < 4; mi++) {
        long r0 = m0 + wm + mi * 16 + grp;
        long r1 = r0 + 8;
#pragma unroll
        for (int ni = 0; ni < 8; ni++) {
            long col = n0 + wn + ni * 8 + qid * 2;
            float bv0 = 0.f, bv1 = 0.f;
            if (bias) { bv0 = bias[col]; bv1 = bias[col + 1]; }
            float v00 = (acc[mi][ni][0] + bv0) * alpha;
            float v01 = (acc[mi][ni][1] + bv1) * alpha;
            float v10 = (acc[mi][ni][2] + bv0) * alpha;
            float v11 = (acc[mi][ni][3] + bv1) * alpha;
            if (ACT == 1) { v00 = tanhf(v00); v01 = tanhf(v01); v10 = tanhf(v10); v11 = tanhf(v11); }
            *(float2*)(C + r0 * ldc + col) = make_float2(v00, v01);
            *(float2*)(C + r1 * ldc + col) = make_float2(v10, v11);
            if (ACT == 1 && Cb) {
                *(__nv_bfloat162*)(Cb + r0 * ldc + col) = __floats2bfloat162_rn(v00, v01);
                *(__nv_bfloat162*)(Cb + r1 * ldc + col) = __floats2bfloat162_rn(v10, v11);
            }
        }
    }
}

// ---------------------------------------------------------------------------
// bf16 NT GEMM + fused exp-rowsum: 128x128 block, 4 warps, warp 64x64, BK=64.
// 2-stage cp.async (64KB SMEM), ldmatrix.x4 fragments, single sync per iter.
// 3 CTAs/SM (reg cap 170) for latency cover on the dominant vocab launch.
// ---------------------------------------------------------------------------
__global__ __launch_bounds__(128, 3)
void mma_bf16_nt_kernel(const __nv_bfloat16* __restrict__ A,
                        const __nv_bfloat16* __restrict__ Bm,
                        const float* __restrict__ bias, float* __restrict__ C,
                        float* __restrict__ rowsum,
                        int K, int lda, int ldb, int ldc)
{
    extern __shared__ unsigned sh[];

    const int t    = threadIdx.x;
    const int lane = t & 31;
    const int warp = t >> 5;
    const int wm   = (warp >> 1) * 64;
    const int wn   = (warp & 1) * 64;
    const int grp  = lane >> 2;
    const int qid  = lane & 3;

    const long m0 = (long)blockIdx.y * 128;
    const long n0 = (long)blockIdx.x * 128;

    float acc[4][8][4];
#pragma unroll
    for (int mi = 0; mi < 4; mi++)
#pragma unroll
        for (int ni = 0; ni < 8; ni++)
#pragma unroll
            for (int c = 0; c < 4; c++) acc[mi][ni][c] = 0.f;

    const int row0 = t >> 3;
    const int c8   = t & 7;
    const __nv_bfloat16* aptr0 = A  + (m0 + row0) * lda + c8 * 8;
    const __nv_bfloat16* bptr0 = Bm + (n0 + row0) * ldb + c8 * 8;
    const unsigned soff0 = (unsigned)(row0 * 128 + ((c8 ^ (row0 & 7)) << 4));
    const unsigned sbase = (unsigned)__cvta_generic_to_shared(sh);

    const int a_lr = lane & 15;
    const int a_cs = lane >> 4;
    unsigned a_off[4]; int a_m7[4];
#pragma unroll
    for (int mi = 0; mi < 4; mi++) {
        int m = wm + mi * 16 + a_lr;
        a_off[mi] = (unsigned)(m * 128);
        a_m7[mi]  = m & 7;
    }
    const int b_g  = lane >> 3;
    const int b_cs = b_g & 1;
    unsigned b_off[4]; int b_n7[4];
#pragma unroll
    for (int p = 0; p < 4; p++) {
        int n = wn + p * 16 + ((b_g & 2) << 2) + (lane & 7);
        b_off[p] = (unsigned)(n * 128);
        b_n7[p]  = n & 7;
    }

    // stage s (32KB): A at s*32768, B at s*32768 + 16384
    auto issue = [&](int stage, int koff) {
        unsigned ab = sbase + (unsigned)stage * 32768u + soff0;
        unsigned bb = ab + 16384u;
#pragma unroll
        for (int i = 0; i < 8; i++) {
            cp16(ab + i * 2048u, aptr0 + (long)i * 16 * lda + koff);
            cp16(bb + i * 2048u, bptr0 + (long)i * 16 * ldb + koff);
        }
        asm volatile("cp.async.commit_group;\n" ::: "memory");
    };

    const int nIter = K >> 6;                 // BK=64 (8 for K=512)
    issue(0, 0);
    for (int it = 0; it < nIter; ++it) {
        asm volatile("cp.async.wait_group 0;\n" ::: "memory");
        __syncthreads();
        if (it + 1 < nIter) issue((it + 1) & 1, (it + 1) * 64);

        unsigned abase = sbase + (unsigned)(it & 1) * 32768u;
        unsigned bbase = abase + 16384u;
#pragma unroll
        for (int kk = 0; kk < 4; kk++) {
            unsigned af[4][4], bf[8][2];
            int ca = kk * 2 + a_cs;
            int cb = kk * 2 + b_cs;
#pragma unroll
            for (int mi = 0; mi < 4; mi++) {
                unsigned addr = abase + a_off[mi] + (unsigned)((ca ^ a_m7[mi]) << 4);
                ldsm_x4(af[mi][0], af[mi][1], af[mi][2], af[mi][3], addr);
            }
#pragma unroll
            for (int p = 0; p < 4; p++) {
                unsigned addr = bbase + b_off[p] + (unsigned)((cb ^ b_n7[p]) << 4);
                ldsm_x4(bf[2*p][0], bf[2*p][1], bf[2*p+1][0], bf[2*p+1][1], addr);
            }
#pragma unroll
            for (int mi = 0; mi < 4; mi++)
#pragma unroll
                for (int ni = 0; ni < 8; ni++)
                    mma_bf16(acc[mi][ni][0], acc[mi][ni][1], acc[mi][ni][2], acc[mi][ni][3],
                             af[mi][0], af[mi][1], af[mi][2], af[mi][3],
                             bf[ni][0], bf[ni][1]);
        }
    }

    // epilogue: write logits + per-row sum of exp
#pragma unroll
    for (int mi = 0; mi < 4; mi++) {
        long r0 = m0 + wm + mi * 16 + grp;
        long r1 = r0 + 8;
        float e0 = 0.f, e1 = 0.f;
#pragma unroll
        for (int ni = 0; ni < 8; ni++) {
            long col = n0 + wn + ni * 8 + qid * 2;
            float bv0 = bias[col], bv1 = bias[col + 1];
            float v00 = acc[mi][ni][0] + bv0;
            float v01 = acc[mi][ni][1] + bv1;
            float v10 = acc[mi][ni][2] + bv0;
            float v11 = acc[mi][ni][3] + bv1;
            *(float2*)(C + r0 * ldc + col) = make_float2(v00, v01);
            *(float2*)(C + r1 * ldc + col) = make_float2(v10, v11);
            e0 += fexp(v00) + fexp(v01);
            e1 += fexp(v10) + fexp(v11);
        }
        e0 += __shfl_xor_sync(0xFFFFFFFFu, e0, 1);
        e0 += __shfl_xor_sync(0xFFFFFFFFu, e0, 2);
        e1 += __shfl_xor_sync(0xFFFFFFFFu, e1, 1);
        e1 += __shfl_xor_sync(0xFFFFFFFFu, e1, 2);
        if (qid == 0) {
            atomicAdd(rowsum + r0, e0);
            atomicAdd(rowsum + r1, e1);
        }
    }
}

// ---------------------------------------------------------------------------
// fp32 -> bf16 convert
// ---------------------------------------------------------------------------
__global__ __launch_bounds__(256)
void f2b_kernel(const float4* __restrict__ in, __nv_bfloat162* __restrict__ out, int n4)
{
    int i = blockIdx.x * 256 + threadIdx.x;
    if (i >= n4) return;
    float4 v = in[i];
    out[i * 2]     = __floats2bfloat162_rn(v.x, v.y);
    out[i * 2 + 1] = __floats2bfloat162_rn(v.z, v.w);
}

__global__ void zero_kernel(float* __restrict__ p)
{
    p[blockIdx.x * 256 + threadIdx.x] = 0.f;
}

// ---------------------------------------------------------------------------
// v transpose: vt[b][d][t] = v[(t*B+b)*D + d].
// ---------------------------------------------------------------------------
__global__ __launch_bounds__(256)
void vt_kernel(const float* __restrict__ v, float* __restrict__ vt)
{
    __shared__ float tile[32][33];
    int b  = blockIdx.z;
    int t0 = blockIdx.x * 32;
    int d0 = blockIdx.y * 32;
    int x  = threadIdx.x & 31;
    int y  = threadIdx.x >> 5;
#pragma unroll
    for (int j = 0; j < 32; j += 8)
        tile[y + j][x] = v[((long)(t0 + y + j) * B_ + b) * D_ + d0 + x];
    __syncthreads();
#pragma unroll
    for (int j = 0; j < 32; j += 8)
        vt[(long)b * D_ * T_ + (long)(d0 + y + j) * T_ + t0 + x] = tile[x][y + j];
}

// ---------------------------------------------------------------------------
// Softmax over T (in-place). mask: [B,T] bytes.
// ---------------------------------------------------------------------------
__global__ __launch_bounds__(256)
void attn_softmax_kernel(float* __restrict__ attn, const unsigned char* __restrict__ mask)
{
    int row = blockIdx.x;
    int b   = row & (B_ - 1);
    float* p = attn + (long)row * T_;
    const unsigned char* mrow = mask + (long)b * T_;
    int t = threadIdx.x;
    __shared__ float red[256];

    float x[4];
    float mx = -1e30f;
#pragma unroll
    for (int i = 0; i < 4; i++) {
        int tt = t + i * 256;
        float v = p[tt];
        if (mrow[tt]) v = -1e9f;
        x[i] = v;
        mx = fmaxf(mx, v);
    }
    red[t] = mx; __syncthreads();
    for (int s = 128; s > 0; s >>= 1) {
        if (t < s) red[t] = fmaxf(red[t], red[t + s]);
        __syncthreads();
    }
    mx = red[0]; __syncthreads();

    float sum = 0.f;
#pragma unroll
    for (int i = 0; i < 4; i++) { x[i] = fexp(x[i] - mx); sum += x[i]; }
    red[t] = sum; __syncthreads();
    for (int s = 128; s > 0; s >>= 1) {
        if (t < s) red[t] += red[t + s];
        __syncthreads();
    }
    float inv = 1.f / red[0];
#pragma unroll
    for (int i = 0; i < 4; i++) p[t + i * 256] = x[i] * inv;
}

// ---------------------------------------------------------------------------
// LayerNorm(outs + x).
// ---------------------------------------------------------------------------
__global__ __launch_bounds__(256)
void ln_kernel(const float* __restrict__ outs, const float* __restrict__ x,
               const float* __restrict__ g, const float* __restrict__ bb,
               float* __restrict__ out)
{
    int row = blockIdx.x;
    int t = threadIdx.x;
    const float* o  = outs + (long)row * D_;
    const float* xr = x    + (long)row * D_;
    __shared__ float red[256];

    float v0 = o[t] + xr[t];
    float v1 = o[t + 256] + xr[t + 256];

    red[t] = v0 + v1; __syncthreads();
    for (int s = 128; s > 0; s >>= 1) { if (t < s) red[t] += red[t + s]; __syncthreads(); }
    float mu = red[0] * (1.f / D_); __syncthreads();

    float d0 = v0 - mu, d1 = v1 - mu;
    red[t] = d0 * d0 + d1 * d1; __syncthreads();
    for (int s = 128; s > 0; s >>= 1) { if (t < s) red[t] += red[t + s]; __syncthreads(); }
    float inv = rsqrtf(red[0] * (1.f / D_) + 1e-5f);

    out[(long)row * D_ + t]       = d0 * inv * g[t]       + bb[t];
    out[(long)row * D_ + t + 256] = d1 * inv * g[t + 256] + bb[t + 256];
}

// ---------------------------------------------------------------------------
// 2-way gate
// ---------------------------------------------------------------------------
__global__ __launch_bounds__(128)
void gates_kernel(const float* __restrict__ tok, const float* __restrict__ Wdiv,
                  const float* __restrict__ bdiv, float* __restrict__ gates)
{
    int row = blockIdx.x;
    int t = threadIdx.x;
    const float* x = tok + (long)row * D_;
    float z0 = 0.f, z1 = 0.f;
    for (int d = t; d < D_; d += 128) {
        float xv = x[d];
        z0 = fmaf(xv, Wdiv[d],      z0);
        z1 = fmaf(xv, Wdiv[D_ + d], z1);
    }
    __shared__ float r0[128], r1[128];
    r0[t] = z0; r1[t] = z1; __syncthreads();
    for (int s = 64; s > 0; s >>= 1) {
        if (t < s) { r0[t] += r0[t + s]; r1[t] += r1[t + s]; }
        __syncthreads();
    }
    if (t == 0) {
        float a = r0[0] + bdiv[0], b = r1[0] + bdiv[1];
        float m = fmaxf(a, b);
        float e0 = __expf(a - m), e1 = __expf(b - m);
        float inv = 1.f / (e0 + e1);
        gates[row * 2 + 0] = e0 * inv;
        gates[row * 2 + 1] = e1 * inv;
    }
}

// ---------------------------------------------------------------------------
// Fused coef + log-prob base + copy-scatter. One block (256 thr) per row.
// ---------------------------------------------------------------------------
__global__ __launch_bounds__(256)
void lp_scatter_kernel(float* __restrict__ out, const float* __restrict__ rowsum,
                       const float* __restrict__ gates, const float* __restrict__ attn,
                       const int* __restrict__ copy_seq)
{
    int row = blockIdx.x;
    int t   = threadIdx.x;
    int b   = row & (B_ - 1);

    float coef = __logf(gates[row * 2 + 0]) - __logf(rowsum[row]);
    float gate1 = gates[row * 2 + 1];

    float4* o4 = (float4*)(out + (long)row * V_);
    for (int j = t; j < V_ / 4; j += 256) {
        float4 v = o4[j];
        v.x += coef; v.y += coef; v.z += coef; v.w += coef;
        o4[j] = v;
    }
    __syncthreads();

    const float* arow = attn + (long)row * T_;
    float* orow = out + (long)row * V_;
#pragma unroll
    for (int e = 0; e < 4; e++) {
        int tt = t + e * 256;
        float val = gate1 * arow[tt];
        int idx = copy_seq[tt * B_ + b];
        int* ia = (int*)(orow + idx);
        int assumed = *ia;
        int old;
        do {
            old = assumed;
            float cur = __int_as_float(old);
            float nv = __logf(__expf(cur) + val);
            assumed = atomicCAS(ia, old, __float_as_int(nv));
        } while (assumed != old);
    }
}

// ---------------------------------------------------------------------------
// Launch
// ---------------------------------------------------------------------------
extern "C" void kernel_launch(void* const* d_in, const int* in_sizes, int n_in,
                              void* d_out, int out_size)
{
    const float* outs = (const float*)d_in[0];
    const float* gs   = (const float*)d_in[1];
    const unsigned char* mask = (const unsigned char*)d_in[2];
    const int*   cseq = (const int*)d_in[3];
    const float* Wq = (const float*)d_in[4],  *bq = (const float*)d_in[5];
    const float* Wk = (const float*)d_in[6],  *bk = (const float*)d_in[7];
    const float* Wv = (const float*)d_in[8],  *bv = (const float*)d_in[9];
    const float* Wo = (const float*)d_in[10], *bo = (const float*)d_in[11];
    const float* lng = (const float*)d_in[12], *lnb = (const float*)d_in[13];
    const float* Wt = (const float*)d_in[14], *bt = (const float*)d_in[15];
    const float* Wgen = (const float*)d_in[16], *bgen = (const float*)d_in[17];
    const float* Wdiv = (const float*)d_in[18], *bdiv = (const float*)d_in[19];
    float* out = (float*)d_out;

    float* sc = nullptr;
    cudaGetSymbolAddress((void**)&sc, g_scratch);
    float* q     = sc + OQ;
    float* k     = sc + OK_;
    float* v     = sc + OV;
    float* vt    = sc + OVT;
    float* attn  = sc + OA;
    float* ctx   = sc + OC;
    float* ln    = sc + OL;
    float* tok   = sc + OT;
    float* gts   = sc + OG;
    float* rowsum = sc + ORS;
    __nv_bfloat16* wgen_b = (__nv_bfloat16*)(sc + OWB);
    __nv_bfloat16* tok_b  = (__nv_bfloat16*)(sc + OTB);

    const float scale = 0.044194173824159216f; // 1/sqrt(512)
    constexpr int SMEM  = 65536;
    cudaFuncSetAttribute(mma_nt_kernel<0>, cudaFuncAttributeMaxDynamicSharedMemorySize, SMEM);
    cudaFuncSetAttribute(mma_nt_kernel<1>, cudaFuncAttributeMaxDynamicSharedMemorySize, SMEM);
    cudaFuncSetAttribute(mma_bf16_nt_kernel, cudaFuncAttributeMaxDynamicSharedMemorySize, SMEM);
    dim3 blk(256);
    dim3 blkG(128);

    // Side stream + events (created once on the uncaptured correctness call).
    static cudaStream_t s2 = [] { cudaStream_t s; cudaStreamCreate(&s); return s; }();
    static cudaEvent_t evFork = [] { cudaEvent_t e; cudaEventCreateWithFlags(&e, cudaEventDisableTiming); return e; }();
    static cudaEvent_t evWgen = [] { cudaEvent_t e; cudaEventCreateWithFlags(&e, cudaEventDisableTiming); return e; }();
    static cudaEvent_t evV    = [] { cudaEvent_t e; cudaEventCreateWithFlags(&e, cudaEventDisableTiming); return e; }();
    static cudaEvent_t evVT   = [] { cudaEvent_t e; cudaEventCreateWithFlags(&e, cudaEventDisableTiming); return e; }();

    // fork: Wgen->bf16 + rowsum=0 on side stream (overlaps q/k/v GEMMs)
    cudaEventRecord(evFork, 0);
    cudaStreamWaitEvent(s2, evFork, 0);
    f2b_kernel<<<(V_ * TS_ / 4 + 255) / 256, blk, 0, s2>>>((const float4*)Wgen, (__nv_bfloat162*)wgen_b, V_ * TS_ / 4);
    zero_kernel<<<SB / 256, blk, 0, s2>>>(rowsum);
    cudaEventRecord(evWgen, s2);

    // main: q = (outs @ Wq^T + bq) * scale   [2048 x 512]
    mma_nt_kernel<0><<<dim3(4, 16, 1), blkG, SMEM>>>(outs, Wq, bq, q, nullptr, D_, D_, D_, D_, 0, 0, 0, scale);
    // k = gs @ Wk^T + bk                     [8192 x 512]
    mma_nt_kernel<0><<<dim3(4, 64, 1), blkG, SMEM>>>(gs, Wk, bk, k, nullptr, D_, D_, D_, D_, 0, 0, 0, 1.f);
    // v = gs @ Wv^T + bv
    mma_nt_kernel<0><<<dim3(4, 64, 1), blkG, SMEM>>>(gs, Wv, bv, v, nullptr, D_, D_, D_, D_, 0, 0, 0, 1.f);
    cudaEventRecord(evV, 0);

    // side: v transpose (overlaps scores + softmax on main)
    cudaStreamWaitEvent(s2, evV, 0);
    vt_kernel<<<dim3(32, 16, 8), blk, 0, s2>>>(v, vt);
    cudaEventRecord(evVT, s2);

    // main: scores[s,b,t] = q . k (batched over b), then softmax
    mma_nt_kernel<0><<<dim3(8, 2, 8), blkG, SMEM>>>(q, k, nullptr, attn, nullptr,
                                                    D_, B_ * D_, B_ * D_, B_ * T_,
                                                    D_, D_, T_, 1.f);
    attn_softmax_kernel<<<SB, 256>>>(attn, mask);

    // join vt, then ctx = attn @ v  (NT vs v_T, batched over b)
    cudaStreamWaitEvent(0, evVT, 0);
    mma_nt_kernel<0><<<dim3(4, 2, 8), blkG, SMEM>>>(attn, vt, nullptr, ctx, nullptr,
                                                    T_, B_ * T_, T_, B_ * D_,
                                                    T_, (long)D_ * T_, D_, 1.f);
    // x = ctx @ Wo^T + bo   -> reuse q buffer
    mma_nt_kernel<0><<<dim3(4, 16, 1), blkG, SMEM>>>(ctx, Wo, bo, q, nullptr, D_, D_, D_, D_, 0, 0, 0, 1.f);
    // outs_ln = LN(outs + x)
    ln_kernel<<<SB, 256>>>(outs, q, lng, lnb, ln);
    // tok = tanh(outs_ln @ Wt^T + bt); fused bf16 emit
    mma_nt_kernel<1><<<dim3(4, 16, 1), blkG, SMEM>>>(ln, Wt, bt, tok, tok_b, D_, D_, D_, TS_, 0, 0, 0, 1.f);
    // gates
    gates_kernel<<<SB, 128>>>(tok, Wdiv, bdiv, gts);

    // join Wgen conversion + rowsum init, then vocab GEMM (fused exp-rowsum)
    cudaStreamWaitEvent(0, evWgen, 0);
    mma_bf16_nt_kernel<<<dim3(250, 16, 1), blkG, SMEM>>>(tok_b, wgen_b, bgen, out, rowsum,
                                                         TS_, TS_, TS_, V_);
    // fused coef + base log-probs + copy scatter (one block per row)
    lp_scatter_kernel<<<SB, 256>>>(out, rowsum, gts, attn, cseq);
}

// round 13
// speedup vs baseline: 1.1095x; 1.0119x over previous
#include <cuda_runtime.h>
#include <cuda_bf16.h>
#include <math.h>
#include <stdint.h>

// Problem dims (fixed for this dataset)
constexpr int S_  = 256;
constexpr int B_  = 8;
constexpr int T_  = 1024;
constexpr int D_  = 512;
constexpr int TS_ = 512;
constexpr int V_  = 32000;
constexpr int SB  = S_ * B_;   // 2048
constexpr int TB  = T_ * B_;   // 8192

// ---------------------------------------------------------------------------
// Scratch arena
// ---------------------------------------------------------------------------
constexpr size_t OQ  = 0;                        // q / later x      : SB*D
constexpr size_t OK_ = OQ  + (size_t)SB * D_;    // k                : TB*D
constexpr size_t OV  = OK_ + (size_t)TB * D_;    // v                : TB*D
constexpr size_t OVT = OV  + (size_t)TB * D_;    // v transposed     : TB*D
constexpr size_t OA  = OVT + (size_t)TB * D_;    // attn (scores)    : SB*T
constexpr size_t OC  = OA  + (size_t)SB * T_;    // ctx              : SB*D
constexpr size_t OL  = OC  + (size_t)SB * D_;    // layernorm out    : SB*D
constexpr size_t OT  = OL  + (size_t)SB * D_;    // outs_token (f32) : SB*D
constexpr size_t OG  = OT  + (size_t)SB * D_;    // gates            : SB*2
constexpr size_t ORS = OG  + (size_t)SB * 2;     // rowsum exp       : SB
constexpr size_t OWB = ORS + SB;                 // Wgen bf16        : V*TS/2 floats
constexpr size_t OTB = OWB + (size_t)V_ * TS_ / 2;  // tok bf16      : SB*TS/2
constexpr size_t SCRATCH_FLOATS = OTB + (size_t)SB * TS_ / 2;

__device__ float g_scratch[SCRATCH_FLOATS];

// ---------------------------------------------------------------------------
// math helpers
// ---------------------------------------------------------------------------
__device__ __forceinline__ float fexp(float x) {
    float t = fmaxf(fminf(x * 1.4426950408889634f, 126.f), -126.f);
    float mg = t + 12582912.f;
    int   n  = __float_as_int(mg) - 0x4B400000;
    float f  = t - (mg - 12582912.f);
    float p  = 1.54035304e-4f;
    p = fmaf(p, f, 1.33335581e-3f);
    p = fmaf(p, f, 9.61812911e-3f);
    p = fmaf(p, f, 5.55041087e-2f);
    p = fmaf(p, f, 2.40226507e-1f);
    p = fmaf(p, f, 6.93147182e-1f);
    p = fmaf(p, f, 1.0f);
    return __int_as_float(__float_as_int(p) + (n << 23));
}

__device__ __forceinline__ void mma_tf32(float& c0, float& c1, float& c2, float& c3,
                                         unsigned a0, unsigned a1, unsigned a2, unsigned a3,
                                         unsigned b0, unsigned b1)
{
    asm volatile(
        "mma.sync.aligned.m16n8k8.row.col.f32.tf32.tf32.f32 "
        "{%0,%1,%2,%3}, {%4,%5,%6,%7}, {%8,%9}, {%0,%1,%2,%3};"
        : "+f"(c0), "+f"(c1), "+f"(c2), "+f"(c3)
        : "r"(a0), "r"(a1), "r"(a2), "r"(a3), "r"(b0), "r"(b1));
}

__device__ __forceinline__ void mma_bf16(float& c0, float& c1, float& c2, float& c3,
                                         unsigned a0, unsigned a1, unsigned a2, unsigned a3,
                                         unsigned b0, unsigned b1)
{
    asm volatile(
        "mma.sync.aligned.m16n8k16.row.col.f32.bf16.bf16.f32 "
        "{%0,%1,%2,%3}, {%4,%5,%6,%7}, {%8,%9}, {%0,%1,%2,%3};"
        : "+f"(c0), "+f"(c1), "+f"(c2), "+f"(c3)
        : "r"(a0), "r"(a1), "r"(a2), "r"(a3), "r"(b0), "r"(b1));
}

__device__ __forceinline__ void ldsm_x4(unsigned& r0, unsigned& r1, unsigned& r2, unsigned& r3,
                                        unsigned addr)
{
    asm volatile("ldmatrix.sync.aligned.m8n8.x4.shared.b16 {%0,%1,%2,%3}, [%4];"
                 : "=r"(r0), "=r"(r1), "=r"(r2), "=r"(r3) : "r"(addr));
}

__device__ __forceinline__ void cp16(unsigned dst, const void* src) {
    asm volatile("cp.async.cg.shared.global [%0], [%1], 16;\n" :: "r"(dst), "l"(src));
}

// ---------------------------------------------------------------------------
// Tensor-core NT GEMM (tf32): C[m,n] = ACT(alpha*(sum A[m,k]*B[n,k] + bias[n]))
// 128x128 block, 4 warps, warp tile 64x64, BK=32, 64KB SMEM, 2 CTAs/SM.
// Single __syncthreads per k-iter. If ACT==1 and Cb, also emits bf16 copy.
// ---------------------------------------------------------------------------
template <int ACT>
__global__ __launch_bounds__(128, 2)
void mma_nt_kernel(const float* __restrict__ A, const float* __restrict__ Bm,
                   const float* __restrict__ bias, float* __restrict__ C,
                   __nv_bfloat16* __restrict__ Cb,
                   int K, int lda, int ldb, int ldc,
                   long sA, long sB, long sC, float alpha)
{
    extern __shared__ unsigned sh[];

    A  += (long)blockIdx.z * sA;
    Bm += (long)blockIdx.z * sB;
    C  += (long)blockIdx.z * sC;

    const int t    = threadIdx.x;
    const int lane = t & 31;
    const int warp = t >> 5;
    const int wm   = (warp >> 1) * 64;
    const int wn   = (warp & 1) * 64;
    const int grp  = lane >> 2;
    const int qid  = lane & 3;

    const long m0 = (long)blockIdx.y * 128;
    const long n0 = (long)blockIdx.x * 128;

    float acc[4][8][4];
#pragma unroll
    for (int mi = 0; mi < 4; mi++)
#pragma unroll
        for (int ni = 0; ni < 8; ni++)
#pragma unroll
            for (int c = 0; c < 4; c++) acc[mi][ni][c] = 0.f;

    const int row0 = t >> 3;
    const int c4   = t & 7;
    const float* aptr0 = A  + (m0 + row0) * lda + c4 * 4;
    const float* bptr0 = Bm + (n0 + row0) * ldb + c4 * 4;
    const unsigned soff0 = (unsigned)(row0 * 32 + ((c4 ^ (row0 & 7)) << 2)) * 4u;
    const unsigned sbase = (unsigned)__cvta_generic_to_shared(sh);

    auto issue = [&](int stage, int koff) {
        unsigned ab = sbase + (unsigned)stage * 16384u + soff0;
        unsigned bb = sbase + 32768u + (unsigned)stage * 16384u + soff0;
#pragma unroll
        for (int i = 0; i < 8; i++) {
            cp16(ab + i * 2048u, aptr0 + (long)i * 16 * lda + koff);
            cp16(bb + i * 2048u, bptr0 + (long)i * 16 * ldb + koff);
        }
        asm volatile("cp.async.commit_group;\n" ::: "memory");
    };

    issue(0, 0);
    const int nIter = K >> 5;
    for (int it = 0; it < nIter; ++it) {
        asm volatile("cp.async.wait_group 0;\n" ::: "memory");
        __syncthreads();
        if (it + 1 < nIter) issue((it + 1) & 1, (it + 1) * 32);

        const unsigned* Asb = sh + (it & 1) * 4096;
        const unsigned* Bsb = sh + 8192 + (it & 1) * 4096;
#pragma unroll
        for (int kk = 0; kk < 4; kk++) {
            unsigned af[4][4], bf[8][2];
#pragma unroll
            for (int mi = 0; mi < 4; mi++) {
                int m  = wm + mi * 16 + grp;
                int m8 = m + 8;
                af[mi][0] = Asb[m  * 32 + ((( kk * 2    ) ^ (m  & 7)) << 2) + qid];
                af[mi][1] = Asb[m8 * 32 + ((( kk * 2    ) ^ (m8 & 7)) << 2) + qid];
                af[mi][2] = Asb[m  * 32 + ((( kk * 2 + 1) ^ (m  & 7)) << 2) + qid];
                af[mi][3] = Asb[m8 * 32 + ((( kk * 2 + 1) ^ (m8 & 7)) << 2) + qid];
            }
#pragma unroll
            for (int ni = 0; ni < 8; ni++) {
                int n = wn + ni * 8 + grp;
                bf[ni][0] = Bsb[n * 32 + ((( kk * 2    ) ^ (n & 7)) << 2) + qid];
                bf[ni][1] = Bsb[n * 32 + ((( kk * 2 + 1) ^ (n & 7)) << 2) + qid];
            }
#pragma unroll
            for (int mi = 0; mi < 4; mi++)
#pragma unroll
                for (int ni = 0; ni < 8; ni++)
                    mma_tf32(acc[mi][ni][0], acc[mi][ni][1], acc[mi][ni][2], acc[mi][ni][3],
                             af[mi][0], af[mi][1], af[mi][2], af[mi][3],
                             bf[ni][0], bf[ni][1]);
        }
    }

#pragma unroll
    for (int mi = 0; mi < 4; mi++) {
        long r0 = m0 + wm + mi * 16 + grp;
        long r1 = r0 + 8;
#pragma unroll
        for (int ni = 0; ni < 8; ni++) {
            long col = n0 + wn + ni * 8 + qid * 2;
            float bv0 = 0.f, bv1 = 0.f;
            if (bias) { bv0 = bias[col]; bv1 = bias[col + 1]; }
            float v00 = (acc[mi][ni][0] + bv0) * alpha;
            float v01 = (acc[mi][ni][1] + bv1) * alpha;
            float v10 = (acc[mi][ni][2] + bv0) * alpha;
            float v11 = (acc[mi][ni][3] + bv1) * alpha;
            if (ACT == 1) { v00 = tanhf(v00); v01 = tanhf(v01); v10 = tanhf(v10); v11 = tanhf(v11); }
            *(float2*)(C + r0 * ldc + col) = make_float2(v00, v01);
            *(float2*)(C + r1 * ldc + col) = make_float2(v10, v11);
            if (ACT == 1 && Cb) {
                *(__nv_bfloat162*)(Cb + r0 * ldc + col) = __floats2bfloat162_rn(v00, v01);
                *(__nv_bfloat162*)(Cb + r1 * ldc + col) = __floats2bfloat162_rn(v10, v11);
            }
        }
    }
}

// ---------------------------------------------------------------------------
// bf16 NT GEMM + fused exp-rowsum: 128x128 block, 4 warps, warp 64x64, BK=64.
// 2-stage cp.async (64KB SMEM), ldmatrix.x4 fragments, 3 CTAs/SM.
// ---------------------------------------------------------------------------
__global__ __launch_bounds__(128, 3)
void mma_bf16_nt_kernel(const __nv_bfloat16* __restrict__ A,
                        const __nv_bfloat16* __restrict__ Bm,
                        const float* __restrict__ bias, float* __restrict__ C,
                        float* __restrict__ rowsum,
                        int K, int lda, int ldb, int ldc)
{
    extern __shared__ unsigned sh[];

    const int t    = threadIdx.x;
    const int lane = t & 31;
    const int warp = t >> 5;
    const int wm   = (warp >> 1) * 64;
    const int wn   = (warp & 1) * 64;
    const int grp  = lane >> 2;
    const int qid  = lane & 3;

    const long m0 = (long)blockIdx.y * 128;
    const long n0 = (long)blockIdx.x * 128;

    float acc[4][8][4];
#pragma unroll
    for (int mi = 0; mi < 4; mi++)
#pragma unroll
        for (int ni = 0; ni < 8; ni++)
#pragma unroll
            for (int c = 0; c < 4; c++) acc[mi][ni][c] = 0.f;

    const int row0 = t >> 3;
    const int c8   = t & 7;
    const __nv_bfloat16* aptr0 = A  + (m0 + row0) * lda + c8 * 8;
    const __nv_bfloat16* bptr0 = Bm + (n0 + row0) * ldb + c8 * 8;
    const unsigned soff0 = (unsigned)(row0 * 128 + ((c8 ^ (row0 & 7)) << 4));
    const unsigned sbase = (unsigned)__cvta_generic_to_shared(sh);

    const int a_lr = lane & 15;
    const int a_cs = lane >> 4;
    unsigned a_off[4]; int a_m7[4];
#pragma unroll
    for (int mi = 0; mi < 4; mi++) {
        int m = wm + mi * 16 + a_lr;
        a_off[mi] = (unsigned)(m * 128);
        a_m7[mi]  = m & 7;
    }
    const int b_g  = lane >> 3;
    const int b_cs = b_g & 1;
    unsigned b_off[4]; int b_n7[4];
#pragma unroll
    for (int p = 0; p < 4; p++) {
        int n = wn + p * 16 + ((b_g & 2) << 2) + (lane & 7);
        b_off[p] = (unsigned)(n * 128);
        b_n7[p]  = n & 7;
    }

    auto issue = [&](int stage, int koff) {
        unsigned ab = sbase + (unsigned)stage * 32768u + soff0;
        unsigned bb = ab + 16384u;
#pragma unroll
        for (int i = 0; i < 8; i++) {
            cp16(ab + i * 2048u, aptr0 + (long)i * 16 * lda + koff);
            cp16(bb + i * 2048u, bptr0 + (long)i * 16 * ldb + koff);
        }
        asm volatile("cp.async.commit_group;\n" ::: "memory");
    };

    const int nIter = K >> 6;
    issue(0, 0);
    for (int it = 0; it < nIter; ++it) {
        asm volatile("cp.async.wait_group 0;\n" ::: "memory");
        __syncthreads();
        if (it + 1 < nIter) issue((it + 1) & 1, (it + 1) * 64);

        unsigned abase = sbase + (unsigned)(it & 1) * 32768u;
        unsigned bbase = abase + 16384u;
#pragma unroll
        for (int kk = 0; kk < 4; kk++) {
            unsigned af[4][4], bf[8][2];
            int ca = kk * 2 + a_cs;
            int cb = kk * 2 + b_cs;
#pragma unroll
            for (int mi = 0; mi < 4; mi++) {
                unsigned addr = abase + a_off[mi] + (unsigned)((ca ^ a_m7[mi]) << 4);
                ldsm_x4(af[mi][0], af[mi][1], af[mi][2], af[mi][3], addr);
            }
#pragma unroll
            for (int p = 0; p < 4; p++) {
                unsigned addr = bbase + b_off[p] + (unsigned)((cb ^ b_n7[p]) << 4);
                ldsm_x4(bf[2*p][0], bf[2*p][1], bf[2*p+1][0], bf[2*p+1][1], addr);
            }
#pragma unroll
            for (int mi = 0; mi < 4; mi++)
#pragma unroll
                for (int ni = 0; ni < 8; ni++)
                    mma_bf16(acc[mi][ni][0], acc[mi][ni][1], acc[mi][ni][2], acc[mi][ni][3],
                             af[mi][0], af[mi][1], af[mi][2], af[mi][3],
                             bf[ni][0], bf[ni][1]);
        }
    }

    // epilogue: write logits + per-row sum of exp
#pragma unroll
    for (int mi = 0; mi < 4; mi++) {
        long r0 = m0 + wm + mi * 16 + grp;
        long r1 = r0 + 8;
        float e0 = 0.f, e1 = 0.f;
#pragma unroll
        for (int ni = 0; ni < 8; ni++) {
            long col = n0 + wn + ni * 8 + qid * 2;
            float bv0 = bias[col], bv1 = bias[col + 1];
            float v00 = acc[mi][ni][0] + bv0;
            float v01 = acc[mi][ni][1] + bv1;
            float v10 = acc[mi][ni][2] + bv0;
            float v11 = acc[mi][ni][3] + bv1;
            *(float2*)(C + r0 * ldc + col) = make_float2(v00, v01);
            *(float2*)(C + r1 * ldc + col) = make_float2(v10, v11);
            e0 += fexp(v00) + fexp(v01);
            e1 += fexp(v10) + fexp(v11);
        }
        e0 += __shfl_xor_sync(0xFFFFFFFFu, e0, 1);
        e0 += __shfl_xor_sync(0xFFFFFFFFu, e0, 2);
        e1 += __shfl_xor_sync(0xFFFFFFFFu, e1, 1);
        e1 += __shfl_xor_sync(0xFFFFFFFFu, e1, 2);
        if (qid == 0) {
            atomicAdd(rowsum + r0, e0);
            atomicAdd(rowsum + r1, e1);
        }
    }
}

// ---------------------------------------------------------------------------
// fp32 -> bf16 convert
// ---------------------------------------------------------------------------
__global__ __launch_bounds__(256)
void f2b_kernel(const float4* __restrict__ in, __nv_bfloat162* __restrict__ out, int n4)
{
    int i = blockIdx.x * 256 + threadIdx.x;
    if (i >= n4) return;
    float4 v = in[i];
    out[i * 2]     = __floats2bfloat162_rn(v.x, v.y);
    out[i * 2 + 1] = __floats2bfloat162_rn(v.z, v.w);
}

__global__ void zero_kernel(float* __restrict__ p)
{
    p[blockIdx.x * 256 + threadIdx.x] = 0.f;
}

// ---------------------------------------------------------------------------
// v transpose: vt[b][d][t] = v[(t*B+b)*D + d].
// ---------------------------------------------------------------------------
__global__ __launch_bounds__(256)
void vt_kernel(const float* __restrict__ v, float* __restrict__ vt)
{
    __shared__ float tile[32][33];
    int b  = blockIdx.z;
    int t0 = blockIdx.x * 32;
    int d0 = blockIdx.y * 32;
    int x  = threadIdx.x & 31;
    int y  = threadIdx.x >> 5;
#pragma unroll
    for (int j = 0; j < 32; j += 8)
        tile[y + j][x] = v[((long)(t0 + y + j) * B_ + b) * D_ + d0 + x];
    __syncthreads();
#pragma unroll
    for (int j = 0; j < 32; j += 8)
        vt[(long)b * D_ * T_ + (long)(d0 + y + j) * T_ + t0 + x] = tile[x][y + j];
}

// ---------------------------------------------------------------------------
// Softmax over T (in-place). mask: [B,T] bytes.
// ---------------------------------------------------------------------------
__global__ __launch_bounds__(256)
void attn_softmax_kernel(float* __restrict__ attn, const unsigned char* __restrict__ mask)
{
    int row = blockIdx.x;
    int b   = row & (B_ - 1);
    float* p = attn + (long)row * T_;
    const unsigned char* mrow = mask + (long)b * T_;
    int t = threadIdx.x;
    __shared__ float red[256];

    float x[4];
    float mx = -1e30f;
#pragma unroll
    for (int i = 0; i < 4; i++) {
        int tt = t + i * 256;
        float v = p[tt];
        if (mrow[tt]) v = -1e9f;
        x[i] = v;
        mx = fmaxf(mx, v);
    }
    red[t] = mx; __syncthreads();
    for (int s = 128; s > 0; s >>= 1) {
        if (t < s) red[t] = fmaxf(red[t], red[t + s]);
        __syncthreads();
    }
    mx = red[0]; __syncthreads();

    float sum = 0.f;
#pragma unroll
    for (int i = 0; i < 4; i++) { x[i] = fexp(x[i] - mx); sum += x[i]; }
    red[t] = sum; __syncthreads();
    for (int s = 128; s > 0; s >>= 1) {
        if (t < s) red[t] += red[t + s];
        __syncthreads();
    }
    float inv = 1.f / red[0];
#pragma unroll
    for (int i = 0; i < 4; i++) p[t + i * 256] = x[i] * inv;
}

// ---------------------------------------------------------------------------
// LayerNorm(outs + x).
// ---------------------------------------------------------------------------
__global__ __launch_bounds__(256)
void ln_kernel(const float* __restrict__ outs, const float* __restrict__ x,
               const float* __restrict__ g, const float* __restrict__ bb,
               float* __restrict__ out)
{
    int row = blockIdx.x;
    int t = threadIdx.x;
    const float* o  = outs + (long)row * D_;
    const float* xr = x    + (long)row * D_;
    __shared__ float red[256];

    float v0 = o[t] + xr[t];
    float v1 = o[t + 256] + xr[t + 256];

    red[t] = v0 + v1; __syncthreads();
    for (int s = 128; s > 0; s >>= 1) { if (t < s) red[t] += red[t + s]; __syncthreads(); }
    float mu = red[0] * (1.f / D_); __syncthreads();

    float d0 = v0 - mu, d1 = v1 - mu;
    red[t] = d0 * d0 + d1 * d1; __syncthreads();
    for (int s = 128; s > 0; s >>= 1) { if (t < s) red[t] += red[t + s]; __syncthreads(); }
    float inv = rsqrtf(red[0] * (1.f / D_) + 1e-5f);

    out[(long)row * D_ + t]       = d0 * inv * g[t]       + bb[t];
    out[(long)row * D_ + t + 256] = d1 * inv * g[t + 256] + bb[t + 256];
}

// ---------------------------------------------------------------------------
// 2-way gate
// ---------------------------------------------------------------------------
__global__ __launch_bounds__(128)
void gates_kernel(const float* __restrict__ tok, const float* __restrict__ Wdiv,
                  const float* __restrict__ bdiv, float* __restrict__ gates)
{
    int row = blockIdx.x;
    int t = threadIdx.x;
    const float* x = tok + (long)row * D_;
    float z0 = 0.f, z1 = 0.f;
    for (int d = t; d < D_; d += 128) {
        float xv = x[d];
        z0 = fmaf(xv, Wdiv[d],      z0);
        z1 = fmaf(xv, Wdiv[D_ + d], z1);
    }
    __shared__ float r0[128], r1[128];
    r0[t] = z0; r1[t] = z1; __syncthreads();
    for (int s = 64; s > 0; s >>= 1) {
        if (t < s) { r0[t] += r0[t + s]; r1[t] += r1[t + s]; }
        __syncthreads();
    }
    if (t == 0) {
        float a = r0[0] + bdiv[0], b = r1[0] + bdiv[1];
        float m = fmaxf(a, b);
        float e0 = __expf(a - m), e1 = __expf(b - m);
        float inv = 1.f / (e0 + e1);
        gates[row * 2 + 0] = e0 * inv;
        gates[row * 2 + 1] = e1 * inv;
    }
}

// ---------------------------------------------------------------------------
// Fused coef + log-prob base + copy-scatter. One block (256 thr) per row.
// Pointers pre-offset by the caller for M-half splitting (1024 % 8 == 0 keeps
// the b = row&7 mapping valid under pointer offsetting).
// ---------------------------------------------------------------------------
__global__ __launch_bounds__(256)
void lp_scatter_kernel(float* __restrict__ out, const float* __restrict__ rowsum,
                       const float* __restrict__ gates, const float* __restrict__ attn,
                       const int* __restrict__ copy_seq)
{
    int row = blockIdx.x;
    int t   = threadIdx.x;
    int b   = row & (B_ - 1);

    float coef = __logf(gates[row * 2 + 0]) - __logf(rowsum[row]);
    float gate1 = gates[row * 2 + 1];

    float4* o4 = (float4*)(out + (long)row * V_);
    for (int j = t; j < V_ / 4; j += 256) {
        float4 v = o4[j];
        v.x += coef; v.y += coef; v.z += coef; v.w += coef;
        o4[j] = v;
    }
    __syncthreads();

    const float* arow = attn + (long)row * T_;
    float* orow = out + (long)row * V_;
#pragma unroll
    for (int e = 0; e < 4; e++) {
        int tt = t + e * 256;
        float val = gate1 * arow[tt];
        int idx = copy_seq[tt * B_ + b];
        int* ia = (int*)(orow + idx);
        int assumed = *ia;
        int old;
        do {
            old = assumed;
            float cur = __int_as_float(old);
            float nv = __logf(__expf(cur) + val);
            assumed = atomicCAS(ia, old, __float_as_int(nv));
        } while (assumed != old);
    }
}

// ---------------------------------------------------------------------------
// Launch
// ---------------------------------------------------------------------------
extern "C" void kernel_launch(void* const* d_in, const int* in_sizes, int n_in,
                              void* d_out, int out_size)
{
    const float* outs = (const float*)d_in[0];
    const float* gs   = (const float*)d_in[1];
    const unsigned char* mask = (const unsigned char*)d_in[2];
    const int*   cseq = (const int*)d_in[3];
    const float* Wq = (const float*)d_in[4],  *bq = (const float*)d_in[5];
    const float* Wk = (const float*)d_in[6],  *bk = (const float*)d_in[7];
    const float* Wv = (const float*)d_in[8],  *bv = (const float*)d_in[9];
    const float* Wo = (const float*)d_in[10], *bo = (const float*)d_in[11];
    const float* lng = (const float*)d_in[12], *lnb = (const float*)d_in[13];
    const float* Wt = (const float*)d_in[14], *bt = (const float*)d_in[15];
    const float* Wgen = (const float*)d_in[16], *bgen = (const float*)d_in[17];
    const float* Wdiv = (const float*)d_in[18], *bdiv = (const float*)d_in[19];
    float* out = (float*)d_out;

    float* sc = nullptr;
    cudaGetSymbolAddress((void**)&sc, g_scratch);
    float* q     = sc + OQ;
    float* k     = sc + OK_;
    float* v     = sc + OV;
    float* vt    = sc + OVT;
    float* attn  = sc + OA;
    float* ctx   = sc + OC;
    float* ln    = sc + OL;
    float* tok   = sc + OT;
    float* gts   = sc + OG;
    float* rowsum = sc + ORS;
    __nv_bfloat16* wgen_b = (__nv_bfloat16*)(sc + OWB);
    __nv_bfloat16* tok_b  = (__nv_bfloat16*)(sc + OTB);

    const float scale = 0.044194173824159216f; // 1/sqrt(512)
    constexpr int SMEM  = 65536;
    cudaFuncSetAttribute(mma_nt_kernel<0>, cudaFuncAttributeMaxDynamicSharedMemorySize, SMEM);
    cudaFuncSetAttribute(mma_nt_kernel<1>, cudaFuncAttributeMaxDynamicSharedMemorySize, SMEM);
    cudaFuncSetAttribute(mma_bf16_nt_kernel, cudaFuncAttributeMaxDynamicSharedMemorySize, SMEM);
    dim3 blk(256);
    dim3 blkG(128);

    // Side streams + events (created once on the uncaptured correctness call;
    // record/wait pairs are graph-capturable fork/join; all forks rejoin main).
    static cudaStream_t s2 = [] { cudaStream_t s; cudaStreamCreate(&s); return s; }();
    static cudaStream_t s3 = [] { cudaStream_t s; cudaStreamCreate(&s); return s; }();
    static cudaEvent_t evFork = [] { cudaEvent_t e; cudaEventCreateWithFlags(&e, cudaEventDisableTiming); return e; }();
    static cudaEvent_t evWgen = [] { cudaEvent_t e; cudaEventCreateWithFlags(&e, cudaEventDisableTiming); return e; }();
    static cudaEvent_t evQ    = [] { cudaEvent_t e; cudaEventCreateWithFlags(&e, cudaEventDisableTiming); return e; }();
    static cudaEvent_t evV    = [] { cudaEvent_t e; cudaEventCreateWithFlags(&e, cudaEventDisableTiming); return e; }();
    static cudaEvent_t evVT   = [] { cudaEvent_t e; cudaEventCreateWithFlags(&e, cudaEventDisableTiming); return e; }();
    static cudaEvent_t evG0   = [] { cudaEvent_t e; cudaEventCreateWithFlags(&e, cudaEventDisableTiming); return e; }();
    static cudaEvent_t evS0   = [] { cudaEvent_t e; cudaEventCreateWithFlags(&e, cudaEventDisableTiming); return e; }();

    // fork from main
    cudaEventRecord(evFork, 0);
    cudaStreamWaitEvent(s2, evFork, 0);
    cudaStreamWaitEvent(s3, evFork, 0);

    // s2: Wgen->bf16 + rowsum=0 (overlaps q/k/v GEMMs)
    f2b_kernel<<<(V_ * TS_ / 4 + 255) / 256, blk, 0, s2>>>((const float4*)Wgen, (__nv_bfloat162*)wgen_b, V_ * TS_ / 4);
    zero_kernel<<<SB / 256, blk, 0, s2>>>(rowsum);
    cudaEventRecord(evWgen, s2);

    // s3: q = (outs @ Wq^T + bq) * scale  (concurrent with k/v on main)
    mma_nt_kernel<0><<<dim3(4, 16, 1), blkG, SMEM, s3>>>(outs, Wq, bq, q, nullptr, D_, D_, D_, D_, 0, 0, 0, scale);
    cudaEventRecord(evQ, s3);

    // main: k and v GEMMs
    mma_nt_kernel<0><<<dim3(4, 64, 1), blkG, SMEM>>>(gs, Wk, bk, k, nullptr, D_, D_, D_, D_, 0, 0, 0, 1.f);
    mma_nt_kernel<0><<<dim3(4, 64, 1), blkG, SMEM>>>(gs, Wv, bv, v, nullptr, D_, D_, D_, D_, 0, 0, 0, 1.f);
    cudaEventRecord(evV, 0);

    // s3: v transpose (after v; overlaps scores+softmax on main)
    cudaStreamWaitEvent(s3, evV, 0);
    vt_kernel<<<dim3(32, 16, 8), blk, 0, s3>>>(v, vt);
    cudaEventRecord(evVT, s3);

    // main: join q, then scores + softmax
    cudaStreamWaitEvent(0, evQ, 0);
    mma_nt_kernel<0><<<dim3(8, 2, 8), blkG, SMEM>>>(q, k, nullptr, attn, nullptr,
                                                    D_, B_ * D_, B_ * D_, B_ * T_,
                                                    D_, D_, T_, 1.f);
    attn_softmax_kernel<<<SB, 256>>>(attn, mask);

    // join vt, then ctx = attn @ v  (NT vs v_T, batched over b)
    cudaStreamWaitEvent(0, evVT, 0);
    mma_nt_kernel<0><<<dim3(4, 2, 8), blkG, SMEM>>>(attn, vt, nullptr, ctx, nullptr,
                                                    T_, B_ * T_, T_, B_ * D_,
                                                    T_, (long)D_ * T_, D_, 1.f);
    // x = ctx @ Wo^T + bo   -> reuse q buffer
    mma_nt_kernel<0><<<dim3(4, 16, 1), blkG, SMEM>>>(ctx, Wo, bo, q, nullptr, D_, D_, D_, D_, 0, 0, 0, 1.f);
    // outs_ln = LN(outs + x)
    ln_kernel<<<SB, 256>>>(outs, q, lng, lnb, ln);
    // tok = tanh(outs_ln @ Wt^T + bt); fused bf16 emit
    mma_nt_kernel<1><<<dim3(4, 16, 1), blkG, SMEM>>>(ln, Wt, bt, tok, tok_b, D_, D_, D_, TS_, 0, 0, 0, 1.f);
    // gates
    gates_kernel<<<SB, 128>>>(tok, Wdiv, bdiv, gts);

    // join Wgen conversion + rowsum init, then vocab GEMM split in M-halves
    cudaStreamWaitEvent(0, evWgen, 0);
    constexpr int MH = SB / 2;  // 1024 rows per half
    // half 0 (rows 0..1023)
    mma_bf16_nt_kernel<<<dim3(250, 8, 1), blkG, SMEM>>>(tok_b, wgen_b, bgen, out, rowsum,
                                                        TS_, TS_, TS_, V_);
    cudaEventRecord(evG0, 0);
    // half 1 (rows 1024..2047) on main
    mma_bf16_nt_kernel<<<dim3(250, 8, 1), blkG, SMEM>>>(tok_b + (long)MH * TS_, wgen_b, bgen,
                                                        out + (long)MH * V_, rowsum + MH,
                                                        TS_, TS_, TS_, V_);
    // s2: scatter half 0 overlaps GEMM half 1
    cudaStreamWaitEvent(s2, evG0, 0);
    lp_scatter_kernel<<<MH, 256, 0, s2>>>(out, rowsum, gts, attn, cseq);
    cudaEventRecord(evS0, s2);
    // main: scatter half 1, then join s2
    lp_scatter_kernel<<<MH, 256>>>(out + (long)MH * V_, rowsum + MH, gts + 2 * MH,
                                   attn + (long)MH * T_, cseq);
    cudaStreamWaitEvent(0, evS0, 0);
}